// round 1
// baseline (speedup 1.0000x reference)
#include <cuda_runtime.h>
#include <cuda_bf16.h>
#include <math.h>

#define B_ 4
#define T_ 256
#define D_ 1024
#define H_ 16
#define HD_ 64
#define F_ 4096
#define L_ 6
#define V_ 32000

typedef long long ll;

// ---------------- scratch (static device memory, no allocs) ----------------
__device__ float g_x [B_*T_*D_];
__device__ float g_h [B_*T_*D_];
__device__ float g_q [B_*T_*D_];
__device__ float g_k [B_*T_*D_];
__device__ float g_v [B_*T_*D_];
__device__ float g_ao[B_*T_*D_];
__device__ float g_sc[B_*H_*T_*T_];
__device__ float g_f1[B_*T_*F_];
__device__ float g_f3[B_*T_*F_];
__device__ float g_hlast[B_*D_];
__device__ float g_ll[B_*V_];
__device__ float g_cos[T_*(HD_/2)];
__device__ float g_sin[T_*(HD_/2)];

// ---------------- control flags (device-side control flow) -----------------
__device__ int d_do_skip;
__device__ int d_exited[B_];
__device__ int d_newly[B_];
__device__ int d_exl[B_];

// ---------------------------------------------------------------------------
__global__ void init_k() {
    int t = threadIdx.x;
    if (t < B_) { d_exited[t] = 0; d_newly[t] = 0; d_exl[t] = -1; }
    if (t == 0) d_do_skip = 0;
}

__global__ void finalize_k() {
    int t = threadIdx.x;
    if (t < B_) {
        int nv = d_exited[t] ? 0 : 1;
        d_newly[t] = nv;
        if (nv) d_exl[t] = L_ - 1;
    }
    if (t == 0) d_do_skip = 0;
}

__global__ void write_exl_k(float* out) {
    int t = threadIdx.x;
    if (t < B_) out[t] = (float)d_exl[t];
}

__global__ void rope_tables_k() {
    int idx = blockIdx.x * 256 + threadIdx.x;   // T_* (HD_/2) = 8192
    int t = idx >> 5;
    int i = idx & 31;
    float inv = expf(-logf(10000.f) * (2.f * (float)i) / (float)HD_);
    float f = (float)t * inv;
    g_cos[idx] = cosf(f);
    g_sin[idx] = sinf(f);
}

__global__ void embed_k(const int* __restrict__ ids, const float* __restrict__ emb) {
    ll idx = (ll)blockIdx.x * 256 + threadIdx.x;     // B*T*D
    int tok = ids[idx >> 10];
    g_x[idx] = emb[(ll)tok * D_ + (idx & 1023)];
}

// in-place RoPE on q or k; layout (B,T,H,HD)
__global__ void rope_k(float* __restrict__ q) {
    if (d_do_skip) return;
    int idx = blockIdx.x * 256 + threadIdx.x;   // B*T*H*(HD/2) = 524288
    int i = idx & 31;
    int t = (idx >> 9) & 255;
    ll base = (ll)(idx >> 5) * HD_ + i;
    float c = g_cos[t * 32 + i], s = g_sin[t * 32 + i];
    float x1 = q[base], x2 = q[base + 32];
    q[base]      = x1 * c - x2 * s;
    q[base + 32] = x1 * s + x2 * c;
}

// causal softmax over rows of scores (B,H,T,T)
__global__ void softmax_k() {
    if (d_do_skip) return;
    int r = blockIdx.x;          // (b*H+h)*T + q
    int qrow = r & (T_ - 1);
    float* row = g_sc + (ll)r * T_;
    int tid = threadIdx.x;
    float v = (tid <= qrow) ? row[tid] : -3.4e38f;
    __shared__ float red[256];
    red[tid] = v; __syncthreads();
    for (int o = 128; o > 0; o >>= 1) { if (tid < o) red[tid] = fmaxf(red[tid], red[tid + o]); __syncthreads(); }
    float m = red[0]; __syncthreads();
    float e = (tid <= qrow) ? expf(v - m) : 0.f;
    red[tid] = e; __syncthreads();
    for (int o = 128; o > 0; o >>= 1) { if (tid < o) red[tid] += red[tid + o]; __syncthreads(); }
    row[tid] = e / red[0];
}

__global__ void silu_mul_k() {
    if (d_do_skip) return;
    ll idx = (ll)blockIdx.x * 256 + threadIdx.x;    // B*T*F
    float a = g_f1[idx], b = g_f3[idx];
    g_f1[idx] = (a / (1.f + expf(-a))) * b;
}

// rmsnorm: one block per row, D_=1024 hardcoded, 256 threads x float4
// gateMode: 0 none, 1 skip-if-do_skip, 2 run-if-newly[row/rowsPerBatch]
__global__ void rmsnorm_k(const float* __restrict__ in, const float* __restrict__ w,
                          float* __restrict__ out, ll inStride, ll outStride,
                          int gateMode, int rowsPerBatch) {
    if (gateMode == 1 && d_do_skip) return;
    int row = blockIdx.x;
    if (gateMode == 2 && !d_newly[row / rowsPerBatch]) return;
    const float* xr = in + (ll)row * inStride;
    float* orow = out + (ll)row * outStride;
    int tid = threadIdx.x;
    float4 v = reinterpret_cast<const float4*>(xr)[tid];
    float s = v.x * v.x + v.y * v.y + v.z * v.z + v.w * v.w;
    __shared__ float red[256];
    red[tid] = s; __syncthreads();
    for (int o = 128; o > 0; o >>= 1) { if (tid < o) red[tid] += red[tid + o]; __syncthreads(); }
    float scale = rsqrtf(red[0] * (1.f / (float)D_) + 1e-6f);
    float4 wv = reinterpret_cast<const float4*>(w)[tid];
    float4 ov;
    ov.x = v.x * wv.x * scale; ov.y = v.y * wv.y * scale;
    ov.z = v.z * wv.z * scale; ov.w = v.w * wv.w * scale;
    reinterpret_cast<float4*>(orow)[tid] = ov;
}

// last-position logits: g_ll[b,v] = dot(g_hlast[b,:], lm_head[:,v])
__global__ void logits_last_k(const float* __restrict__ lm_head) {
    if (d_do_skip) return;
    int b = blockIdx.y;
    int v = blockIdx.x * 256 + threadIdx.x;
    __shared__ float hs[D_];
    for (int i = threadIdx.x; i < D_; i += 256) hs[i] = g_hlast[b * D_ + i];
    __syncthreads();
    float acc = 0.f;
    const float* col = lm_head + v;
#pragma unroll 4
    for (int d = 0; d < D_; d++) acc = fmaf(hs[d], col[(ll)d * V_], acc);
    g_ll[(ll)b * V_ + v] = acc;   // TEMP = 1
}

__global__ void compute_skip_k(const float* __restrict__ x,
                               const float* __restrict__ sw,
                               const float* __restrict__ sb, int li) {
    __shared__ float red[256];
    __shared__ float sp[B_];
    int tid = threadIdx.x;
    for (int b = 0; b < B_; b++) {
        const float* xr = x + ((ll)b * T_ + (T_ - 1)) * D_;
        float s = 0.f;
        for (int i = tid; i < D_; i += 256) s += xr[i] * sw[i];
        red[tid] = s; __syncthreads();
        for (int o = 128; o > 0; o >>= 1) { if (tid < o) red[tid] += red[tid + o]; __syncthreads(); }
        if (tid == 0) sp[b] = 1.f / (1.f + expf(-(red[0] + sb[0])));
        __syncthreads();
    }
    if (tid == 0) {
        float cnt = 0.f, s = 0.f;
        for (int b = 0; b < B_; b++) {
            float a = d_exited[b] ? 0.f : 1.f;
            cnt += a; s += sp[b] * a;
        }
        float mean = s / fmaxf(cnt, 1.f);
        d_do_skip = (li >= 1 && cnt > 0.f && mean < 0.1f) ? 1 : 0;
    }
}

__global__ void exit_decide_k(const float* __restrict__ x,
                              const float* __restrict__ ew,
                              const float* __restrict__ eb, int li) {
    int tid = threadIdx.x;
    if (d_do_skip) { if (tid < B_) d_newly[tid] = 0; return; }
    __shared__ float red[256];
    __shared__ float confs[B_], eps_[B_];
    for (int b = 0; b < B_; b++) {
        const float* lr = g_ll + (ll)b * V_;
        float m = -3.4e38f;
        for (int i = tid; i < V_; i += 256) m = fmaxf(m, lr[i]);
        red[tid] = m; __syncthreads();
        for (int o = 128; o > 0; o >>= 1) { if (tid < o) red[tid] = fmaxf(red[tid], red[tid + o]); __syncthreads(); }
        float mx = red[0]; __syncthreads();
        float s = 0.f;
        for (int i = tid; i < V_; i += 256) s += expf(lr[i] - mx);
        red[tid] = s; __syncthreads();
        for (int o = 128; o > 0; o >>= 1) { if (tid < o) red[tid] += red[tid + o]; __syncthreads(); }
        if (tid == 0) confs[b] = 1.f / red[0];
        __syncthreads();
        const float* xr = x + ((ll)b * T_ + (T_ - 1)) * D_;
        float e = 0.f;
        for (int i = tid; i < D_; i += 256) e += xr[i] * ew[i];
        red[tid] = e; __syncthreads();
        for (int o = 128; o > 0; o >>= 1) { if (tid < o) red[tid] += red[tid + o]; __syncthreads(); }
        if (tid == 0) eps_[b] = 1.f / (1.f + expf(-(red[0] + eb[0])));
        __syncthreads();
    }
    if (tid < B_) {
        int b = tid;
        int should = (confs[b] > 0.9f) || (eps_[b] > 0.9f);
        int nw = (should && !d_exited[b]) ? 1 : 0;
        d_newly[b] = nw;
        if (nw) { d_exited[b] = 1; d_exl[b] = li; }
    }
}

// ---------------- generic strided-batch SGEMM, 128x128x8, 8x8 micro --------
// C = alpha * A @ op(B) (+ C), per-z offsets: (z/HB)*sXo + (z%HB)*sXi
__global__ __launch_bounds__(256) void gemm_k(
    const float* __restrict__ A, const float* __restrict__ Bm, float* __restrict__ C,
    int M, int N, int K, int lda, int ldb, int ldc,
    int HB, ll sAo, ll sAi, ll sBo, ll sBi, ll sCo, ll sCi,
    float alpha, int accumulate, int transB, int gateMode) {
    if (gateMode == 1 && d_do_skip) return;
    if (gateMode == 2 && !d_newly[blockIdx.z]) return;
    int z = blockIdx.z;
    const float* Ab = A  + (ll)(z / HB) * sAo + (ll)(z % HB) * sAi;
    const float* Bb = Bm + (ll)(z / HB) * sBo + (ll)(z % HB) * sBi;
    float*       Cb = C  + (ll)(z / HB) * sCo + (ll)(z % HB) * sCi;

    __shared__ float As[8][132];
    __shared__ float Bs[8][132];

    const int tid = threadIdx.x;
    const int tx = tid & 15;
    const int ty = tid >> 4;
    const int rowBase = blockIdx.y * 128;
    const int colBase = blockIdx.x * 128;

    float acc[8][8];
#pragma unroll
    for (int i = 0; i < 8; i++)
#pragma unroll
        for (int j = 0; j < 8; j++) acc[i][j] = 0.f;

    const int arow = tid >> 1;
    const int ac4  = (tid & 1) << 2;

    for (int k0 = 0; k0 < K; k0 += 8) {
        // load A tile -> As[k][m]
        {
            int gm = rowBase + arow;
            float4 av = make_float4(0.f, 0.f, 0.f, 0.f);
            if (gm < M) {
                const float* p = Ab + (ll)gm * lda;
                if (k0 + ac4 + 3 < K) av = *reinterpret_cast<const float4*>(p + k0 + ac4);
                else {
                    if (k0 + ac4 + 0 < K) av.x = p[k0 + ac4 + 0];
                    if (k0 + ac4 + 1 < K) av.y = p[k0 + ac4 + 1];
                    if (k0 + ac4 + 2 < K) av.z = p[k0 + ac4 + 2];
                }
            }
            As[ac4 + 0][arow] = av.x;
            As[ac4 + 1][arow] = av.y;
            As[ac4 + 2][arow] = av.z;
            As[ac4 + 3][arow] = av.w;
        }
        // load B tile -> Bs[k][n]
        if (!transB) {
            int brow = tid >> 5;
            int bcol = (tid & 31) << 2;
            int gn = colBase + bcol;
            float4 bv = make_float4(0.f, 0.f, 0.f, 0.f);
            if (k0 + brow < K) {
                const float* p = Bb + (ll)(k0 + brow) * ldb;
                if (gn + 3 < N) bv = *reinterpret_cast<const float4*>(p + gn);
                else {
                    if (gn + 0 < N) bv.x = p[gn + 0];
                    if (gn + 1 < N) bv.y = p[gn + 1];
                    if (gn + 2 < N) bv.z = p[gn + 2];
                }
            }
            Bs[brow][bcol + 0] = bv.x;
            Bs[brow][bcol + 1] = bv.y;
            Bs[brow][bcol + 2] = bv.z;
            Bs[brow][bcol + 3] = bv.w;
        } else {
            int bn = tid >> 1;
            int bk = (tid & 1) << 2;
            int gn = colBase + bn;
            float4 bv = make_float4(0.f, 0.f, 0.f, 0.f);
            if (gn < N) {
                const float* p = Bb + (ll)gn * ldb;
                if (k0 + bk + 3 < K) bv = *reinterpret_cast<const float4*>(p + k0 + bk);
                else {
                    if (k0 + bk + 0 < K) bv.x = p[k0 + bk + 0];
                    if (k0 + bk + 1 < K) bv.y = p[k0 + bk + 1];
                    if (k0 + bk + 2 < K) bv.z = p[k0 + bk + 2];
                }
            }
            Bs[bk + 0][bn] = bv.x;
            Bs[bk + 1][bn] = bv.y;
            Bs[bk + 2][bn] = bv.z;
            Bs[bk + 3][bn] = bv.w;
        }
        __syncthreads();
#pragma unroll
        for (int kk = 0; kk < 8; kk++) {
            float ar[8], br[8];
#pragma unroll
            for (int i = 0; i < 8; i++) ar[i] = As[kk][ty * 8 + i];
#pragma unroll
            for (int j = 0; j < 8; j++) br[j] = Bs[kk][tx * 8 + j];
#pragma unroll
            for (int i = 0; i < 8; i++)
#pragma unroll
                for (int j = 0; j < 8; j++) acc[i][j] = fmaf(ar[i], br[j], acc[i][j]);
        }
        __syncthreads();
    }

#pragma unroll
    for (int i = 0; i < 8; i++) {
        int gm = rowBase + ty * 8 + i;
        if (gm >= M) continue;
        float* crow = Cb + (ll)gm * ldc;
#pragma unroll
        for (int j = 0; j < 8; j++) {
            int gn = colBase + tx * 8 + j;
            if (gn >= N) continue;
            float v = alpha * acc[i][j];
            if (accumulate) crow[gn] += v;
            else            crow[gn] = v;
        }
    }
}

static void gemm(const float* A, const float* Bm, float* C, int M, int N, int K,
                 int lda, int ldb, int ldc, int batch, int HB,
                 ll sAo, ll sAi, ll sBo, ll sBi, ll sCo, ll sCi,
                 float alpha, int accum, int transB, int gateMode) {
    dim3 grid((N + 127) / 128, (M + 127) / 128, batch);
    gemm_k<<<grid, 256>>>(A, Bm, C, M, N, K, lda, ldb, ldc,
                          HB, sAo, sAi, sBo, sBi, sCo, sCi,
                          alpha, accum, transB, gateMode);
}

// ---------------------------------------------------------------------------
extern "C" void kernel_launch(void* const* d_in, const int* in_sizes, int n_in,
                              void* d_out, int out_size) {
    const int*   ids        = (const int*)  d_in[0];
    const float* embed      = (const float*)d_in[1];
    const float* wq         = (const float*)d_in[2];
    const float* wk         = (const float*)d_in[3];
    const float* wv         = (const float*)d_in[4];
    const float* wo         = (const float*)d_in[5];
    const float* w1         = (const float*)d_in[6];
    const float* w2         = (const float*)d_in[7];
    const float* w3         = (const float*)d_in[8];
    const float* norm1      = (const float*)d_in[9];
    const float* norm2      = (const float*)d_in[10];
    const float* final_norm = (const float*)d_in[11];
    const float* lm_head    = (const float*)d_in[12];
    const float* exit_w     = (const float*)d_in[13];
    const float* exit_b     = (const float*)d_in[14];
    const float* skip_w     = (const float*)d_in[15];
    const float* skip_b     = (const float*)d_in[16];
    float* out = (float*)d_out;

    float *px, *ph, *pq, *pk, *pv, *pao, *psc, *pf1, *pf3, *phl;
    cudaGetSymbolAddress((void**)&px,  g_x);
    cudaGetSymbolAddress((void**)&ph,  g_h);
    cudaGetSymbolAddress((void**)&pq,  g_q);
    cudaGetSymbolAddress((void**)&pk,  g_k);
    cudaGetSymbolAddress((void**)&pv,  g_v);
    cudaGetSymbolAddress((void**)&pao, g_ao);
    cudaGetSymbolAddress((void**)&psc, g_sc);
    cudaGetSymbolAddress((void**)&pf1, g_f1);
    cudaGetSymbolAddress((void**)&pf3, g_f3);
    cudaGetSymbolAddress((void**)&phl, g_hlast);

    init_k<<<1, 32>>>();
    rope_tables_k<<<(T_ * (HD_ / 2)) / 256, 256>>>();
    embed_k<<<(B_ * T_ * D_) / 256, 256>>>(ids, embed);

    for (int li = 0; li < L_; li++) {
        const float* wq_l = wq + (ll)li * D_ * D_;
        const float* wk_l = wk + (ll)li * D_ * D_;
        const float* wv_l = wv + (ll)li * D_ * D_;
        const float* wo_l = wo + (ll)li * D_ * D_;
        const float* w1_l = w1 + (ll)li * D_ * F_;
        const float* w2_l = w2 + (ll)li * F_ * D_;
        const float* w3_l = w3 + (ll)li * D_ * F_;

        // 1) skip decision (uses x BEFORE the block)
        compute_skip_k<<<1, 256>>>(px, skip_w + (ll)li * D_, skip_b + li, li);

        // 2) transformer block (all gated by do_skip, gateMode=1)
        rmsnorm_k<<<B_ * T_, 256>>>(px, norm1 + (ll)li * D_, ph, D_, D_, 1, 1);
        gemm(ph, wq_l, pq, B_ * T_, D_, D_, D_, D_, D_, 1, 1, 0,0,0,0,0,0, 1.f, 0, 0, 1);
        gemm(ph, wk_l, pk, B_ * T_, D_, D_, D_, D_, D_, 1, 1, 0,0,0,0,0,0, 1.f, 0, 0, 1);
        gemm(ph, wv_l, pv, B_ * T_, D_, D_, D_, D_, D_, 1, 1, 0,0,0,0,0,0, 1.f, 0, 0, 1);
        rope_k<<<(B_ * T_ * D_ / 2) / 256, 256>>>(pq);
        rope_k<<<(B_ * T_ * D_ / 2) / 256, 256>>>(pk);
        // scores = (Q @ K^T) / sqrt(HD), batched over (b,h)
        gemm(pq, pk, psc, T_, T_, HD_, D_, D_, T_, B_ * H_, H_,
             (ll)T_ * D_, HD_, (ll)T_ * D_, HD_, (ll)H_ * T_ * T_, (ll)T_ * T_,
             0.125f, 0, 1, 1);
        softmax_k<<<B_ * H_ * T_, 256>>>();
        // o = att @ V -> (B,T,H,HD) layout
        gemm(psc, pv, pao, T_, HD_, T_, T_, D_, D_, B_ * H_, H_,
             (ll)H_ * T_ * T_, (ll)T_ * T_, (ll)T_ * D_, HD_, (ll)T_ * D_, HD_,
             1.f, 0, 0, 1);
        // x += o @ wo
        gemm(pao, wo_l, px, B_ * T_, D_, D_, D_, D_, D_, 1, 1, 0,0,0,0,0,0, 1.f, 1, 0, 1);
        // FFN
        rmsnorm_k<<<B_ * T_, 256>>>(px, norm2 + (ll)li * D_, ph, D_, D_, 1, 1);
        gemm(ph, w1_l, pf1, B_ * T_, F_, D_, D_, F_, F_, 1, 1, 0,0,0,0,0,0, 1.f, 0, 0, 1);
        gemm(ph, w3_l, pf3, B_ * T_, F_, D_, D_, F_, F_, 1, 1, 0,0,0,0,0,0, 1.f, 0, 0, 1);
        silu_mul_k<<<(B_ * T_ * F_) / 256, 256>>>();
        gemm(pf1, w2_l, px, B_ * T_, D_, F_, F_, D_, D_, 1, 1, 0,0,0,0,0,0, 1.f, 1, 0, 1);

        // 3) exit logic: last-position logits + confidence
        rmsnorm_k<<<B_, 256>>>(px + (ll)(T_ - 1) * D_, final_norm, phl,
                               (ll)T_ * D_, D_, 1, 1);
        logits_last_k<<<dim3(V_ / 256, B_), 256>>>(lm_head);
        exit_decide_k<<<1, 256>>>(px, exit_w + (ll)li * D_, exit_b + li, li);

        // 4) full logits only for newly-exited batches (gateMode=2)
        rmsnorm_k<<<B_ * T_, 256>>>(px, final_norm, ph, D_, D_, 2, T_);
        gemm(ph, lm_head, out, T_, V_, D_, D_, V_, V_, B_, 1,
             (ll)T_ * D_, 0, 0, 0, (ll)T_ * V_, 0, 1.f, 0, 0, 2);
    }

    // final logits for batches that never exited
    finalize_k<<<1, 32>>>();
    rmsnorm_k<<<B_ * T_, 256>>>(px, final_norm, ph, D_, D_, 2, T_);
    gemm(ph, lm_head, out, T_, V_, D_, D_, V_, V_, B_, 1,
         (ll)T_ * D_, 0, 0, 0, (ll)T_ * V_, 0, 1.f, 0, 0, 2);

    if (out_size >= B_ * T_ * V_ + B_)
        write_exl_k<<<1, 32>>>(out + (ll)B_ * T_ * V_);
}

// round 3
// speedup vs baseline: 2.0298x; 2.0298x over previous
#include <cuda_runtime.h>
#include <cuda_bf16.h>
#include <math.h>
#include <stdint.h>

#define B_ 4
#define T_ 256
#define D_ 1024
#define H_ 16
#define HD_ 64
#define F_ 4096
#define L_ 6
#define V_ 32000

typedef long long ll;

// ---------------- scratch (static device memory, no allocs) ----------------
__device__ float g_x [B_*T_*D_];
__device__ float g_h [B_*T_*D_];
__device__ float g_q [B_*T_*D_];
__device__ float g_k [B_*T_*D_];
__device__ float g_v [B_*T_*D_];
__device__ float g_ao[B_*T_*D_];
__device__ float g_sc[B_*H_*T_*T_];
__device__ float g_f1[B_*T_*F_];
__device__ float g_f3[B_*T_*F_];
__device__ float g_hlast[B_*D_];
__device__ float g_ll[B_*V_];
__device__ float g_cos[T_*(HD_/2)];
__device__ float g_sin[T_*(HD_/2)];

// ---------------- control flags (device-side control flow) -----------------
__device__ int d_do_skip;
__device__ int d_exited[B_];
__device__ int d_newly[B_];
__device__ int d_exl[B_];

// ---------------------------------------------------------------------------
__global__ void init_k() {
    int t = threadIdx.x;
    if (t < B_) { d_exited[t] = 0; d_newly[t] = 0; d_exl[t] = -1; }
    if (t == 0) d_do_skip = 0;
}

__global__ void finalize_k() {
    int t = threadIdx.x;
    if (t < B_) {
        int nv = d_exited[t] ? 0 : 1;
        d_newly[t] = nv;
        if (nv) d_exl[t] = L_ - 1;
    }
    if (t == 0) d_do_skip = 0;
}

__global__ void write_exl_k(float* out) {
    int t = threadIdx.x;
    if (t < B_) out[t] = (float)d_exl[t];
}

__global__ void rope_tables_k() {
    int idx = blockIdx.x * 256 + threadIdx.x;   // T_*(HD_/2) = 8192
    int t = idx >> 5;
    int i = idx & 31;
    float inv = expf(-logf(10000.f) * (2.f * (float)i) / (float)HD_);
    float f = (float)t * inv;
    g_cos[idx] = cosf(f);
    g_sin[idx] = sinf(f);
}

__global__ void embed_k(const int* __restrict__ ids, const float* __restrict__ emb) {
    ll idx = (ll)blockIdx.x * 256 + threadIdx.x;     // B*T*D
    int tok = ids[idx >> 10];
    g_x[idx] = emb[(ll)tok * D_ + (idx & 1023)];
}

// in-place RoPE on q or k; layout (B,T,H,HD)
__global__ void rope_k(float* __restrict__ q) {
    if (d_do_skip) return;
    int idx = blockIdx.x * 256 + threadIdx.x;   // B*T*H*(HD/2)
    int i = idx & 31;
    int t = (idx >> 9) & 255;
    ll base = (ll)(idx >> 5) * HD_ + i;
    float c = g_cos[t * 32 + i], s = g_sin[t * 32 + i];
    float x1 = q[base], x2 = q[base + 32];
    q[base]      = x1 * c - x2 * s;
    q[base + 32] = x1 * s + x2 * c;
}

// causal softmax over rows of scores (B,H,T,T)
__global__ void softmax_k() {
    if (d_do_skip) return;
    int r = blockIdx.x;          // (b*H+h)*T + q
    int qrow = r & (T_ - 1);
    float* row = g_sc + (ll)r * T_;
    int tid = threadIdx.x;
    float v = (tid <= qrow) ? row[tid] : -3.4e38f;
    __shared__ float red[256];
    red[tid] = v; __syncthreads();
    for (int o = 128; o > 0; o >>= 1) { if (tid < o) red[tid] = fmaxf(red[tid], red[tid + o]); __syncthreads(); }
    float m = red[0]; __syncthreads();
    float e = (tid <= qrow) ? expf(v - m) : 0.f;
    red[tid] = e; __syncthreads();
    for (int o = 128; o > 0; o >>= 1) { if (tid < o) red[tid] += red[tid + o]; __syncthreads(); }
    row[tid] = e / red[0];
}

__global__ void silu_mul_k() {
    if (d_do_skip) return;
    ll idx = (ll)blockIdx.x * 256 + threadIdx.x;    // B*T*F
    float a = g_f1[idx], b = g_f3[idx];
    g_f1[idx] = (a / (1.f + expf(-a))) * b;
}

// rmsnorm: one block per row, D_=1024, 256 threads x float4
// gateMode: 0 none, 1 skip-if-do_skip, 2 run-if-newly[row/rowsPerBatch]
__global__ void rmsnorm_k(const float* __restrict__ in, const float* __restrict__ w,
                          float* __restrict__ out, ll inStride, ll outStride,
                          int gateMode, int rowsPerBatch) {
    if (gateMode == 1 && d_do_skip) return;
    int row = blockIdx.x;
    if (gateMode == 2 && !d_newly[row / rowsPerBatch]) return;
    const float* xr = in + (ll)row * inStride;
    float* orow = out + (ll)row * outStride;
    int tid = threadIdx.x;
    float4 v = reinterpret_cast<const float4*>(xr)[tid];
    float s = v.x * v.x + v.y * v.y + v.z * v.z + v.w * v.w;
    __shared__ float red[256];
    red[tid] = s; __syncthreads();
    for (int o = 128; o > 0; o >>= 1) { if (tid < o) red[tid] += red[tid + o]; __syncthreads(); }
    float scale = rsqrtf(red[0] * (1.f / (float)D_) + 1e-6f);
    float4 wv = reinterpret_cast<const float4*>(w)[tid];
    float4 ov;
    ov.x = v.x * wv.x * scale; ov.y = v.y * wv.y * scale;
    ov.z = v.z * wv.z * scale; ov.w = v.w * wv.w * scale;
    reinterpret_cast<float4*>(orow)[tid] = ov;
}

// last-position logits: g_ll[b,v] = dot(g_hlast[b,:], lm_head[:,v])
__global__ void logits_last_k(const float* __restrict__ lm_head) {
    if (d_do_skip) return;
    int b = blockIdx.y;
    int v = blockIdx.x * 256 + threadIdx.x;
    __shared__ float hs[D_];
    for (int i = threadIdx.x; i < D_; i += 256) hs[i] = g_hlast[b * D_ + i];
    __syncthreads();
    float acc = 0.f;
    const float* col = lm_head + v;
#pragma unroll 4
    for (int d = 0; d < D_; d++) acc = fmaf(hs[d], col[(ll)d * V_], acc);
    g_ll[(ll)b * V_ + v] = acc;   // TEMP = 1
}

__global__ void compute_skip_k(const float* __restrict__ x,
                               const float* __restrict__ sw,
                               const float* __restrict__ sb, int li) {
    __shared__ float red[256];
    __shared__ float sp[B_];
    int tid = threadIdx.x;
    for (int b = 0; b < B_; b++) {
        const float* xr = x + ((ll)b * T_ + (T_ - 1)) * D_;
        float s = 0.f;
        for (int i = tid; i < D_; i += 256) s += xr[i] * sw[i];
        red[tid] = s; __syncthreads();
        for (int o = 128; o > 0; o >>= 1) { if (tid < o) red[tid] += red[tid + o]; __syncthreads(); }
        if (tid == 0) sp[b] = 1.f / (1.f + expf(-(red[0] + sb[0])));
        __syncthreads();
    }
    if (tid == 0) {
        float cnt = 0.f, s = 0.f;
        for (int b = 0; b < B_; b++) {
            float a = d_exited[b] ? 0.f : 1.f;
            cnt += a; s += sp[b] * a;
        }
        float mean = s / fmaxf(cnt, 1.f);
        d_do_skip = (li >= 1 && cnt > 0.f && mean < 0.1f) ? 1 : 0;
    }
}

__global__ void exit_decide_k(const float* __restrict__ x,
                              const float* __restrict__ ew,
                              const float* __restrict__ eb, int li) {
    int tid = threadIdx.x;
    if (d_do_skip) { if (tid < B_) d_newly[tid] = 0; return; }
    __shared__ float red[256];
    __shared__ float confs[B_], eps_[B_];
    for (int b = 0; b < B_; b++) {
        const float* lr = g_ll + (ll)b * V_;
        float m = -3.4e38f;
        for (int i = tid; i < V_; i += 256) m = fmaxf(m, lr[i]);
        red[tid] = m; __syncthreads();
        for (int o = 128; o > 0; o >>= 1) { if (tid < o) red[tid] = fmaxf(red[tid], red[tid + o]); __syncthreads(); }
        float mx = red[0]; __syncthreads();
        float s = 0.f;
        for (int i = tid; i < V_; i += 256) s += expf(lr[i] - mx);
        red[tid] = s; __syncthreads();
        for (int o = 128; o > 0; o >>= 1) { if (tid < o) red[tid] += red[tid + o]; __syncthreads(); }
        if (tid == 0) confs[b] = 1.f / red[0];
        __syncthreads();
        const float* xr = x + ((ll)b * T_ + (T_ - 1)) * D_;
        float e = 0.f;
        for (int i = tid; i < D_; i += 256) e += xr[i] * ew[i];
        red[tid] = e; __syncthreads();
        for (int o = 128; o > 0; o >>= 1) { if (tid < o) red[tid] += red[tid + o]; __syncthreads(); }
        if (tid == 0) eps_[b] = 1.f / (1.f + expf(-(red[0] + eb[0])));
        __syncthreads();
    }
    if (tid < B_) {
        int b = tid;
        int should = (confs[b] > 0.9f) || (eps_[b] > 0.9f);
        int nw = (should && !d_exited[b]) ? 1 : 0;
        d_newly[b] = nw;
        if (nw) { d_exited[b] = 1; d_exl[b] = li; }
    }
}

// ---------------- bf16x2-emulated fp32 tensor-core GEMM --------------------
// C = alpha * A @ op(B) (+C). 128x128 block tile, KT=16, 8 warps (2x4),
// warp tile 64x32 via 4x4 grid of m16n8k16 bf16 MMAs.
// Each fp32 value x = hi + lo (bf16 each); product emulated as
// hi*hi + hi*lo + lo*hi (fp32 accumulate). Residual ~3e-5 per element.
#define KT 16
#define SP2 136   // uint32 row stride; lr*8+lq -> conflict-free

__device__ __forceinline__ void split_pack(float x0, float x1,
                                           uint32_t& hi, uint32_t& lo) {
    __nv_bfloat16 h0 = __float2bfloat16(x0);
    __nv_bfloat16 h1 = __float2bfloat16(x1);
    __nv_bfloat16 l0 = __float2bfloat16(x0 - __bfloat162float(h0));
    __nv_bfloat16 l1 = __float2bfloat16(x1 - __bfloat162float(h1));
    hi = ((uint32_t)__bfloat16_as_ushort(h1) << 16) | __bfloat16_as_ushort(h0);
    lo = ((uint32_t)__bfloat16_as_ushort(l1) << 16) | __bfloat16_as_ushort(l0);
}

#define MMA_BF16(acc, a, b)                                                   \
    asm volatile(                                                             \
        "mma.sync.aligned.m16n8k16.row.col.f32.bf16.bf16.f32 "                \
        "{%0,%1,%2,%3}, {%4,%5,%6,%7}, {%8,%9}, {%0,%1,%2,%3};"               \
        : "+f"(acc[0]), "+f"(acc[1]), "+f"(acc[2]), "+f"(acc[3])              \
        : "r"(a[0]), "r"(a[1]), "r"(a[2]), "r"(a[3]), "r"(b[0]), "r"(b[1]))

__global__ __launch_bounds__(256) void gemm_bf16x2_k(
    const float* __restrict__ A, const float* __restrict__ Bm, float* __restrict__ C,
    int M, int N, int K, int lda, int ldb, int ldc,
    int HB, ll sAo, ll sAi, ll sBo, ll sBi, ll sCo, ll sCi,
    float alpha, int accumulate, int transB, int gateMode) {
    if (gateMode == 1 && d_do_skip) return;
    if (gateMode == 2 && !d_newly[blockIdx.z]) return;
    int z = blockIdx.z;
    const float* Ab = A  + (ll)(z / HB) * sAo + (ll)(z % HB) * sAi;
    const float* Bb = Bm + (ll)(z / HB) * sBo + (ll)(z % HB) * sBi;
    float*       Cb = C  + (ll)(z / HB) * sCo + (ll)(z % HB) * sCi;

    // [k-pair][m or n] packed bf16x2 (k, k+1)
    __shared__ uint32_t AsH[KT/2][SP2], AsL[KT/2][SP2];
    __shared__ uint32_t BsH[KT/2][SP2], BsL[KT/2][SP2];

    const int tid = threadIdx.x;
    const int lane = tid & 31;
    const int warp = tid >> 5;
    const int warpRow = warp >> 2;       // 0..1
    const int warpCol = warp & 3;        // 0..3
    const int rowBase = blockIdx.y * 128;
    const int colBase = blockIdx.x * 128;

    float acc[4][4][4];
#pragma unroll
    for (int i = 0; i < 4; i++)
#pragma unroll
        for (int j = 0; j < 4; j++)
#pragma unroll
            for (int r = 0; r < 4; r++) acc[i][j][r] = 0.f;

    const int lq = lane >> 2;   // 0..7
    const int lr = lane & 3;    // 0..3

    for (int k0 = 0; k0 < K; k0 += KT) {
        // ---- A tile: 128 rows x 16 k. thread: m = tid>>1, k-octet = (tid&1)*8
        {
            int m = tid >> 1;
            int kk = (tid & 1) * 8;
            int kp0 = kk >> 1;           // base k-pair row (0 or 4)
            int gm = rowBase + m;
            float4 v0 = make_float4(0, 0, 0, 0), v1 = make_float4(0, 0, 0, 0);
            if (gm < M) {
                const float* p = Ab + (ll)gm * lda + k0 + kk;
                v0 = *reinterpret_cast<const float4*>(p);
                v1 = *reinterpret_cast<const float4*>(p + 4);
            }
            uint32_t h, l;
            split_pack(v0.x, v0.y, h, l); AsH[kp0 + 0][m] = h; AsL[kp0 + 0][m] = l;
            split_pack(v0.z, v0.w, h, l); AsH[kp0 + 1][m] = h; AsL[kp0 + 1][m] = l;
            split_pack(v1.x, v1.y, h, l); AsH[kp0 + 2][m] = h; AsL[kp0 + 2][m] = l;
            split_pack(v1.z, v1.w, h, l); AsH[kp0 + 3][m] = h; AsL[kp0 + 3][m] = l;
        }
        // ---- B tile: 16 k x 128 n ----
        if (!transB) {
            // B row-major (K,N): thread covers 2 k-rows x 4 n
            int kp = tid >> 5;              // 0..7
            int n4 = (tid & 31) * 4;        // 0..124
            int gn = colBase + n4;
            const float* p0 = Bb + (ll)(k0 + 2 * kp) * ldb + gn;
            const float* p1 = p0 + ldb;
            float u[4], w[4];
            if (gn + 3 < N) {
                float4 a4 = *reinterpret_cast<const float4*>(p0);
                float4 b4 = *reinterpret_cast<const float4*>(p1);
                u[0] = a4.x; u[1] = a4.y; u[2] = a4.z; u[3] = a4.w;
                w[0] = b4.x; w[1] = b4.y; w[2] = b4.z; w[3] = b4.w;
            } else {
#pragma unroll
                for (int q = 0; q < 4; q++) {
                    u[q] = (gn + q < N) ? p0[q] : 0.f;
                    w[q] = (gn + q < N) ? p1[q] : 0.f;
                }
            }
#pragma unroll
            for (int q = 0; q < 4; q++) {
                uint32_t h, l;
                split_pack(u[q], w[q], h, l);
                BsH[kp][n4 + q] = h; BsL[kp][n4 + q] = l;
            }
        } else {
            // B is (N,K) row-major; Bs[k][n] = B[n][k]
            int n = tid >> 1;
            int kk = (tid & 1) * 8;
            int kp0 = kk >> 1;
            int gn = colBase + n;
            float4 v0 = make_float4(0, 0, 0, 0), v1 = make_float4(0, 0, 0, 0);
            if (gn < N) {
                const float* p = Bb + (ll)gn * ldb + k0 + kk;
                v0 = *reinterpret_cast<const float4*>(p);
                v1 = *reinterpret_cast<const float4*>(p + 4);
            }
            uint32_t h, l;
            split_pack(v0.x, v0.y, h, l); BsH[kp0 + 0][n] = h; BsL[kp0 + 0][n] = l;
            split_pack(v0.z, v0.w, h, l); BsH[kp0 + 1][n] = h; BsL[kp0 + 1][n] = l;
            split_pack(v1.x, v1.y, h, l); BsH[kp0 + 2][n] = h; BsL[kp0 + 2][n] = l;
            split_pack(v1.z, v1.w, h, l); BsH[kp0 + 3][n] = h; BsL[kp0 + 3][n] = l;
        }
        __syncthreads();

        // ---- fragments (one k16 step per tile) ----
        uint32_t aH[4][4], aL[4][4], bH[4][2], bL[4][2];
#pragma unroll
        for (int i = 0; i < 4; i++) {
            int m0 = warpRow * 64 + i * 16 + lq;
            aH[i][0] = AsH[lr][m0];     aH[i][1] = AsH[lr][m0 + 8];
            aH[i][2] = AsH[lr + 4][m0]; aH[i][3] = AsH[lr + 4][m0 + 8];
            aL[i][0] = AsL[lr][m0];     aL[i][1] = AsL[lr][m0 + 8];
            aL[i][2] = AsL[lr + 4][m0]; aL[i][3] = AsL[lr + 4][m0 + 8];
        }
#pragma unroll
        for (int j = 0; j < 4; j++) {
            int n0 = warpCol * 32 + j * 8 + lq;
            bH[j][0] = BsH[lr][n0]; bH[j][1] = BsH[lr + 4][n0];
            bL[j][0] = BsL[lr][n0]; bL[j][1] = BsL[lr + 4][n0];
        }
        // ---- 3 products: hi*lo, lo*hi (small terms first), then hi*hi ----
#pragma unroll
        for (int i = 0; i < 4; i++)
#pragma unroll
            for (int j = 0; j < 4; j++) MMA_BF16(acc[i][j], aH[i], bL[j]);
#pragma unroll
        for (int i = 0; i < 4; i++)
#pragma unroll
            for (int j = 0; j < 4; j++) MMA_BF16(acc[i][j], aL[i], bH[j]);
#pragma unroll
        for (int i = 0; i < 4; i++)
#pragma unroll
            for (int j = 0; j < 4; j++) MMA_BF16(acc[i][j], aH[i], bH[j]);
        __syncthreads();
    }

    // ---- epilogue (m16n8 C layout: rows lq/lq+8, cols 2lr, 2lr+1) ----
#pragma unroll
    for (int i = 0; i < 4; i++) {
#pragma unroll
        for (int r2 = 0; r2 < 2; r2++) {
            int gm = rowBase + warpRow * 64 + i * 16 + lq + r2 * 8;
            if (gm >= M) continue;
            float* crow = Cb + (ll)gm * ldc;
#pragma unroll
            for (int j = 0; j < 4; j++) {
                int gn = colBase + warpCol * 32 + j * 8 + lr * 2;
                float v0 = alpha * acc[i][j][r2 * 2 + 0];
                float v1 = alpha * acc[i][j][r2 * 2 + 1];
                if (gn < N) {
                    if (accumulate) crow[gn] += v0; else crow[gn] = v0;
                }
                if (gn + 1 < N) {
                    if (accumulate) crow[gn + 1] += v1; else crow[gn + 1] = v1;
                }
            }
        }
    }
}

static void gemm(const float* A, const float* Bm, float* C, int M, int N, int K,
                 int lda, int ldb, int ldc, int batch, int HB,
                 ll sAo, ll sAi, ll sBo, ll sBi, ll sCo, ll sCi,
                 float alpha, int accum, int transB, int gateMode) {
    dim3 grid((N + 127) / 128, (M + 127) / 128, batch);
    gemm_bf16x2_k<<<grid, 256>>>(A, Bm, C, M, N, K, lda, ldb, ldc,
                                 HB, sAo, sAi, sBo, sBi, sCo, sCi,
                                 alpha, accum, transB, gateMode);
}

// ---------------------------------------------------------------------------
extern "C" void kernel_launch(void* const* d_in, const int* in_sizes, int n_in,
                              void* d_out, int out_size) {
    const int*   ids        = (const int*)  d_in[0];
    const float* embed      = (const float*)d_in[1];
    const float* wq         = (const float*)d_in[2];
    const float* wk         = (const float*)d_in[3];
    const float* wv         = (const float*)d_in[4];
    const float* wo         = (const float*)d_in[5];
    const float* w1         = (const float*)d_in[6];
    const float* w2         = (const float*)d_in[7];
    const float* w3         = (const float*)d_in[8];
    const float* norm1      = (const float*)d_in[9];
    const float* norm2      = (const float*)d_in[10];
    const float* final_norm = (const float*)d_in[11];
    const float* lm_head    = (const float*)d_in[12];
    const float* exit_w     = (const float*)d_in[13];
    const float* exit_b     = (const float*)d_in[14];
    const float* skip_w     = (const float*)d_in[15];
    const float* skip_b     = (const float*)d_in[16];
    float* out = (float*)d_out;

    float *px, *ph, *pq, *pk, *pv, *pao, *psc, *pf1, *pf3, *phl;
    cudaGetSymbolAddress((void**)&px,  g_x);
    cudaGetSymbolAddress((void**)&ph,  g_h);
    cudaGetSymbolAddress((void**)&pq,  g_q);
    cudaGetSymbolAddress((void**)&pk,  g_k);
    cudaGetSymbolAddress((void**)&pv,  g_v);
    cudaGetSymbolAddress((void**)&pao, g_ao);
    cudaGetSymbolAddress((void**)&psc, g_sc);
    cudaGetSymbolAddress((void**)&pf1, g_f1);
    cudaGetSymbolAddress((void**)&pf3, g_f3);
    cudaGetSymbolAddress((void**)&phl, g_hlast);

    init_k<<<1, 32>>>();
    rope_tables_k<<<(T_ * (HD_ / 2)) / 256, 256>>>();
    embed_k<<<(B_ * T_ * D_) / 256, 256>>>(ids, embed);

    for (int li = 0; li < L_; li++) {
        const float* wq_l = wq + (ll)li * D_ * D_;
        const float* wk_l = wk + (ll)li * D_ * D_;
        const float* wv_l = wv + (ll)li * D_ * D_;
        const float* wo_l = wo + (ll)li * D_ * D_;
        const float* w1_l = w1 + (ll)li * D_ * F_;
        const float* w2_l = w2 + (ll)li * F_ * D_;
        const float* w3_l = w3 + (ll)li * D_ * F_;

        // 1) skip decision (uses x BEFORE the block)
        compute_skip_k<<<1, 256>>>(px, skip_w + (ll)li * D_, skip_b + li, li);

        // 2) transformer block (gated by do_skip)
        rmsnorm_k<<<B_ * T_, 256>>>(px, norm1 + (ll)li * D_, ph, D_, D_, 1, 1);
        gemm(ph, wq_l, pq, B_ * T_, D_, D_, D_, D_, D_, 1, 1, 0,0,0,0,0,0, 1.f, 0, 0, 1);
        gemm(ph, wk_l, pk, B_ * T_, D_, D_, D_, D_, D_, 1, 1, 0,0,0,0,0,0, 1.f, 0, 0, 1);
        gemm(ph, wv_l, pv, B_ * T_, D_, D_, D_, D_, D_, 1, 1, 0,0,0,0,0,0, 1.f, 0, 0, 1);
        rope_k<<<(B_ * T_ * D_ / 2) / 256, 256>>>(pq);
        rope_k<<<(B_ * T_ * D_ / 2) / 256, 256>>>(pk);
        // scores = (Q @ K^T) / sqrt(HD), batched over (b,h)
        gemm(pq, pk, psc, T_, T_, HD_, D_, D_, T_, B_ * H_, H_,
             (ll)T_ * D_, HD_, (ll)T_ * D_, HD_, (ll)H_ * T_ * T_, (ll)T_ * T_,
             0.125f, 0, 1, 1);
        softmax_k<<<B_ * H_ * T_, 256>>>();
        // o = att @ V -> (B,T,H,HD)
        gemm(psc, pv, pao, T_, HD_, T_, T_, D_, D_, B_ * H_, H_,
             (ll)H_ * T_ * T_, (ll)T_ * T_, (ll)T_ * D_, HD_, (ll)T_ * D_, HD_,
             1.f, 0, 0, 1);
        // x += o @ wo
        gemm(pao, wo_l, px, B_ * T_, D_, D_, D_, D_, D_, 1, 1, 0,0,0,0,0,0, 1.f, 1, 0, 1);
        // FFN
        rmsnorm_k<<<B_ * T_, 256>>>(px, norm2 + (ll)li * D_, ph, D_, D_, 1, 1);
        gemm(ph, w1_l, pf1, B_ * T_, F_, D_, D_, F_, F_, 1, 1, 0,0,0,0,0,0, 1.f, 0, 0, 1);
        gemm(ph, w3_l, pf3, B_ * T_, F_, D_, D_, F_, F_, 1, 1, 0,0,0,0,0,0, 1.f, 0, 0, 1);
        silu_mul_k<<<(B_ * T_ * F_) / 256, 256>>>();
        gemm(pf1, w2_l, px, B_ * T_, D_, F_, F_, D_, D_, 1, 1, 0,0,0,0,0,0, 1.f, 1, 0, 1);

        // 3) exit logic: last-position logits + confidence
        rmsnorm_k<<<B_, 256>>>(px + (ll)(T_ - 1) * D_, final_norm, phl,
                               (ll)T_ * D_, D_, 1, 1);
        logits_last_k<<<dim3(V_ / 256, B_), 256>>>(lm_head);
        exit_decide_k<<<1, 256>>>(px, exit_w + (ll)li * D_, exit_b + li, li);

        // 4) full logits only for newly-exited batches
        rmsnorm_k<<<B_ * T_, 256>>>(px, final_norm, ph, D_, D_, 2, T_);
        gemm(ph, lm_head, out, T_, V_, D_, D_, V_, V_, B_, 1,
             (ll)T_ * D_, 0, 0, 0, (ll)T_ * V_, 0, 1.f, 0, 0, 2);
    }

    // final logits for batches that never exited
    finalize_k<<<1, 32>>>();
    rmsnorm_k<<<B_ * T_, 256>>>(px, final_norm, ph, D_, D_, 2, T_);
    gemm(ph, lm_head, out, T_, V_, D_, D_, V_, V_, B_, 1,
         (ll)T_ * D_, 0, 0, 0, (ll)T_ * V_, 0, 1.f, 0, 0, 2);

    if (out_size >= B_ * T_ * V_ + B_)
        write_exl_k<<<1, 32>>>(out + (ll)B_ * T_ * V_);
}

// round 4
// speedup vs baseline: 2.4360x; 1.2001x over previous
#include <cuda_runtime.h>
#include <cuda_bf16.h>
#include <math.h>
#include <stdint.h>

#define B_ 4
#define T_ 256
#define D_ 1024
#define H_ 16
#define HD_ 64
#define F_ 4096
#define L_ 6
#define V_ 32000

typedef long long ll;

#define BTD (B_*T_*D_)
#define BTF (B_*T_*F_)

// ---------------- scratch (static device memory, no allocs) ----------------
__device__ float g_x  [BTD];
__device__ float g_h  [BTD];
__device__ float g_qkv[3*BTD];      // q | k | v contiguous
__device__ float g_ao [BTD];
__device__ float g_sc [B_*H_*T_*T_];
__device__ float g_f13[2*BTF];      // f1 | f3 contiguous
__device__ float g_hlast[B_*D_];
__device__ float g_ll[B_*V_];
__device__ float g_cos[T_*(HD_/2)];
__device__ float g_sin[T_*(HD_/2)];

// ---------------- control flags (device-side control flow) -----------------
__device__ int d_do_skip;
__device__ int d_exited[B_];
__device__ int d_newly[B_];
__device__ int d_exl[B_];

// ---------------------------------------------------------------------------
__global__ void init_k() {
    int t = threadIdx.x;
    if (t < B_) { d_exited[t] = 0; d_newly[t] = 0; d_exl[t] = -1; }
    if (t == 0) d_do_skip = 0;
}

__global__ void finalize_k() {
    int t = threadIdx.x;
    if (t < B_) {
        int nv = d_exited[t] ? 0 : 1;
        d_newly[t] = nv;
        if (nv) d_exl[t] = L_ - 1;
    }
    if (t == 0) d_do_skip = 0;
}

__global__ void write_exl_k(float* out) {
    int t = threadIdx.x;
    if (t < B_) out[t] = (float)d_exl[t];
}

__global__ void rope_tables_k() {
    int idx = blockIdx.x * 256 + threadIdx.x;   // T_*(HD_/2) = 8192
    int t = idx >> 5;
    int i = idx & 31;
    float inv = expf(-logf(10000.f) * (2.f * (float)i) / (float)HD_);
    float f = (float)t * inv;
    g_cos[idx] = cosf(f);
    g_sin[idx] = sinf(f);
}

__global__ void embed_k(const int* __restrict__ ids, const float* __restrict__ emb) {
    ll idx = (ll)blockIdx.x * 256 + threadIdx.x;     // B*T*D
    int tok = ids[idx >> 10];
    g_x[idx] = emb[(ll)tok * D_ + (idx & 1023)];
}

// in-place RoPE on q and k together (contiguous in g_qkv); layout (2B,T,H,HD)
__global__ void rope_k(float* __restrict__ q) {
    if (d_do_skip) return;
    int idx = blockIdx.x * 256 + threadIdx.x;   // 2*B*T*H*(HD/2)
    int i = idx & 31;
    int t = (idx >> 9) & 255;
    ll base = (ll)(idx >> 5) * HD_ + i;
    float c = g_cos[t * 32 + i], s = g_sin[t * 32 + i];
    float x1 = q[base], x2 = q[base + 32];
    q[base]      = x1 * c - x2 * s;
    q[base + 32] = x1 * s + x2 * c;
}

// causal softmax over rows of scores (B,H,T,T)
__global__ void softmax_k() {
    if (d_do_skip) return;
    int r = blockIdx.x;          // (b*H+h)*T + q
    int qrow = r & (T_ - 1);
    float* row = g_sc + (ll)r * T_;
    int tid = threadIdx.x;
    float v = (tid <= qrow) ? row[tid] : -3.4e38f;
    __shared__ float red[256];
    red[tid] = v; __syncthreads();
    for (int o = 128; o > 0; o >>= 1) { if (tid < o) red[tid] = fmaxf(red[tid], red[tid + o]); __syncthreads(); }
    float m = red[0]; __syncthreads();
    float e = (tid <= qrow) ? expf(v - m) : 0.f;
    red[tid] = e; __syncthreads();
    for (int o = 128; o > 0; o >>= 1) { if (tid < o) red[tid] += red[tid + o]; __syncthreads(); }
    row[tid] = e / red[0];
}

__global__ void silu_mul_k() {
    if (d_do_skip) return;
    ll idx = (ll)blockIdx.x * 256 + threadIdx.x;    // B*T*F
    float a = g_f13[idx], b = g_f13[idx + BTF];
    g_f13[idx] = (a / (1.f + expf(-a))) * b;
}

// rmsnorm: one block per row, D_=1024, 256 threads x float4
// gateMode: 0 none, 1 skip-if-do_skip, 2 run-if-newly[row/rowsPerBatch]
__global__ void rmsnorm_k(const float* __restrict__ in, const float* __restrict__ w,
                          float* __restrict__ out, ll inStride, ll outStride,
                          int gateMode, int rowsPerBatch) {
    if (gateMode == 1 && d_do_skip) return;
    int row = blockIdx.x;
    if (gateMode == 2 && !d_newly[row / rowsPerBatch]) return;
    const float* xr = in + (ll)row * inStride;
    float* orow = out + (ll)row * outStride;
    int tid = threadIdx.x;
    float4 v = reinterpret_cast<const float4*>(xr)[tid];
    float s = v.x * v.x + v.y * v.y + v.z * v.z + v.w * v.w;
    __shared__ float red[256];
    red[tid] = s; __syncthreads();
    for (int o = 128; o > 0; o >>= 1) { if (tid < o) red[tid] += red[tid + o]; __syncthreads(); }
    float scale = rsqrtf(red[0] * (1.f / (float)D_) + 1e-6f);
    float4 wv = reinterpret_cast<const float4*>(w)[tid];
    float4 ov;
    ov.x = v.x * wv.x * scale; ov.y = v.y * wv.y * scale;
    ov.z = v.z * wv.z * scale; ov.w = v.w * wv.w * scale;
    reinterpret_cast<float4*>(orow)[tid] = ov;
}

// last-position logits: g_ll[b,v] = dot(g_hlast[b,:], lm_head[:,v])
__global__ void logits_last_k(const float* __restrict__ lm_head) {
    if (d_do_skip) return;
    int b = blockIdx.y;
    int v = blockIdx.x * 256 + threadIdx.x;
    __shared__ float hs[D_];
    for (int i = threadIdx.x; i < D_; i += 256) hs[i] = g_hlast[b * D_ + i];
    __syncthreads();
    float acc = 0.f;
    const float* col = lm_head + v;
#pragma unroll 4
    for (int d = 0; d < D_; d++) acc = fmaf(hs[d], col[(ll)d * V_], acc);
    g_ll[(ll)b * V_ + v] = acc;   // TEMP = 1
}

__global__ void compute_skip_k(const float* __restrict__ x,
                               const float* __restrict__ sw,
                               const float* __restrict__ sb, int li) {
    __shared__ float red[256];
    __shared__ float sp[B_];
    int tid = threadIdx.x;
    for (int b = 0; b < B_; b++) {
        const float* xr = x + ((ll)b * T_ + (T_ - 1)) * D_;
        float s = 0.f;
        for (int i = tid; i < D_; i += 256) s += xr[i] * sw[i];
        red[tid] = s; __syncthreads();
        for (int o = 128; o > 0; o >>= 1) { if (tid < o) red[tid] += red[tid + o]; __syncthreads(); }
        if (tid == 0) sp[b] = 1.f / (1.f + expf(-(red[0] + sb[0])));
        __syncthreads();
    }
    if (tid == 0) {
        float cnt = 0.f, s = 0.f;
        for (int b = 0; b < B_; b++) {
            float a = d_exited[b] ? 0.f : 1.f;
            cnt += a; s += sp[b] * a;
        }
        float mean = s / fmaxf(cnt, 1.f);
        d_do_skip = (li >= 1 && cnt > 0.f && mean < 0.1f) ? 1 : 0;
    }
}

__global__ void exit_decide_k(const float* __restrict__ x,
                              const float* __restrict__ ew,
                              const float* __restrict__ eb, int li) {
    int tid = threadIdx.x;
    if (d_do_skip) { if (tid < B_) d_newly[tid] = 0; return; }
    __shared__ float red[256];
    __shared__ float confs[B_], eps_[B_];
    for (int b = 0; b < B_; b++) {
        const float* lr = g_ll + (ll)b * V_;
        float m = -3.4e38f;
        for (int i = tid; i < V_; i += 256) m = fmaxf(m, lr[i]);
        red[tid] = m; __syncthreads();
        for (int o = 128; o > 0; o >>= 1) { if (tid < o) red[tid] = fmaxf(red[tid], red[tid + o]); __syncthreads(); }
        float mx = red[0]; __syncthreads();
        float s = 0.f;
        for (int i = tid; i < V_; i += 256) s += expf(lr[i] - mx);
        red[tid] = s; __syncthreads();
        for (int o = 128; o > 0; o >>= 1) { if (tid < o) red[tid] += red[tid + o]; __syncthreads(); }
        if (tid == 0) confs[b] = 1.f / red[0];
        __syncthreads();
        const float* xr = x + ((ll)b * T_ + (T_ - 1)) * D_;
        float e = 0.f;
        for (int i = tid; i < D_; i += 256) e += xr[i] * ew[i];
        red[tid] = e; __syncthreads();
        for (int o = 128; o > 0; o >>= 1) { if (tid < o) red[tid] += red[tid + o]; __syncthreads(); }
        if (tid == 0) eps_[b] = 1.f / (1.f + expf(-(red[0] + eb[0])));
        __syncthreads();
    }
    if (tid < B_) {
        int b = tid;
        int should = (confs[b] > 0.9f) || (eps_[b] > 0.9f);
        int nw = (should && !d_exited[b]) ? 1 : 0;
        d_newly[b] = nw;
        if (nw) { d_exited[b] = 1; d_exl[b] = li; }
    }
}

// ---------------- bf16x2-emulated fp32 tensor-core GEMM, pipelined ---------
// C = alpha * A @ op(B) (+C). 128x128 block tile, KT=32, 8 warps (2x4),
// warp tile 64x32 via 4x4 grid of m16n8k16 bf16 MMAs, 3-product emulation.
// Register double-buffering: prefetch tile t+1 globals during tile t MMAs.
#define KT 32
#define SP2 136   // uint32 row stride; conflict-free fragment reads

__device__ __forceinline__ void split_pack(float x0, float x1,
                                           uint32_t& hi, uint32_t& lo) {
    __nv_bfloat16 h0 = __float2bfloat16(x0);
    __nv_bfloat16 h1 = __float2bfloat16(x1);
    __nv_bfloat16 l0 = __float2bfloat16(x0 - __bfloat162float(h0));
    __nv_bfloat16 l1 = __float2bfloat16(x1 - __bfloat162float(h1));
    hi = ((uint32_t)__bfloat16_as_ushort(h1) << 16) | __bfloat16_as_ushort(h0);
    lo = ((uint32_t)__bfloat16_as_ushort(l1) << 16) | __bfloat16_as_ushort(l0);
}

#define MMA_BF16(acc, a, b)                                                   \
    asm volatile(                                                             \
        "mma.sync.aligned.m16n8k16.row.col.f32.bf16.bf16.f32 "                \
        "{%0,%1,%2,%3}, {%4,%5,%6,%7}, {%8,%9}, {%0,%1,%2,%3};"               \
        : "+f"(acc[0]), "+f"(acc[1]), "+f"(acc[2]), "+f"(acc[3])              \
        : "r"(a[0]), "r"(a[1]), "r"(a[2]), "r"(a[3]), "r"(b[0]), "r"(b[1]))

__global__ __launch_bounds__(256) void gemm_bf16x2_k(
    const float* __restrict__ A, const float* __restrict__ Bm, float* __restrict__ C,
    const float* __restrict__ B1, const float* __restrict__ B2, int multiB,
    int M, int N, int K, int lda, int ldb, int ldc,
    int HB, ll sAo, ll sAi, ll sBo, ll sBi, ll sCo, ll sCi,
    float alpha, int accumulate, int transB, int gateMode) {
    if (gateMode == 1 && d_do_skip) return;
    if (gateMode == 2 && !d_newly[blockIdx.z]) return;
    int z = blockIdx.z;
    const float* Ab;
    const float* Bb;
    float* Cb;
    if (multiB) {
        Ab = A;
        Bb = (z == 0) ? Bm : ((z == 1) ? B1 : B2);
        Cb = C + (ll)z * sCo;
    } else {
        Ab = A  + (ll)(z / HB) * sAo + (ll)(z % HB) * sAi;
        Bb = Bm + (ll)(z / HB) * sBo + (ll)(z % HB) * sBi;
        Cb = C  + (ll)(z / HB) * sCo + (ll)(z % HB) * sCi;
    }

    // [k-pair][m or n] packed bf16x2 (k, k+1); KT/2 = 16 k-pairs
    __shared__ uint32_t AsH[KT/2][SP2], AsL[KT/2][SP2];
    __shared__ uint32_t BsH[KT/2][SP2], BsL[KT/2][SP2];

    const int tid = threadIdx.x;
    const int lane = tid & 31;
    const int warp = tid >> 5;
    const int warpRow = warp >> 2;       // 0..1
    const int warpCol = warp & 3;        // 0..3
    const int rowBase = blockIdx.y * 128;
    const int colBase = blockIdx.x * 128;

    float acc[4][4][4];
#pragma unroll
    for (int i = 0; i < 4; i++)
#pragma unroll
        for (int j = 0; j < 4; j++)
#pragma unroll
            for (int r = 0; r < 4; r++) acc[i][j][r] = 0.f;

    const int lq = lane >> 2;   // 0..7
    const int lr = lane & 3;    // 0..3

    // ---- staging registers for prefetch ----
    float4 ar[4];               // A: m=tid>>1, k-octets (tid&1)*8 and +16
    float4 br[4];               // B: layout-dependent

    const int a_m   = tid >> 1;
    const int a_kk0 = (tid & 1) * 8;
    const int bn_kp = tid >> 5;          // non-trans: k-pair row
    const int bn_n4 = (tid & 31) * 4;    // non-trans: n base
    const int bt_n  = tid >> 1;          // trans: n
    const int bt_kk0= (tid & 1) * 8;     // trans: k base

    const int gmA = rowBase + a_m;
    const bool aOk = (gmA < M);
    const int gnBn = colBase + bn_n4;
    const int gnBt = colBase + bt_n;

    // loaders: fill ar/br for k-tile starting at k0
    auto loadA = [&](int k0) {
#pragma unroll
        for (int seg = 0; seg < 2; seg++) {
            int kk = a_kk0 + seg * 16;
            if (aOk) {
                const float* p = Ab + (ll)gmA * lda + k0 + kk;
                ar[seg * 2 + 0] = *reinterpret_cast<const float4*>(p);
                ar[seg * 2 + 1] = *reinterpret_cast<const float4*>(p + 4);
            } else {
                ar[seg * 2 + 0] = make_float4(0, 0, 0, 0);
                ar[seg * 2 + 1] = make_float4(0, 0, 0, 0);
            }
        }
    };
    auto loadB = [&](int k0) {
        if (!transB) {
#pragma unroll
            for (int seg = 0; seg < 2; seg++) {
                int kpair = bn_kp + seg * 8;
                const float* p0 = Bb + (ll)(k0 + 2 * kpair) * ldb + gnBn;
                const float* p1 = p0 + ldb;
                if (gnBn + 3 < N) {
                    br[seg * 2 + 0] = *reinterpret_cast<const float4*>(p0);
                    br[seg * 2 + 1] = *reinterpret_cast<const float4*>(p1);
                } else {
                    float u[4], w[4];
#pragma unroll
                    for (int q = 0; q < 4; q++) {
                        u[q] = (gnBn + q < N) ? p0[q] : 0.f;
                        w[q] = (gnBn + q < N) ? p1[q] : 0.f;
                    }
                    br[seg * 2 + 0] = make_float4(u[0], u[1], u[2], u[3]);
                    br[seg * 2 + 1] = make_float4(w[0], w[1], w[2], w[3]);
                }
            }
        } else {
#pragma unroll
            for (int seg = 0; seg < 2; seg++) {
                int kk = bt_kk0 + seg * 16;
                if (gnBt < N) {
                    const float* p = Bb + (ll)gnBt * ldb + k0 + kk;
                    br[seg * 2 + 0] = *reinterpret_cast<const float4*>(p);
                    br[seg * 2 + 1] = *reinterpret_cast<const float4*>(p + 4);
                } else {
                    br[seg * 2 + 0] = make_float4(0, 0, 0, 0);
                    br[seg * 2 + 1] = make_float4(0, 0, 0, 0);
                }
            }
        }
    };
    auto storeA = [&]() {
#pragma unroll
        for (int seg = 0; seg < 2; seg++) {
            int kp0 = (a_kk0 + seg * 16) >> 1;
            float4 v0 = ar[seg * 2 + 0], v1 = ar[seg * 2 + 1];
            uint32_t h, l;
            split_pack(v0.x, v0.y, h, l); AsH[kp0 + 0][a_m] = h; AsL[kp0 + 0][a_m] = l;
            split_pack(v0.z, v0.w, h, l); AsH[kp0 + 1][a_m] = h; AsL[kp0 + 1][a_m] = l;
            split_pack(v1.x, v1.y, h, l); AsH[kp0 + 2][a_m] = h; AsL[kp0 + 2][a_m] = l;
            split_pack(v1.z, v1.w, h, l); AsH[kp0 + 3][a_m] = h; AsL[kp0 + 3][a_m] = l;
        }
    };
    auto storeB = [&]() {
        if (!transB) {
#pragma unroll
            for (int seg = 0; seg < 2; seg++) {
                int kpair = bn_kp + seg * 8;
                float4 u4 = br[seg * 2 + 0], w4 = br[seg * 2 + 1];
                float u[4] = {u4.x, u4.y, u4.z, u4.w};
                float w[4] = {w4.x, w4.y, w4.z, w4.w};
#pragma unroll
                for (int q = 0; q < 4; q++) {
                    uint32_t h, l;
                    split_pack(u[q], w[q], h, l);
                    BsH[kpair][bn_n4 + q] = h; BsL[kpair][bn_n4 + q] = l;
                }
            }
        } else {
#pragma unroll
            for (int seg = 0; seg < 2; seg++) {
                int kp0 = (bt_kk0 + seg * 16) >> 1;
                float4 v0 = br[seg * 2 + 0], v1 = br[seg * 2 + 1];
                uint32_t h, l;
                split_pack(v0.x, v0.y, h, l); BsH[kp0 + 0][bt_n] = h; BsL[kp0 + 0][bt_n] = l;
                split_pack(v0.z, v0.w, h, l); BsH[kp0 + 1][bt_n] = h; BsL[kp0 + 1][bt_n] = l;
                split_pack(v1.x, v1.y, h, l); BsH[kp0 + 2][bt_n] = h; BsL[kp0 + 2][bt_n] = l;
                split_pack(v1.z, v1.w, h, l); BsH[kp0 + 3][bt_n] = h; BsL[kp0 + 3][bt_n] = l;
            }
        }
    };

    // ---- pipelined main loop ----
    const int nt = K / KT;
    loadA(0); loadB(0);
    storeA(); storeB();
    for (int t = 0; t < nt; t++) {
        __syncthreads();                       // smem tile t ready
        if (t + 1 < nt) { loadA((t + 1) * KT); loadB((t + 1) * KT); }

        // compute tile t: two k16 steps
#pragma unroll
        for (int st = 0; st < 2; st++) {
            int base = st * 8;
            uint32_t aH[4][4], aL[4][4], bH[4][2], bL[4][2];
#pragma unroll
            for (int i = 0; i < 4; i++) {
                int m0 = warpRow * 64 + i * 16 + lq;
                aH[i][0] = AsH[base + lr][m0];     aH[i][1] = AsH[base + lr][m0 + 8];
                aH[i][2] = AsH[base + lr + 4][m0]; aH[i][3] = AsH[base + lr + 4][m0 + 8];
                aL[i][0] = AsL[base + lr][m0];     aL[i][1] = AsL[base + lr][m0 + 8];
                aL[i][2] = AsL[base + lr + 4][m0]; aL[i][3] = AsL[base + lr + 4][m0 + 8];
            }
#pragma unroll
            for (int j = 0; j < 4; j++) {
                int n0 = warpCol * 32 + j * 8 + lq;
                bH[j][0] = BsH[base + lr][n0]; bH[j][1] = BsH[base + lr + 4][n0];
                bL[j][0] = BsL[base + lr][n0]; bL[j][1] = BsL[base + lr + 4][n0];
            }
#pragma unroll
            for (int i = 0; i < 4; i++)
#pragma unroll
                for (int j = 0; j < 4; j++) MMA_BF16(acc[i][j], aH[i], bL[j]);
#pragma unroll
            for (int i = 0; i < 4; i++)
#pragma unroll
                for (int j = 0; j < 4; j++) MMA_BF16(acc[i][j], aL[i], bH[j]);
#pragma unroll
            for (int i = 0; i < 4; i++)
#pragma unroll
                for (int j = 0; j < 4; j++) MMA_BF16(acc[i][j], aH[i], bH[j]);
        }
        __syncthreads();                       // done reading smem tile t
        if (t + 1 < nt) { storeA(); storeB(); }
    }

    // ---- epilogue (m16n8 C layout: rows lq/lq+8, cols 2lr, 2lr+1) ----
#pragma unroll
    for (int i = 0; i < 4; i++) {
#pragma unroll
        for (int r2 = 0; r2 < 2; r2++) {
            int gm = rowBase + warpRow * 64 + i * 16 + lq + r2 * 8;
            if (gm >= M) continue;
            float* crow = Cb + (ll)gm * ldc;
#pragma unroll
            for (int j = 0; j < 4; j++) {
                int gn = colBase + warpCol * 32 + j * 8 + lr * 2;
                float v0 = alpha * acc[i][j][r2 * 2 + 0];
                float v1 = alpha * acc[i][j][r2 * 2 + 1];
                if (gn < N) {
                    if (accumulate) crow[gn] += v0; else crow[gn] = v0;
                }
                if (gn + 1 < N) {
                    if (accumulate) crow[gn + 1] += v1; else crow[gn + 1] = v1;
                }
            }
        }
    }
}

static void gemm(const float* A, const float* Bm, float* C, int M, int N, int K,
                 int lda, int ldb, int ldc, int batch, int HB,
                 ll sAo, ll sAi, ll sBo, ll sBi, ll sCo, ll sCi,
                 float alpha, int accum, int transB, int gateMode,
                 const float* B1 = nullptr, const float* B2 = nullptr,
                 int multiB = 0) {
    dim3 grid((N + 127) / 128, (M + 127) / 128, batch);
    gemm_bf16x2_k<<<grid, 256>>>(A, Bm, C, B1, B2, multiB,
                                 M, N, K, lda, ldb, ldc,
                                 HB, sAo, sAi, sBo, sBi, sCo, sCi,
                                 alpha, accum, transB, gateMode);
}

// ---------------------------------------------------------------------------
extern "C" void kernel_launch(void* const* d_in, const int* in_sizes, int n_in,
                              void* d_out, int out_size) {
    const int*   ids        = (const int*)  d_in[0];
    const float* embed      = (const float*)d_in[1];
    const float* wq         = (const float*)d_in[2];
    const float* wk         = (const float*)d_in[3];
    const float* wv         = (const float*)d_in[4];
    const float* wo         = (const float*)d_in[5];
    const float* w1         = (const float*)d_in[6];
    const float* w2         = (const float*)d_in[7];
    const float* w3         = (const float*)d_in[8];
    const float* norm1      = (const float*)d_in[9];
    const float* norm2      = (const float*)d_in[10];
    const float* final_norm = (const float*)d_in[11];
    const float* lm_head    = (const float*)d_in[12];
    const float* exit_w     = (const float*)d_in[13];
    const float* exit_b     = (const float*)d_in[14];
    const float* skip_w     = (const float*)d_in[15];
    const float* skip_b     = (const float*)d_in[16];
    float* out = (float*)d_out;

    float *px, *ph, *pqkv, *pao, *psc, *pf13, *phl;
    cudaGetSymbolAddress((void**)&px,   g_x);
    cudaGetSymbolAddress((void**)&ph,   g_h);
    cudaGetSymbolAddress((void**)&pqkv, g_qkv);
    cudaGetSymbolAddress((void**)&pao,  g_ao);
    cudaGetSymbolAddress((void**)&psc,  g_sc);
    cudaGetSymbolAddress((void**)&pf13, g_f13);
    cudaGetSymbolAddress((void**)&phl,  g_hlast);
    float* pq = pqkv;
    float* pk = pqkv + (ll)BTD;
    float* pv = pqkv + 2ll * BTD;
    float* pf1 = pf13;

    init_k<<<1, 32>>>();
    rope_tables_k<<<(T_ * (HD_ / 2)) / 256, 256>>>();
    embed_k<<<(B_ * T_ * D_) / 256, 256>>>(ids, embed);

    for (int li = 0; li < L_; li++) {
        const float* wq_l = wq + (ll)li * D_ * D_;
        const float* wk_l = wk + (ll)li * D_ * D_;
        const float* wv_l = wv + (ll)li * D_ * D_;
        const float* wo_l = wo + (ll)li * D_ * D_;
        const float* w1_l = w1 + (ll)li * D_ * F_;
        const float* w2_l = w2 + (ll)li * F_ * D_;
        const float* w3_l = w3 + (ll)li * D_ * F_;

        // 1) skip decision (uses x BEFORE the block)
        compute_skip_k<<<1, 256>>>(px, skip_w + (ll)li * D_, skip_b + li, li);

        // 2) transformer block (gated by do_skip)
        rmsnorm_k<<<B_ * T_, 256>>>(px, norm1 + (ll)li * D_, ph, D_, D_, 1, 1);
        // fused QKV: z selects wq/wk/wv, C = g_qkv + z*BTD
        gemm(ph, wq_l, pqkv, B_ * T_, D_, D_, D_, D_, D_, 3, 1,
             0, 0, 0, 0, (ll)BTD, 0, 1.f, 0, 0, 1, wk_l, wv_l, 1);
        // RoPE over q and k (contiguous)
        rope_k<<<(2 * B_ * T_ * D_ / 2) / 256, 256>>>(pq);
        // scores = (Q @ K^T) / sqrt(HD), batched over (b,h)
        gemm(pq, pk, psc, T_, T_, HD_, D_, D_, T_, B_ * H_, H_,
             (ll)T_ * D_, HD_, (ll)T_ * D_, HD_, (ll)H_ * T_ * T_, (ll)T_ * T_,
             0.125f, 0, 1, 1);
        softmax_k<<<B_ * H_ * T_, 256>>>();
        // o = att @ V -> (B,T,H,HD)
        gemm(psc, pv, pao, T_, HD_, T_, T_, D_, D_, B_ * H_, H_,
             (ll)H_ * T_ * T_, (ll)T_ * T_, (ll)T_ * D_, HD_, (ll)T_ * D_, HD_,
             1.f, 0, 0, 1);
        // x += o @ wo
        gemm(pao, wo_l, px, B_ * T_, D_, D_, D_, D_, D_, 1, 1, 0,0,0,0,0,0, 1.f, 1, 0, 1);
        // FFN
        rmsnorm_k<<<B_ * T_, 256>>>(px, norm2 + (ll)li * D_, ph, D_, D_, 1, 1);
        // fused w1/w3: z selects weight, C = g_f13 + z*BTF
        gemm(ph, w1_l, pf13, B_ * T_, F_, D_, D_, F_, F_, 2, 1,
             0, 0, 0, 0, (ll)BTF, 0, 1.f, 0, 0, 1, w3_l, nullptr, 1);
        silu_mul_k<<<(B_ * T_ * F_) / 256, 256>>>();
        gemm(pf1, w2_l, px, B_ * T_, D_, F_, F_, D_, D_, 1, 1, 0,0,0,0,0,0, 1.f, 1, 0, 1);

        // 3) exit logic: last-position logits + confidence
        rmsnorm_k<<<B_, 256>>>(px + (ll)(T_ - 1) * D_, final_norm, phl,
                               (ll)T_ * D_, D_, 1, 1);
        logits_last_k<<<dim3(V_ / 256, B_), 256>>>(lm_head);
        exit_decide_k<<<1, 256>>>(px, exit_w + (ll)li * D_, exit_b + li, li);

        // 4) full logits only for newly-exited batches
        rmsnorm_k<<<B_ * T_, 256>>>(px, final_norm, ph, D_, D_, 2, T_);
        gemm(ph, lm_head, out, T_, V_, D_, D_, V_, V_, B_, 1,
             (ll)T_ * D_, 0, 0, 0, (ll)T_ * V_, 0, 1.f, 0, 0, 2);
    }

    // final logits for batches that never exited
    finalize_k<<<1, 32>>>();
    rmsnorm_k<<<B_ * T_, 256>>>(px, final_norm, ph, D_, D_, 2, T_);
    gemm(ph, lm_head, out, T_, V_, D_, D_, V_, V_, B_, 1,
         (ll)T_ * D_, 0, 0, 0, (ll)T_ * V_, 0, 1.f, 0, 0, 2);

    if (out_size >= B_ * T_ * V_ + B_)
        write_exl_k<<<1, 32>>>(out + (ll)B_ * T_ * V_);
}

// round 7
// speedup vs baseline: 3.0196x; 1.2396x over previous
#include <cuda_runtime.h>
#include <cuda_bf16.h>
#include <math.h>
#include <stdint.h>

#define B_ 4
#define T_ 256
#define D_ 1024
#define H_ 16
#define HD_ 64
#define F_ 4096
#define L_ 6
#define V_ 32000

typedef long long ll;

#define BTD (B_*T_*D_)
#define BTF (B_*T_*F_)

// ---------------- scratch (static device memory, no allocs) ----------------
__device__ float g_x  [BTD];
__device__ float g_h  [BTD];
__device__ float g_qkv[3*BTD];      // q | k | v contiguous
__device__ float g_ao [BTD];
__device__ float g_sc [B_*H_*T_*T_];
__device__ float g_f13[2*BTF];      // f1 | f3 contiguous
__device__ float g_hlast[B_*D_];
__device__ float g_ll[B_*V_];
__device__ float g_cos[T_*(HD_/2)];
__device__ float g_sin[T_*(HD_/2)];

// ---------------- control flags (device-side control flow) -----------------
__device__ int d_do_skip;
__device__ int d_exited[B_];
__device__ int d_newly[B_];
__device__ int d_exl[B_];

// ---------------------------------------------------------------------------
__global__ void init_k() {
    int t = threadIdx.x;
    if (t < B_) { d_exited[t] = 0; d_newly[t] = 0; d_exl[t] = -1; }
    if (t == 0) d_do_skip = 0;
}

__global__ void finalize_k() {
    int t = threadIdx.x;
    if (t < B_) {
        int nv = d_exited[t] ? 0 : 1;
        d_newly[t] = nv;
        if (nv) d_exl[t] = L_ - 1;
    }
    if (t == 0) d_do_skip = 0;
}

__global__ void write_exl_k(float* out) {
    int t = threadIdx.x;
    if (t < B_) out[t] = (float)d_exl[t];
}

__global__ void rope_tables_k() {
    int idx = blockIdx.x * 256 + threadIdx.x;   // T_*(HD_/2) = 8192
    int t = idx >> 5;
    int i = idx & 31;
    float inv = expf(-logf(10000.f) * (2.f * (float)i) / (float)HD_);
    float f = (float)t * inv;
    g_cos[idx] = cosf(f);
    g_sin[idx] = sinf(f);
}

__global__ void embed_k(const int* __restrict__ ids, const float* __restrict__ emb) {
    ll idx = (ll)blockIdx.x * 256 + threadIdx.x;     // B*T*D
    int tok = ids[idx >> 10];
    g_x[idx] = emb[(ll)tok * D_ + (idx & 1023)];
}

// in-place RoPE on q and k together (contiguous in g_qkv); layout (2B,T,H,HD)
__global__ void rope_k(float* __restrict__ q) {
    if (d_do_skip) return;
    int idx = blockIdx.x * 256 + threadIdx.x;   // 2*B*T*H*(HD/2)
    int i = idx & 31;
    int t = (idx >> 9) & 255;
    ll base = (ll)(idx >> 5) * HD_ + i;
    float c = g_cos[t * 32 + i], s = g_sin[t * 32 + i];
    float x1 = q[base], x2 = q[base + 32];
    q[base]      = x1 * c - x2 * s;
    q[base + 32] = x1 * s + x2 * c;
}

// causal softmax over rows of scores (B,H,T,T)
__global__ void softmax_k() {
    if (d_do_skip) return;
    int r = blockIdx.x;          // (b*H+h)*T + q
    int qrow = r & (T_ - 1);
    float* row = g_sc + (ll)r * T_;
    int tid = threadIdx.x;
    float v = (tid <= qrow) ? row[tid] : -3.4e38f;
    __shared__ float red[256];
    red[tid] = v; __syncthreads();
    for (int o = 128; o > 0; o >>= 1) { if (tid < o) red[tid] = fmaxf(red[tid], red[tid + o]); __syncthreads(); }
    float m = red[0]; __syncthreads();
    float e = (tid <= qrow) ? expf(v - m) : 0.f;
    red[tid] = e; __syncthreads();
    for (int o = 128; o > 0; o >>= 1) { if (tid < o) red[tid] += red[tid + o]; __syncthreads(); }
    row[tid] = e / red[0];
}

__global__ void silu_mul_k() {
    if (d_do_skip) return;
    ll idx = (ll)blockIdx.x * 256 + threadIdx.x;    // B*T*F
    float a = g_f13[idx], b = g_f13[idx + BTF];
    g_f13[idx] = (a / (1.f + expf(-a))) * b;
}

// rmsnorm: one block per row, D_=1024, 256 threads x float4
// gateMode: 0 none, 1 skip-if-do_skip, 2 run-if-newly[row/rowsPerBatch]
__global__ void rmsnorm_k(const float* __restrict__ in, const float* __restrict__ w,
                          float* __restrict__ out, ll inStride, ll outStride,
                          int gateMode, int rowsPerBatch) {
    if (gateMode == 1 && d_do_skip) return;
    int row = blockIdx.x;
    if (gateMode == 2 && !d_newly[row / rowsPerBatch]) return;
    const float* xr = in + (ll)row * inStride;
    float* orow = out + (ll)row * outStride;
    int tid = threadIdx.x;
    float4 v = reinterpret_cast<const float4*>(xr)[tid];
    float s = v.x * v.x + v.y * v.y + v.z * v.z + v.w * v.w;
    __shared__ float red[256];
    red[tid] = s; __syncthreads();
    for (int o = 128; o > 0; o >>= 1) { if (tid < o) red[tid] += red[tid + o]; __syncthreads(); }
    float scale = rsqrtf(red[0] * (1.f / (float)D_) + 1e-6f);
    float4 wv = reinterpret_cast<const float4*>(w)[tid];
    float4 ov;
    ov.x = v.x * wv.x * scale; ov.y = v.y * wv.y * scale;
    ov.z = v.z * wv.z * scale; ov.w = v.w * wv.w * scale;
    reinterpret_cast<float4*>(orow)[tid] = ov;
}

// last-position logits: g_ll[b,v] = dot(g_hlast[b,:], lm_head[:,v])
__global__ void logits_last_k(const float* __restrict__ lm_head) {
    if (d_do_skip) return;
    int b = blockIdx.y;
    int v = blockIdx.x * 256 + threadIdx.x;
    __shared__ float hs[D_];
    for (int i = threadIdx.x; i < D_; i += 256) hs[i] = g_hlast[b * D_ + i];
    __syncthreads();
    float acc = 0.f;
    const float* col = lm_head + v;
#pragma unroll 4
    for (int d = 0; d < D_; d++) acc = fmaf(hs[d], col[(ll)d * V_], acc);
    g_ll[(ll)b * V_ + v] = acc;   // TEMP = 1
}

// warp-per-batch skip decision
__global__ void compute_skip_k(const float* __restrict__ x,
                               const float* __restrict__ sw,
                               const float* __restrict__ sb, int li) {
    int tid = threadIdx.x;
    int w = tid >> 5, l = tid & 31;
    __shared__ float sp[B_];
    if (w < B_) {
        const float* xr = x + ((ll)w * T_ + (T_ - 1)) * D_;
        float s = 0.f;
#pragma unroll 8
        for (int i = l; i < D_; i += 32) s += xr[i] * sw[i];
#pragma unroll
        for (int o = 16; o > 0; o >>= 1) s += __shfl_down_sync(0xffffffff, s, o);
        if (l == 0) sp[w] = 1.f / (1.f + expf(-(s + sb[0])));
    }
    __syncthreads();
    if (tid == 0) {
        float cnt = 0.f, s = 0.f;
        for (int b = 0; b < B_; b++) {
            float a = d_exited[b] ? 0.f : 1.f;
            cnt += a; s += sp[b] * a;
        }
        float mean = s / fmaxf(cnt, 1.f);
        d_do_skip = (li >= 1 && cnt > 0.f && mean < 0.1f) ? 1 : 0;
    }
}

// parallel exit decision: 4 batches x 64 threads
__global__ void exit_decide_k(const float* __restrict__ x,
                              const float* __restrict__ ew,
                              const float* __restrict__ eb, int li) {
    int tid = threadIdx.x;
    if (d_do_skip) { if (tid < B_) d_newly[tid] = 0; return; }
    __shared__ float red[256];
    __shared__ float mxs[B_], sums[B_], eps_[B_];
    int b = tid >> 6, l = tid & 63;
    const float* lr = g_ll + (ll)b * V_;
    float m = -3.4e38f;
    for (int i = l; i < V_; i += 64) m = fmaxf(m, lr[i]);
    red[tid] = m; __syncthreads();
    for (int o = 32; o > 0; o >>= 1) { if (l < o) red[tid] = fmaxf(red[tid], red[tid + o]); __syncthreads(); }
    if (l == 0) mxs[b] = red[tid];
    __syncthreads();
    float mx = mxs[b];
    float s = 0.f;
    for (int i = l; i < V_; i += 64) s += expf(lr[i] - mx);
    red[tid] = s; __syncthreads();
    for (int o = 32; o > 0; o >>= 1) { if (l < o) red[tid] += red[tid + o]; __syncthreads(); }
    if (l == 0) sums[b] = red[tid];
    __syncthreads();
    const float* xr = x + ((ll)b * T_ + (T_ - 1)) * D_;
    float e = 0.f;
    for (int i = l; i < D_; i += 64) e += xr[i] * ew[i];
    red[tid] = e; __syncthreads();
    for (int o = 32; o > 0; o >>= 1) { if (l < o) red[tid] += red[tid + o]; __syncthreads(); }
    if (l == 0) eps_[b] = 1.f / (1.f + expf(-(red[tid] + eb[0])));
    __syncthreads();
    if (tid < B_) {
        int bb = tid;
        float conf = 1.f / sums[bb];
        int should = (conf > 0.9f) || (eps_[bb] > 0.9f);
        int nw = (should && !d_exited[bb]) ? 1 : 0;
        d_newly[bb] = nw;
        if (nw) { d_exited[bb] = 1; d_exl[bb] = li; }
    }
}

// ---------------- bf16x2-emulated fp32 tensor-core GEMM, pipelined ---------
// C = alpha * A @ op(B) (+C). BM x 128 block tile (BM = IBLK*32), KT=32,
// 8 warps (2x4), warp tile (IBLK*16) x 32 via m16n8k16 bf16 MMAs,
// 3-product hi/lo emulation. Register double-buffered global prefetch.
#define KT 32

__device__ __forceinline__ void split_pack(float x0, float x1,
                                           uint32_t& hi, uint32_t& lo) {
    __nv_bfloat16 h0 = __float2bfloat16(x0);
    __nv_bfloat16 h1 = __float2bfloat16(x1);
    __nv_bfloat16 l0 = __float2bfloat16(x0 - __bfloat162float(h0));
    __nv_bfloat16 l1 = __float2bfloat16(x1 - __bfloat162float(h1));
    hi = ((uint32_t)__bfloat16_as_ushort(h1) << 16) | __bfloat16_as_ushort(h0);
    lo = ((uint32_t)__bfloat16_as_ushort(l1) << 16) | __bfloat16_as_ushort(l0);
}

#define MMA_BF16(acc, a, b)                                                   \
    asm volatile(                                                             \
        "mma.sync.aligned.m16n8k16.row.col.f32.bf16.bf16.f32 "                \
        "{%0,%1,%2,%3}, {%4,%5,%6,%7}, {%8,%9}, {%0,%1,%2,%3};"               \
        : "+f"(acc[0]), "+f"(acc[1]), "+f"(acc[2]), "+f"(acc[3])              \
        : "r"(a[0]), "r"(a[1]), "r"(a[2]), "r"(a[3]), "r"(b[0]), "r"(b[1]))

template <int IBLK>
__global__ __launch_bounds__(256, (IBLK == 2) ? 2 : 1) void gemm_bf16x2_k(
    const float* __restrict__ A, const float* __restrict__ Bm, float* __restrict__ C,
    const float* __restrict__ B1, const float* __restrict__ B2, int multiB,
    int M, int N, int K, int lda, int ldb, int ldc,
    int HB, ll sAo, ll sAi, ll sBo, ll sBi, ll sCo, ll sCi,
    float alpha, int accumulate, int transB, int gateMode) {
    if (gateMode == 1 && d_do_skip) return;
    if (gateMode == 2 && !d_newly[blockIdx.z]) return;
    constexpr int BM = IBLK * 32;
    constexpr int SPA = BM + 8;
    constexpr int SPB = 136;

    int z = blockIdx.z;
    const float* Ab;
    const float* Bb;
    float* Cb;
    if (multiB) {
        Ab = A;
        Bb = (z == 0) ? Bm : ((z == 1) ? B1 : B2);
        Cb = C + (ll)z * sCo;
    } else {
        Ab = A  + (ll)(z / HB) * sAo + (ll)(z % HB) * sAi;
        Bb = Bm + (ll)(z / HB) * sBo + (ll)(z % HB) * sBi;
        Cb = C  + (ll)(z / HB) * sCo + (ll)(z % HB) * sCi;
    }

    __shared__ uint32_t AsH[KT/2][SPA], AsL[KT/2][SPA];
    __shared__ uint32_t BsH[KT/2][SPB], BsL[KT/2][SPB];

    const int tid = threadIdx.x;
    const int lane = tid & 31;
    const int warp = tid >> 5;
    const int warpRow = warp >> 2;       // 0..1
    const int warpCol = warp & 3;        // 0..3
    const int rowBase = blockIdx.y * BM;
    const int colBase = blockIdx.x * 128;

    float acc[IBLK][4][4];
#pragma unroll
    for (int i = 0; i < IBLK; i++)
#pragma unroll
        for (int j = 0; j < 4; j++)
#pragma unroll
            for (int r = 0; r < 4; r++) acc[i][j][r] = 0.f;

    const int lq = lane >> 2;   // 0..7
    const int lr = lane & 3;    // 0..3

    // ---- staging registers ----
    float4 ar[IBLK];
    float4 br[4];

    const int a_m   = (IBLK == 4) ? (tid >> 1) : (tid >> 2);
    const int a_kk0 = (IBLK == 4) ? ((tid & 1) * 8) : ((tid & 3) * 8);
    const int bn_kp = tid >> 5;          // non-trans: k-pair row
    const int bn_n4 = (tid & 31) * 4;    // non-trans: n base
    const int bt_n  = tid >> 1;          // trans: n
    const int bt_kk0= (tid & 1) * 8;     // trans: k base

    const int gmA = rowBase + a_m;
    const bool aOk = (gmA < M);
    const int gnBn = colBase + bn_n4;
    const int gnBt = colBase + bt_n;

    auto loadA = [&](int k0) {
        if (IBLK == 4) {
#pragma unroll
            for (int seg = 0; seg < 2; seg++) {
                int kk = a_kk0 + seg * 16;
                if (aOk) {
                    const float* p = Ab + (ll)gmA * lda + k0 + kk;
                    ar[seg * 2 + 0] = *reinterpret_cast<const float4*>(p);
                    ar[seg * 2 + 1] = *reinterpret_cast<const float4*>(p + 4);
                } else {
                    ar[seg * 2 + 0] = make_float4(0, 0, 0, 0);
                    ar[seg * 2 + 1] = make_float4(0, 0, 0, 0);
                }
            }
        } else {
            if (aOk) {
                const float* p = Ab + (ll)gmA * lda + k0 + a_kk0;
                ar[0] = *reinterpret_cast<const float4*>(p);
                ar[1] = *reinterpret_cast<const float4*>(p + 4);
            } else {
                ar[0] = make_float4(0, 0, 0, 0);
                ar[1] = make_float4(0, 0, 0, 0);
            }
        }
    };
    auto loadB = [&](int k0) {
        if (!transB) {
#pragma unroll
            for (int seg = 0; seg < 2; seg++) {
                int kpair = bn_kp + seg * 8;
                const float* p0 = Bb + (ll)(k0 + 2 * kpair) * ldb + gnBn;
                const float* p1 = p0 + ldb;
                if (gnBn + 3 < N) {
                    br[seg * 2 + 0] = *reinterpret_cast<const float4*>(p0);
                    br[seg * 2 + 1] = *reinterpret_cast<const float4*>(p1);
                } else {
                    float u[4], w[4];
#pragma unroll
                    for (int q = 0; q < 4; q++) {
                        u[q] = (gnBn + q < N) ? p0[q] : 0.f;
                        w[q] = (gnBn + q < N) ? p1[q] : 0.f;
                    }
                    br[seg * 2 + 0] = make_float4(u[0], u[1], u[2], u[3]);
                    br[seg * 2 + 1] = make_float4(w[0], w[1], w[2], w[3]);
                }
            }
        } else {
#pragma unroll
            for (int seg = 0; seg < 2; seg++) {
                int kk = bt_kk0 + seg * 16;
                if (gnBt < N) {
                    const float* p = Bb + (ll)gnBt * ldb + k0 + kk;
                    br[seg * 2 + 0] = *reinterpret_cast<const float4*>(p);
                    br[seg * 2 + 1] = *reinterpret_cast<const float4*>(p + 4);
                } else {
                    br[seg * 2 + 0] = make_float4(0, 0, 0, 0);
                    br[seg * 2 + 1] = make_float4(0, 0, 0, 0);
                }
            }
        }
    };
    auto storeA = [&]() {
        if (IBLK == 4) {
#pragma unroll
            for (int seg = 0; seg < 2; seg++) {
                int kp0 = (a_kk0 + seg * 16) >> 1;
                float4 v0 = ar[seg * 2 + 0], v1 = ar[seg * 2 + 1];
                uint32_t h, l;
                split_pack(v0.x, v0.y, h, l); AsH[kp0 + 0][a_m] = h; AsL[kp0 + 0][a_m] = l;
                split_pack(v0.z, v0.w, h, l); AsH[kp0 + 1][a_m] = h; AsL[kp0 + 1][a_m] = l;
                split_pack(v1.x, v1.y, h, l); AsH[kp0 + 2][a_m] = h; AsL[kp0 + 2][a_m] = l;
                split_pack(v1.z, v1.w, h, l); AsH[kp0 + 3][a_m] = h; AsL[kp0 + 3][a_m] = l;
            }
        } else {
            int kp0 = a_kk0 >> 1;
            float4 v0 = ar[0], v1 = ar[1];
            uint32_t h, l;
            split_pack(v0.x, v0.y, h, l); AsH[kp0 + 0][a_m] = h; AsL[kp0 + 0][a_m] = l;
            split_pack(v0.z, v0.w, h, l); AsH[kp0 + 1][a_m] = h; AsL[kp0 + 1][a_m] = l;
            split_pack(v1.x, v1.y, h, l); AsH[kp0 + 2][a_m] = h; AsL[kp0 + 2][a_m] = l;
            split_pack(v1.z, v1.w, h, l); AsH[kp0 + 3][a_m] = h; AsL[kp0 + 3][a_m] = l;
        }
    };
    auto storeB = [&]() {
        if (!transB) {
#pragma unroll
            for (int seg = 0; seg < 2; seg++) {
                int kpair = bn_kp + seg * 8;
                float4 u4 = br[seg * 2 + 0], w4 = br[seg * 2 + 1];
                float u[4] = {u4.x, u4.y, u4.z, u4.w};
                float w[4] = {w4.x, w4.y, w4.z, w4.w};
#pragma unroll
                for (int q = 0; q < 4; q++) {
                    uint32_t h, l;
                    split_pack(u[q], w[q], h, l);
                    BsH[kpair][bn_n4 + q] = h; BsL[kpair][bn_n4 + q] = l;
                }
            }
        } else {
#pragma unroll
            for (int seg = 0; seg < 2; seg++) {
                int kp0 = (bt_kk0 + seg * 16) >> 1;
                float4 v0 = br[seg * 2 + 0], v1 = br[seg * 2 + 1];
                uint32_t h, l;
                split_pack(v0.x, v0.y, h, l); BsH[kp0 + 0][bt_n] = h; BsL[kp0 + 0][bt_n] = l;
                split_pack(v0.z, v0.w, h, l); BsH[kp0 + 1][bt_n] = h; BsL[kp0 + 1][bt_n] = l;
                split_pack(v1.x, v1.y, h, l); BsH[kp0 + 2][bt_n] = h; BsL[kp0 + 2][bt_n] = l;
                split_pack(v1.z, v1.w, h, l); BsH[kp0 + 3][bt_n] = h; BsL[kp0 + 3][bt_n] = l;
            }
        }
    };

    // ---- pipelined main loop ----
    const int nt = K / KT;
    loadA(0); loadB(0);
    storeA(); storeB();
    for (int t = 0; t < nt; t++) {
        __syncthreads();                       // smem tile t ready
        if (t + 1 < nt) { loadA((t + 1) * KT); loadB((t + 1) * KT); }

#pragma unroll
        for (int st = 0; st < 2; st++) {
            int base = st * 8;
            uint32_t aH[IBLK][4], aL[IBLK][4], bH[4][2], bL[4][2];
#pragma unroll
            for (int i = 0; i < IBLK; i++) {
                int m0 = warpRow * (IBLK * 16) + i * 16 + lq;
                aH[i][0] = AsH[base + lr][m0];     aH[i][1] = AsH[base + lr][m0 + 8];
                aH[i][2] = AsH[base + lr + 4][m0]; aH[i][3] = AsH[base + lr + 4][m0 + 8];
                aL[i][0] = AsL[base + lr][m0];     aL[i][1] = AsL[base + lr][m0 + 8];
                aL[i][2] = AsL[base + lr + 4][m0]; aL[i][3] = AsL[base + lr + 4][m0 + 8];
            }
#pragma unroll
            for (int j = 0; j < 4; j++) {
                int n0 = warpCol * 32 + j * 8 + lq;
                bH[j][0] = BsH[base + lr][n0]; bH[j][1] = BsH[base + lr + 4][n0];
                bL[j][0] = BsL[base + lr][n0]; bL[j][1] = BsL[base + lr + 4][n0];
            }
#pragma unroll
            for (int i = 0; i < IBLK; i++)
#pragma unroll
                for (int j = 0; j < 4; j++) MMA_BF16(acc[i][j], aH[i], bL[j]);
#pragma unroll
            for (int i = 0; i < IBLK; i++)
#pragma unroll
                for (int j = 0; j < 4; j++) MMA_BF16(acc[i][j], aL[i], bH[j]);
#pragma unroll
            for (int i = 0; i < IBLK; i++)
#pragma unroll
                for (int j = 0; j < 4; j++) MMA_BF16(acc[i][j], aH[i], bH[j]);
        }
        __syncthreads();                       // done reading smem tile t
        if (t + 1 < nt) { storeA(); storeB(); }
    }

    // ---- epilogue ----
#pragma unroll
    for (int i = 0; i < IBLK; i++) {
#pragma unroll
        for (int r2 = 0; r2 < 2; r2++) {
            int gm = rowBase + warpRow * (IBLK * 16) + i * 16 + lq + r2 * 8;
            if (gm >= M) continue;
            float* crow = Cb + (ll)gm * ldc;
#pragma unroll
            for (int j = 0; j < 4; j++) {
                int gn = colBase + warpCol * 32 + j * 8 + lr * 2;
                float v0 = alpha * acc[i][j][r2 * 2 + 0];
                float v1 = alpha * acc[i][j][r2 * 2 + 1];
                if (gn < N) {
                    if (accumulate) crow[gn] += v0; else crow[gn] = v0;
                }
                if (gn + 1 < N) {
                    if (accumulate) crow[gn + 1] += v1; else crow[gn + 1] = v1;
                }
            }
        }
    }
}

static void gemm(const float* A, const float* Bm, float* C, int M, int N, int K,
                 int lda, int ldb, int ldc, int batch, int HB,
                 ll sAo, ll sAi, ll sBo, ll sBi, ll sCo, ll sCi,
                 float alpha, int accum, int transB, int gateMode,
                 const float* B1 = nullptr, const float* B2 = nullptr,
                 int multiB = 0) {
    int nx = (N + 127) / 128;
    ll blocks128 = (ll)nx * ((M + 127) / 128) * batch;
    if (blocks128 < 296 && (M % 64) == 0) {
        dim3 grid(nx, M / 64, batch);
        gemm_bf16x2_k<2><<<grid, 256>>>(A, Bm, C, B1, B2, multiB,
                                        M, N, K, lda, ldb, ldc,
                                        HB, sAo, sAi, sBo, sBi, sCo, sCi,
                                        alpha, accum, transB, gateMode);
    } else {
        dim3 grid(nx, (M + 127) / 128, batch);
        gemm_bf16x2_k<4><<<grid, 256>>>(A, Bm, C, B1, B2, multiB,
                                        M, N, K, lda, ldb, ldc,
                                        HB, sAo, sAi, sBo, sBi, sCo, sCi,
                                        alpha, accum, transB, gateMode);
    }
}

// ---------------------------------------------------------------------------
extern "C" void kernel_launch(void* const* d_in, const int* in_sizes, int n_in,
                              void* d_out, int out_size) {
    const int*   ids        = (const int*)  d_in[0];
    const float* embed      = (const float*)d_in[1];
    const float* wq         = (const float*)d_in[2];
    const float* wk         = (const float*)d_in[3];
    const float* wv         = (const float*)d_in[4];
    const float* wo         = (const float*)d_in[5];
    const float* w1         = (const float*)d_in[6];
    const float* w2         = (const float*)d_in[7];
    const float* w3         = (const float*)d_in[8];
    const float* norm1      = (const float*)d_in[9];
    const float* norm2      = (const float*)d_in[10];
    const float* final_norm = (const float*)d_in[11];
    const float* lm_head    = (const float*)d_in[12];
    const float* exit_w     = (const float*)d_in[13];
    const float* exit_b     = (const float*)d_in[14];
    const float* skip_w     = (const float*)d_in[15];
    const float* skip_b     = (const float*)d_in[16];
    float* out = (float*)d_out;

    float *px, *ph, *pqkv, *pao, *psc, *pf13, *phl;
    cudaGetSymbolAddress((void**)&px,   g_x);
    cudaGetSymbolAddress((void**)&ph,   g_h);
    cudaGetSymbolAddress((void**)&pqkv, g_qkv);
    cudaGetSymbolAddress((void**)&pao,  g_ao);
    cudaGetSymbolAddress((void**)&psc,  g_sc);
    cudaGetSymbolAddress((void**)&pf13, g_f13);
    cudaGetSymbolAddress((void**)&phl,  g_hlast);
    float* pq = pqkv;
    float* pk = pqkv + (ll)BTD;
    float* pv = pqkv + 2ll * BTD;
    float* pf1 = pf13;

    init_k<<<1, 32>>>();
    rope_tables_k<<<(T_ * (HD_ / 2)) / 256, 256>>>();
    embed_k<<<(B_ * T_ * D_) / 256, 256>>>(ids, embed);

    for (int li = 0; li < L_; li++) {
        const float* wq_l = wq + (ll)li * D_ * D_;
        const float* wk_l = wk + (ll)li * D_ * D_;
        const float* wv_l = wv + (ll)li * D_ * D_;
        const float* wo_l = wo + (ll)li * D_ * D_;
        const float* w1_l = w1 + (ll)li * D_ * F_;
        const float* w2_l = w2 + (ll)li * F_ * D_;
        const float* w3_l = w3 + (ll)li * D_ * F_;

        // 1) skip decision (uses x BEFORE the block)
        compute_skip_k<<<1, 128>>>(px, skip_w + (ll)li * D_, skip_b + li, li);

        // 2) transformer block (gated by do_skip)
        rmsnorm_k<<<B_ * T_, 256>>>(px, norm1 + (ll)li * D_, ph, D_, D_, 1, 1);
        // fused QKV: z selects wq/wk/wv, C = g_qkv + z*BTD
        gemm(ph, wq_l, pqkv, B_ * T_, D_, D_, D_, D_, D_, 3, 1,
             0, 0, 0, 0, (ll)BTD, 0, 1.f, 0, 0, 1, wk_l, wv_l, 1);
        // RoPE over q and k (contiguous)
        rope_k<<<(2 * B_ * T_ * D_ / 2) / 256, 256>>>(pq);
        // scores = (Q @ K^T) / sqrt(HD), batched over (b,h)
        gemm(pq, pk, psc, T_, T_, HD_, D_, D_, T_, B_ * H_, H_,
             (ll)T_ * D_, HD_, (ll)T_ * D_, HD_, (ll)H_ * T_ * T_, (ll)T_ * T_,
             0.125f, 0, 1, 1);
        softmax_k<<<B_ * H_ * T_, 256>>>();
        // o = att @ V -> (B,T,H,HD)
        gemm(psc, pv, pao, T_, HD_, T_, T_, D_, D_, B_ * H_, H_,
             (ll)H_ * T_ * T_, (ll)T_ * T_, (ll)T_ * D_, HD_, (ll)T_ * D_, HD_,
             1.f, 0, 0, 1);
        // x += o @ wo
        gemm(pao, wo_l, px, B_ * T_, D_, D_, D_, D_, D_, 1, 1, 0,0,0,0,0,0, 1.f, 1, 0, 1);
        // FFN
        rmsnorm_k<<<B_ * T_, 256>>>(px, norm2 + (ll)li * D_, ph, D_, D_, 1, 1);
        gemm(ph, w1_l, pf13, B_ * T_, F_, D_, D_, F_, F_, 2, 1,
             0, 0, 0, 0, (ll)BTF, 0, 1.f, 0, 0, 1, w3_l, nullptr, 1);
        silu_mul_k<<<(B_ * T_ * F_) / 256, 256>>>();
        gemm(pf1, w2_l, px, B_ * T_, D_, F_, F_, D_, D_, 1, 1, 0,0,0,0,0,0, 1.f, 1, 0, 1);

        // 3) exit logic: last-position logits + confidence
        rmsnorm_k<<<B_, 256>>>(px + (ll)(T_ - 1) * D_, final_norm, phl,
                               (ll)T_ * D_, D_, 1, 1);
        logits_last_k<<<dim3(V_ / 256, B_), 256>>>(lm_head);
        exit_decide_k<<<1, 256>>>(px, exit_w + (ll)li * D_, exit_b + li, li);

        // 4) full logits only for newly-exited batches
        rmsnorm_k<<<B_ * T_, 256>>>(px, final_norm, ph, D_, D_, 2, T_);
        gemm(ph, lm_head, out, T_, V_, D_, D_, V_, V_, B_, 1,
             (ll)T_ * D_, 0, 0, 0, (ll)T_ * V_, 0, 1.f, 0, 0, 2);
    }

    // final logits for batches that never exited
    finalize_k<<<1, 32>>>();
    rmsnorm_k<<<B_ * T_, 256>>>(px, final_norm, ph, D_, D_, 2, T_);
    gemm(ph, lm_head, out, T_, V_, D_, D_, V_, V_, B_, 1,
         (ll)T_ * D_, 0, 0, 0, (ll)T_ * V_, 0, 1.f, 0, 0, 2);

    if (out_size >= B_ * T_ * V_ + B_)
        write_exl_k<<<1, 32>>>(out + (ll)B_ * T_ * V_);
}

// round 9
// speedup vs baseline: 3.9797x; 1.3180x over previous
#include <cuda_runtime.h>
#include <cuda_bf16.h>
#include <math.h>
#include <stdint.h>

#define B_ 4
#define T_ 256
#define D_ 1024
#define H_ 16
#define HD_ 64
#define F_ 4096
#define L_ 6
#define V_ 32000

typedef long long ll;

#define BTD (B_*T_*D_)
#define BTF (B_*T_*F_)
#define MT  (B_*T_)          // 1024 total rows of activations

// pair counts for packed (bf16x2) tensors
#define WQPAIRS (L_*(D_/2)*D_)       // 3,145,728  (wq/wk/wv/wo each)
#define W1PAIRS (L_*(D_/2)*F_)       // 12,582,912 (w1 / w3 each)
#define W2PAIRS (L_*(F_/2)*D_)       // 12,582,912
#define LMPAIRS ((D_/2)*V_)          // 16,384,000
#define TOTPAIRS (4ll*WQPAIRS + 2ll*W1PAIRS + (ll)W2PAIRS + (ll)LMPAIRS)

#define HPN  ((D_/2)*MT)             // h / ao packs
#define F1PN ((F_/2)*MT)             // f1 pack

// ---------------- scratch (static device memory, no allocs) ----------------
__device__ float g_x  [BTD];
__device__ float g_qkv[3*BTD];      // q | k | v contiguous
__device__ float g_ao [BTD];
__device__ float g_sc [B_*H_*T_*T_];
__device__ float g_f13[2*BTF];      // f1 | f3 contiguous
__device__ float g_hlast[B_*D_];
__device__ float g_ll[B_*V_];
__device__ float g_cos[T_*(HD_/2)];
__device__ float g_sin[T_*(HD_/2)];

// packed activations  [kp][MT]
__device__ uint32_t g_hpH [HPN],  g_hpL [HPN];
__device__ uint32_t g_aopH[HPN],  g_aopL[HPN];
__device__ uint32_t g_f1pH[F1PN], g_f1pL[F1PN];
// packed weights  [L*K/2][N]
__device__ uint32_t g_wqH[WQPAIRS], g_wqL[WQPAIRS];
__device__ uint32_t g_wkH[WQPAIRS], g_wkL[WQPAIRS];
__device__ uint32_t g_wvH[WQPAIRS], g_wvL[WQPAIRS];
__device__ uint32_t g_woH[WQPAIRS], g_woL[WQPAIRS];
__device__ uint32_t g_w1H[W1PAIRS], g_w1L[W1PAIRS];
__device__ uint32_t g_w3H[W1PAIRS], g_w3L[W1PAIRS];
__device__ uint32_t g_w2H[W2PAIRS], g_w2L[W2PAIRS];
__device__ uint32_t g_lmH[LMPAIRS], g_lmL[LMPAIRS];

// ---------------- control flags ----------------
__device__ int d_do_skip;
__device__ int d_exited[B_];
__device__ int d_newly[B_];
__device__ int d_exl[B_];

// ---------------------------------------------------------------------------
__device__ __forceinline__ void split_pack(float x0, float x1,
                                           uint32_t& hi, uint32_t& lo) {
    __nv_bfloat16 h0 = __float2bfloat16(x0);
    __nv_bfloat16 h1 = __float2bfloat16(x1);
    __nv_bfloat16 l0 = __float2bfloat16(x0 - __bfloat162float(h0));
    __nv_bfloat16 l1 = __float2bfloat16(x1 - __bfloat162float(h1));
    hi = ((uint32_t)__bfloat16_as_ushort(h1) << 16) | __bfloat16_as_ushort(h0);
    lo = ((uint32_t)__bfloat16_as_ushort(l1) << 16) | __bfloat16_as_ushort(l0);
}

__global__ void init_k() {
    int t = threadIdx.x;
    if (t < B_) { d_exited[t] = 0; d_newly[t] = 0; d_exl[t] = -1; }
    if (t == 0) d_do_skip = 0;
}

__global__ void finalize_k() {
    int t = threadIdx.x;
    if (t < B_) {
        int nv = d_exited[t] ? 0 : 1;
        d_newly[t] = nv;
        if (nv) d_exl[t] = L_ - 1;
    }
    if (t == 0) d_do_skip = 0;
}

__global__ void write_exl_k(float* out) {
    int t = threadIdx.x;
    if (t < B_) out[t] = (float)d_exl[t];
}

__global__ void rope_tables_k() {
    int idx = blockIdx.x * 256 + threadIdx.x;
    int t = idx >> 5;
    int i = idx & 31;
    float inv = expf(-logf(10000.f) * (2.f * (float)i) / (float)HD_);
    float f = (float)t * inv;
    g_cos[idx] = cosf(f);
    g_sin[idx] = sinf(f);
}

__global__ void embed_k(const int* __restrict__ ids, const float* __restrict__ emb) {
    ll idx = (ll)blockIdx.x * 256 + threadIdx.x;
    int tok = ids[idx >> 10];
    g_x[idx] = emb[(ll)tok * D_ + (idx & 1023)];
}

// ---- weight prepack: fp32 [K][N] -> hi/lo packed uint32 [K/2][N] ----------
__global__ void prepack_k(const float* __restrict__ wq, const float* __restrict__ wk,
                          const float* __restrict__ wv, const float* __restrict__ wo,
                          const float* __restrict__ w1, const float* __restrict__ w2,
                          const float* __restrict__ w3, const float* __restrict__ lm) {
    ll gid = (ll)blockIdx.x * 256 + threadIdx.x;
    if (gid >= TOTPAIRS) return;
    const float* src; uint32_t *dH, *dL; ll idx; int cols;
    ll c4 = 4ll * WQPAIRS;
    if (gid < (ll)WQPAIRS)        { src = wq; dH = g_wqH; dL = g_wqL; idx = gid; cols = D_; }
    else if (gid < 2ll*WQPAIRS)   { src = wk; dH = g_wkH; dL = g_wkL; idx = gid - WQPAIRS; cols = D_; }
    else if (gid < 3ll*WQPAIRS)   { src = wv; dH = g_wvH; dL = g_wvL; idx = gid - 2ll*WQPAIRS; cols = D_; }
    else if (gid < c4)            { src = wo; dH = g_woH; dL = g_woL; idx = gid - 3ll*WQPAIRS; cols = D_; }
    else if (gid < c4 + W1PAIRS)  { src = w1; dH = g_w1H; dL = g_w1L; idx = gid - c4; cols = F_; }
    else if (gid < c4 + 2ll*W1PAIRS) { src = w3; dH = g_w3H; dL = g_w3L; idx = gid - c4 - W1PAIRS; cols = F_; }
    else if (gid < c4 + 2ll*W1PAIRS + W2PAIRS)
                                  { src = w2; dH = g_w2H; dL = g_w2L; idx = gid - c4 - 2ll*W1PAIRS; cols = D_; }
    else                          { src = lm; dH = g_lmH; dL = g_lmL; idx = gid - c4 - 2ll*W1PAIRS - W2PAIRS; cols = V_; }
    ll kp = idx / cols;
    int col = (int)(idx - kp * cols);
    float a = src[(2*kp)     * (ll)cols + col];
    float b = src[(2*kp + 1) * (ll)cols + col];
    uint32_t h, l;
    split_pack(a, b, h, l);
    dH[idx] = h; dL[idx] = l;
}

// in-place RoPE on q and k together; layout (2B,T,H,HD)
__global__ void rope_k(float* __restrict__ q) {
    if (d_do_skip) return;
    int idx = blockIdx.x * 256 + threadIdx.x;
    int i = idx & 31;
    int t = (idx >> 9) & 255;
    ll base = (ll)(idx >> 5) * HD_ + i;
    float c = g_cos[t * 32 + i], s = g_sin[t * 32 + i];
    float x1 = q[base], x2 = q[base + 32];
    q[base]      = x1 * c - x2 * s;
    q[base + 32] = x1 * s + x2 * c;
}

// causal softmax over rows of scores (B,H,T,T)
__global__ void softmax_k() {
    if (d_do_skip) return;
    int r = blockIdx.x;
    int qrow = r & (T_ - 1);
    float* row = g_sc + (ll)r * T_;
    int tid = threadIdx.x;
    float v = (tid <= qrow) ? row[tid] : -3.4e38f;
    __shared__ float red[256];
    red[tid] = v; __syncthreads();
    for (int o = 128; o > 0; o >>= 1) { if (tid < o) red[tid] = fmaxf(red[tid], red[tid + o]); __syncthreads(); }
    float m = red[0]; __syncthreads();
    float e = (tid <= qrow) ? expf(v - m) : 0.f;
    red[tid] = e; __syncthreads();
    for (int o = 128; o > 0; o >>= 1) { if (tid < o) red[tid] += red[tid + o]; __syncthreads(); }
    row[tid] = e / red[0];
}

// silu(f1)*f3 -> packed f1 [F/2][MT] via smem transpose (coalesced both sides)
__global__ void silu_pack_k() {
    if (d_do_skip) return;
    __shared__ float t1[64][65];
    __shared__ float t3[64][65];
    int f0 = blockIdx.x * 64;
    int m0 = blockIdx.y * 64;
    int tid = threadIdx.x;
#pragma unroll
    for (int it = 0; it < 16; it++) {
        int id = it * 256 + tid;
        int mm = id >> 6, ff = id & 63;
        t1[mm][ff] = g_f13[(ll)(m0 + mm) * F_ + f0 + ff];
        t3[mm][ff] = g_f13[(ll)(m0 + mm) * F_ + f0 + ff + (ll)BTF];
    }
    __syncthreads();
#pragma unroll
    for (int it = 0; it < 8; it++) {
        int id = it * 256 + tid;
        int fp = id >> 6, m = id & 63;
        float a0 = t1[m][2*fp],   b0 = t3[m][2*fp];
        float a1 = t1[m][2*fp+1], b1 = t3[m][2*fp+1];
        float v0 = (a0 / (1.f + expf(-a0))) * b0;
        float v1 = (a1 / (1.f + expf(-a1))) * b1;
        uint32_t h, l;
        split_pack(v0, v1, h, l);
        ll o = (ll)(f0/2 + fp) * MT + m0 + m;
        g_f1pH[o] = h; g_f1pL[o] = l;
    }
}

// rmsnorm: one block per row, D_=1024, 256 threads x float4
// outF nullable (fp32 out); packOut -> write g_hp{H,L} [kp][MT] column=row
// gateMode: 0 none, 1 skip-if-do_skip, 2 run-if-newly[row/rowsPerBatch]
__global__ void rmsnorm_k(const float* __restrict__ in, const float* __restrict__ w,
                          float* outF, ll inStride, ll outStride,
                          int gateMode, int rowsPerBatch, int packOut) {
    if (gateMode == 1 && d_do_skip) return;
    int row = blockIdx.x;
    if (gateMode == 2 && !d_newly[row / rowsPerBatch]) return;
    const float* xr = in + (ll)row * inStride;
    int tid = threadIdx.x;
    float4 v = reinterpret_cast<const float4*>(xr)[tid];
    float s = v.x * v.x + v.y * v.y + v.z * v.z + v.w * v.w;
    __shared__ float red[256];
    red[tid] = s; __syncthreads();
    for (int o = 128; o > 0; o >>= 1) { if (tid < o) red[tid] += red[tid + o]; __syncthreads(); }
    float scale = rsqrtf(red[0] * (1.f / (float)D_) + 1e-6f);
    float4 wv = reinterpret_cast<const float4*>(w)[tid];
    float4 ov;
    ov.x = v.x * wv.x * scale; ov.y = v.y * wv.y * scale;
    ov.z = v.z * wv.z * scale; ov.w = v.w * wv.w * scale;
    if (outF) reinterpret_cast<float4*>(outF + (ll)row * outStride)[tid] = ov;
    if (packOut) {
        uint32_t h, l;
        split_pack(ov.x, ov.y, h, l);
        g_hpH[(ll)(2*tid)   * MT + row] = h; g_hpL[(ll)(2*tid)   * MT + row] = l;
        split_pack(ov.z, ov.w, h, l);
        g_hpH[(ll)(2*tid+1) * MT + row] = h; g_hpL[(ll)(2*tid+1) * MT + row] = l;
    }
}

// last-position logits: g_ll[b,v] = dot(g_hlast[b,:], lm_head[:,v])
__global__ void logits_last_k(const float* __restrict__ lm_head) {
    if (d_do_skip) return;
    int b = blockIdx.y;
    int v = blockIdx.x * 256 + threadIdx.x;
    __shared__ float hs[D_];
    for (int i = threadIdx.x; i < D_; i += 256) hs[i] = g_hlast[b * D_ + i];
    __syncthreads();
    float acc = 0.f;
    const float* col = lm_head + v;
#pragma unroll 4
    for (int d = 0; d < D_; d++) acc = fmaf(hs[d], col[(ll)d * V_], acc);
    g_ll[(ll)b * V_ + v] = acc;
}

// warp-per-batch skip decision
__global__ void compute_skip_k(const float* __restrict__ x,
                               const float* __restrict__ sw,
                               const float* __restrict__ sb, int li) {
    int tid = threadIdx.x;
    int w = tid >> 5, l = tid & 31;
    __shared__ float sp[B_];
    if (w < B_) {
        const float* xr = x + ((ll)w * T_ + (T_ - 1)) * D_;
        float s = 0.f;
#pragma unroll 8
        for (int i = l; i < D_; i += 32) s += xr[i] * sw[i];
#pragma unroll
        for (int o = 16; o > 0; o >>= 1) s += __shfl_down_sync(0xffffffff, s, o);
        if (l == 0) sp[w] = 1.f / (1.f + expf(-(s + sb[0])));
    }
    __syncthreads();
    if (tid == 0) {
        float cnt = 0.f, s = 0.f;
        for (int b = 0; b < B_; b++) {
            float a = d_exited[b] ? 0.f : 1.f;
            cnt += a; s += sp[b] * a;
        }
        float mean = s / fmaxf(cnt, 1.f);
        d_do_skip = (li >= 1 && cnt > 0.f && mean < 0.1f) ? 1 : 0;
    }
}

// parallel exit decision: 4 batches x 64 threads
__global__ void exit_decide_k(const float* __restrict__ x,
                              const float* __restrict__ ew,
                              const float* __restrict__ eb, int li) {
    int tid = threadIdx.x;
    if (d_do_skip) { if (tid < B_) d_newly[tid] = 0; return; }
    __shared__ float red[256];
    __shared__ float mxs[B_], sums[B_], eps_[B_];
    int b = tid >> 6, l = tid & 63;
    const float* lr = g_ll + (ll)b * V_;
    float m = -3.4e38f;
    for (int i = l; i < V_; i += 64) m = fmaxf(m, lr[i]);
    red[tid] = m; __syncthreads();
    for (int o = 32; o > 0; o >>= 1) { if (l < o) red[tid] = fmaxf(red[tid], red[tid + o]); __syncthreads(); }
    if (l == 0) mxs[b] = red[tid];
    __syncthreads();
    float mx = mxs[b];
    float s = 0.f;
    for (int i = l; i < V_; i += 64) s += expf(lr[i] - mx);
    red[tid] = s; __syncthreads();
    for (int o = 32; o > 0; o >>= 1) { if (l < o) red[tid] += red[tid + o]; __syncthreads(); }
    if (l == 0) sums[b] = red[tid];
    __syncthreads();
    const float* xr = x + ((ll)b * T_ + (T_ - 1)) * D_;
    float e = 0.f;
    for (int i = l; i < D_; i += 64) e += xr[i] * ew[i];
    red[tid] = e; __syncthreads();
    for (int o = 32; o > 0; o >>= 1) { if (l < o) red[tid] += red[tid + o]; __syncthreads(); }
    if (l == 0) eps_[b] = 1.f / (1.f + expf(-(red[tid] + eb[0])));
    __syncthreads();
    if (tid < B_) {
        int bb = tid;
        float conf = 1.f / sums[bb];
        int should = (conf > 0.9f) || (eps_[bb] > 0.9f);
        int nw = (should && !d_exited[bb]) ? 1 : 0;
        d_newly[bb] = nw;
        if (nw) { d_exited[bb] = 1; d_exl[bb] = li; }
    }
}

#define MMA_BF16(acc, a, b)                                                   \
    asm volatile(                                                             \
        "mma.sync.aligned.m16n8k16.row.col.f32.bf16.bf16.f32 "                \
        "{%0,%1,%2,%3}, {%4,%5,%6,%7}, {%8,%9}, {%0,%1,%2,%3};"               \
        : "+f"(acc[0]), "+f"(acc[1]), "+f"(acc[2]), "+f"(acc[3])              \
        : "r"(a[0]), "r"(a[1]), "r"(a[2]), "r"(a[3]), "r"(b[0]), "r"(b[1]))

// =====================  fast cp.async GEMM on packed operands ==============
// A: packed [K/2][MT] hi/lo (aSel 0=h,1=ao,2=f1). B: packed weights (wSel).
// C fp32 [M][ldc]. BM = IBLK*32, BN=128, KT=32, STG-stage cp.async pipeline.
template <int IBLK, int STG>
__global__ __launch_bounds__(256, (IBLK == 2) ? 2 : 1) void gemm_ws_k(
    int aSel, int wSel, int li, float* __restrict__ C,
    int M, int N, int K, int ldbU, int ldc,
    int aColStride, ll sCo, int accumulate, int gateMode) {
    if (gateMode == 1 && d_do_skip) return;
    if (gateMode == 2 && !d_newly[blockIdx.z]) return;
    constexpr int BM = IBLK * 32;
    constexpr int SPA = BM + 8;
    constexpr int SPB = 136;
    constexpr int KP = 16;                 // k-pairs per tile (KT=32)
    constexpr int AS = KP * SPA, BS = KP * SPB;
    constexpr int STAGE = 2 * AS + 2 * BS;
    constexpr int ACHROW = BM / 4;         // 16B chunks per A row
    constexpr int ACH = KP * ACHROW;
    constexpr int BCH = KP * 32;
    constexpr int TCH = 2 * ACH + 2 * BCH;

    extern __shared__ uint32_t sm[];
    const int z = blockIdx.z;

    const uint32_t* aHp = (aSel == 0) ? g_hpH : ((aSel == 1) ? g_aopH : g_f1pH);
    const uint32_t* aLp = (aSel == 0) ? g_hpL : ((aSel == 1) ? g_aopL : g_f1pL);
    const uint32_t *bHp, *bLp;
    {
        ll off;
        switch (wSel) {
        case 0:
            off = (ll)li * (D_/2) * D_;
            bHp = ((z == 0) ? g_wqH : ((z == 1) ? g_wkH : g_wvH)) + off;
            bLp = ((z == 0) ? g_wqL : ((z == 1) ? g_wkL : g_wvL)) + off;
            break;
        case 1:
            off = (ll)li * (D_/2) * D_;
            bHp = g_woH + off; bLp = g_woL + off; break;
        case 2:
            off = (ll)li * (D_/2) * F_;
            bHp = ((z == 0) ? g_w1H : g_w3H) + off;
            bLp = ((z == 0) ? g_w1L : g_w3L) + off; break;
        case 3:
            off = (ll)li * (F_/2) * D_;
            bHp = g_w2H + off; bLp = g_w2L + off; break;
        default:
            bHp = g_lmH; bLp = g_lmL; break;
        }
    }
    const int aOff = z * aColStride;
    float* Cb = C + (ll)z * sCo;

    const int tid = threadIdx.x;
    const int lane = tid & 31;
    const int warp = tid >> 5;
    const int warpRow = warp >> 2;
    const int warpCol = warp & 3;
    const int rowBase = blockIdx.y * BM;
    const int colBase = blockIdx.x * 128;
    const int lq = lane >> 2;
    const int lr = lane & 3;

    auto loadTile = [&](int t, int s) {
        uint32_t* st = sm + s * STAGE;
        int kp0 = t * KP;
#pragma unroll
        for (int c = tid; c < TCH; c += 256) {
            uint32_t* dst; const uint32_t* src;
            if (c < 2 * ACH) {
                int cc = c; const uint32_t* g = aHp; uint32_t* ss = st;
                if (cc >= ACH) { cc -= ACH; g = aLp; ss = st + AS; }
                int row = cc / ACHROW, col = (cc % ACHROW) * 4;
                dst = ss + row * SPA + col;
                src = g + (ll)(kp0 + row) * MT + aOff + rowBase + col;
            } else {
                int cc = c - 2 * ACH; const uint32_t* g = bHp; uint32_t* ss = st + 2 * AS;
                if (cc >= BCH) { cc -= BCH; g = bLp; ss += BS; }
                int row = cc >> 5, col = (cc & 31) * 4;
                dst = ss + row * SPB + col;
                src = g + (ll)(kp0 + row) * ldbU + colBase + col;
            }
            uint32_t da = (uint32_t)__cvta_generic_to_shared(dst);
            asm volatile("cp.async.cg.shared.global [%0], [%1], 16;\n"
                         :: "r"(da), "l"(src));
        }
        asm volatile("cp.async.commit_group;\n");
    };

    float acc[IBLK][4][4];
#pragma unroll
    for (int i = 0; i < IBLK; i++)
#pragma unroll
        for (int j = 0; j < 4; j++)
#pragma unroll
            for (int r = 0; r < 4; r++) acc[i][j][r] = 0.f;

    const int nt = K / 32;
#pragma unroll
    for (int s = 0; s < STG - 1; s++) loadTile(s, s);

    for (int t = 0; t < nt; t++) {
        asm volatile("cp.async.wait_group %0;\n" :: "n"(STG - 2));
        __syncthreads();
        int tn = t + STG - 1;
        if (tn < nt) loadTile(tn, tn % STG);
        else asm volatile("cp.async.commit_group;\n");

        const uint32_t* AsH = sm + (t % STG) * STAGE;
        const uint32_t* AsL = AsH + AS;
        const uint32_t* BsH = AsH + 2 * AS;
        const uint32_t* BsL = BsH + BS;
#pragma unroll
        for (int st2 = 0; st2 < 2; st2++) {
            int base = st2 * 8;
            uint32_t aH[IBLK][4], aL[IBLK][4], bH[4][2], bL[4][2];
#pragma unroll
            for (int i = 0; i < IBLK; i++) {
                int m0 = warpRow * (IBLK * 16) + i * 16 + lq;
                aH[i][0] = AsH[(base + lr) * SPA + m0];
                aH[i][1] = AsH[(base + lr) * SPA + m0 + 8];
                aH[i][2] = AsH[(base + lr + 4) * SPA + m0];
                aH[i][3] = AsH[(base + lr + 4) * SPA + m0 + 8];
                aL[i][0] = AsL[(base + lr) * SPA + m0];
                aL[i][1] = AsL[(base + lr) * SPA + m0 + 8];
                aL[i][2] = AsL[(base + lr + 4) * SPA + m0];
                aL[i][3] = AsL[(base + lr + 4) * SPA + m0 + 8];
            }
#pragma unroll
            for (int j = 0; j < 4; j++) {
                int n0 = warpCol * 32 + j * 8 + lq;
                bH[j][0] = BsH[(base + lr) * SPB + n0];
                bH[j][1] = BsH[(base + lr + 4) * SPB + n0];
                bL[j][0] = BsL[(base + lr) * SPB + n0];
                bL[j][1] = BsL[(base + lr + 4) * SPB + n0];
            }
#pragma unroll
            for (int i = 0; i < IBLK; i++)
#pragma unroll
                for (int j = 0; j < 4; j++) MMA_BF16(acc[i][j], aH[i], bL[j]);
#pragma unroll
            for (int i = 0; i < IBLK; i++)
#pragma unroll
                for (int j = 0; j < 4; j++) MMA_BF16(acc[i][j], aL[i], bH[j]);
#pragma unroll
            for (int i = 0; i < IBLK; i++)
#pragma unroll
                for (int j = 0; j < 4; j++) MMA_BF16(acc[i][j], aH[i], bH[j]);
        }
    }

#pragma unroll
    for (int i = 0; i < IBLK; i++) {
#pragma unroll
        for (int r2 = 0; r2 < 2; r2++) {
            int gm = rowBase + warpRow * (IBLK * 16) + i * 16 + lq + r2 * 8;
            if (gm >= M) continue;
            float* crow = Cb + (ll)gm * ldc;
#pragma unroll
            for (int j = 0; j < 4; j++) {
                int gn = colBase + warpCol * 32 + j * 8 + lr * 2;
                float v0 = acc[i][j][r2 * 2 + 0];
                float v1 = acc[i][j][r2 * 2 + 1];
                if (gn < N)     { if (accumulate) crow[gn] += v0;     else crow[gn] = v0; }
                if (gn + 1 < N) { if (accumulate) crow[gn + 1] += v1; else crow[gn + 1] = v1; }
            }
        }
    }
}

#define SMEM_WS2 (3 * (2*16*(64+8) + 2*16*136) * 4)
#define SMEM_WS4 (4 * (2*16*(128+8) + 2*16*136) * 4)

static void gemm_fast(int aSel, int wSel, int li, float* C,
                      int M, int N, int K, int ldbU, int ldc,
                      int batch, int aColStride, ll sCo, int acc, int gate) {
    int nx = N / 128;
    int b128 = nx * (M / 128) * batch;
    if (b128 < 296) {
        dim3 g(nx, M / 64, batch);
        gemm_ws_k<2, 3><<<g, 256, SMEM_WS2>>>(aSel, wSel, li, C, M, N, K, ldbU, ldc,
                                              aColStride, sCo, acc, gate);
    } else {
        dim3 g(nx, M / 128, batch);
        gemm_ws_k<4, 4><<<g, 256, SMEM_WS4>>>(aSel, wSel, li, C, M, N, K, ldbU, ldc,
                                              aColStride, sCo, acc, gate);
    }
}

// ============= legacy register-staged GEMM (QK^T and AV paths) =============
#define KT 32

template <int IBLK>
__global__ __launch_bounds__(256, (IBLK == 2) ? 2 : 1) void gemm_bf16x2_k(
    const float* __restrict__ A, const float* __restrict__ Bm, float* __restrict__ C,
    int M, int N, int K, int lda, int ldb, int ldc,
    int HB, ll sAo, ll sAi, ll sBo, ll sBi, ll sCo, ll sCi,
    float alpha, int accumulate, int transB, int gateMode, int splitOut) {
    if (gateMode == 1 && d_do_skip) return;
    constexpr int BM = IBLK * 32;
    constexpr int SPA = BM + 8;
    constexpr int SPB = 136;

    int z = blockIdx.z;
    const float* Ab = A  + (ll)(z / HB) * sAo + (ll)(z % HB) * sAi;
    const float* Bb = Bm + (ll)(z / HB) * sBo + (ll)(z % HB) * sBi;
    float*       Cb = C  + (ll)(z / HB) * sCo + (ll)(z % HB) * sCi;

    __shared__ uint32_t AsH[KT/2][SPA], AsL[KT/2][SPA];
    __shared__ uint32_t BsH[KT/2][SPB], BsL[KT/2][SPB];

    const int tid = threadIdx.x;
    const int lane = tid & 31;
    const int warp = tid >> 5;
    const int warpRow = warp >> 2;
    const int warpCol = warp & 3;
    const int rowBase = blockIdx.y * BM;
    const int colBase = blockIdx.x * 128;

    float acc[IBLK][4][4];
#pragma unroll
    for (int i = 0; i < IBLK; i++)
#pragma unroll
        for (int j = 0; j < 4; j++)
#pragma unroll
            for (int r = 0; r < 4; r++) acc[i][j][r] = 0.f;

    const int lq = lane >> 2;
    const int lr = lane & 3;

    float4 ar[IBLK];
    float4 br[4];

    const int a_m   = (IBLK == 4) ? (tid >> 1) : (tid >> 2);
    const int a_kk0 = (IBLK == 4) ? ((tid & 1) * 8) : ((tid & 3) * 8);
    const int bn_kp = tid >> 5;
    const int bn_n4 = (tid & 31) * 4;
    const int bt_n  = tid >> 1;
    const int bt_kk0= (tid & 1) * 8;

    const int gmA = rowBase + a_m;
    const bool aOk = (gmA < M);
    const int gnBn = colBase + bn_n4;
    const int gnBt = colBase + bt_n;

    auto loadA = [&](int k0) {
        if (IBLK == 4) {
#pragma unroll
            for (int seg = 0; seg < 2; seg++) {
                int kk = a_kk0 + seg * 16;
                if (aOk) {
                    const float* p = Ab + (ll)gmA * lda + k0 + kk;
                    ar[seg * 2 + 0] = *reinterpret_cast<const float4*>(p);
                    ar[seg * 2 + 1] = *reinterpret_cast<const float4*>(p + 4);
                } else {
                    ar[seg * 2 + 0] = make_float4(0, 0, 0, 0);
                    ar[seg * 2 + 1] = make_float4(0, 0, 0, 0);
                }
            }
        } else {
            if (aOk) {
                const float* p = Ab + (ll)gmA * lda + k0 + a_kk0;
                ar[0] = *reinterpret_cast<const float4*>(p);
                ar[1] = *reinterpret_cast<const float4*>(p + 4);
            } else {
                ar[0] = make_float4(0, 0, 0, 0);
                ar[1] = make_float4(0, 0, 0, 0);
            }
        }
    };
    auto loadB = [&](int k0) {
        if (!transB) {
#pragma unroll
            for (int seg = 0; seg < 2; seg++) {
                int kpair = bn_kp + seg * 8;
                const float* p0 = Bb + (ll)(k0 + 2 * kpair) * ldb + gnBn;
                const float* p1 = p0 + ldb;
                if (gnBn + 3 < N) {
                    br[seg * 2 + 0] = *reinterpret_cast<const float4*>(p0);
                    br[seg * 2 + 1] = *reinterpret_cast<const float4*>(p1);
                } else {
                    float u[4], w[4];
#pragma unroll
                    for (int q = 0; q < 4; q++) {
                        u[q] = (gnBn + q < N) ? p0[q] : 0.f;
                        w[q] = (gnBn + q < N) ? p1[q] : 0.f;
                    }
                    br[seg * 2 + 0] = make_float4(u[0], u[1], u[2], u[3]);
                    br[seg * 2 + 1] = make_float4(w[0], w[1], w[2], w[3]);
                }
            }
        } else {
#pragma unroll
            for (int seg = 0; seg < 2; seg++) {
                int kk = bt_kk0 + seg * 16;
                if (gnBt < N) {
                    const float* p = Bb + (ll)gnBt * ldb + k0 + kk;
                    br[seg * 2 + 0] = *reinterpret_cast<const float4*>(p);
                    br[seg * 2 + 1] = *reinterpret_cast<const float4*>(p + 4);
                } else {
                    br[seg * 2 + 0] = make_float4(0, 0, 0, 0);
                    br[seg * 2 + 1] = make_float4(0, 0, 0, 0);
                }
            }
        }
    };
    auto storeA = [&]() {
        if (IBLK == 4) {
#pragma unroll
            for (int seg = 0; seg < 2; seg++) {
                int kp0 = (a_kk0 + seg * 16) >> 1;
                float4 v0 = ar[seg * 2 + 0], v1 = ar[seg * 2 + 1];
                uint32_t h, l;
                split_pack(v0.x, v0.y, h, l); AsH[kp0 + 0][a_m] = h; AsL[kp0 + 0][a_m] = l;
                split_pack(v0.z, v0.w, h, l); AsH[kp0 + 1][a_m] = h; AsL[kp0 + 1][a_m] = l;
                split_pack(v1.x, v1.y, h, l); AsH[kp0 + 2][a_m] = h; AsL[kp0 + 2][a_m] = l;
                split_pack(v1.z, v1.w, h, l); AsH[kp0 + 3][a_m] = h; AsL[kp0 + 3][a_m] = l;
            }
        } else {
            int kp0 = a_kk0 >> 1;
            float4 v0 = ar[0], v1 = ar[1];
            uint32_t h, l;
            split_pack(v0.x, v0.y, h, l); AsH[kp0 + 0][a_m] = h; AsL[kp0 + 0][a_m] = l;
            split_pack(v0.z, v0.w, h, l); AsH[kp0 + 1][a_m] = h; AsL[kp0 + 1][a_m] = l;
            split_pack(v1.x, v1.y, h, l); AsH[kp0 + 2][a_m] = h; AsL[kp0 + 2][a_m] = l;
            split_pack(v1.z, v1.w, h, l); AsH[kp0 + 3][a_m] = h; AsL[kp0 + 3][a_m] = l;
        }
    };
    auto storeB = [&]() {
        if (!transB) {
#pragma unroll
            for (int seg = 0; seg < 2; seg++) {
                int kpair = bn_kp + seg * 8;
                float4 u4 = br[seg * 2 + 0], w4 = br[seg * 2 + 1];
                float u[4] = {u4.x, u4.y, u4.z, u4.w};
                float w[4] = {w4.x, w4.y, w4.z, w4.w};
#pragma unroll
                for (int q = 0; q < 4; q++) {
                    uint32_t h, l;
                    split_pack(u[q], w[q], h, l);
                    BsH[kpair][bn_n4 + q] = h; BsL[kpair][bn_n4 + q] = l;
                }
            }
        } else {
#pragma unroll
            for (int seg = 0; seg < 2; seg++) {
                int kp0 = (bt_kk0 + seg * 16) >> 1;
                float4 v0 = br[seg * 2 + 0], v1 = br[seg * 2 + 1];
                uint32_t h, l;
                split_pack(v0.x, v0.y, h, l); BsH[kp0 + 0][bt_n] = h; BsL[kp0 + 0][bt_n] = l;
                split_pack(v0.z, v0.w, h, l); BsH[kp0 + 1][bt_n] = h; BsL[kp0 + 1][bt_n] = l;
                split_pack(v1.x, v1.y, h, l); BsH[kp0 + 2][bt_n] = h; BsL[kp0 + 2][bt_n] = l;
                split_pack(v1.z, v1.w, h, l); BsH[kp0 + 3][bt_n] = h; BsL[kp0 + 3][bt_n] = l;
            }
        }
    };

    const int nt = K / KT;
    loadA(0); loadB(0);
    storeA(); storeB();
    for (int t = 0; t < nt; t++) {
        __syncthreads();
        if (t + 1 < nt) { loadA((t + 1) * KT); loadB((t + 1) * KT); }
#pragma unroll
        for (int st = 0; st < 2; st++) {
            int base = st * 8;
            uint32_t aH[IBLK][4], aL[IBLK][4], bH[4][2], bL[4][2];
#pragma unroll
            for (int i = 0; i < IBLK; i++) {
                int m0 = warpRow * (IBLK * 16) + i * 16 + lq;
                aH[i][0] = AsH[base + lr][m0];     aH[i][1] = AsH[base + lr][m0 + 8];
                aH[i][2] = AsH[base + lr + 4][m0]; aH[i][3] = AsH[base + lr + 4][m0 + 8];
                aL[i][0] = AsL[base + lr][m0];     aL[i][1] = AsL[base + lr][m0 + 8];
                aL[i][2] = AsL[base + lr + 4][m0]; aL[i][3] = AsL[base + lr + 4][m0 + 8];
            }
#pragma unroll
            for (int j = 0; j < 4; j++) {
                int n0 = warpCol * 32 + j * 8 + lq;
                bH[j][0] = BsH[base + lr][n0]; bH[j][1] = BsH[base + lr + 4][n0];
                bL[j][0] = BsL[base + lr][n0]; bL[j][1] = BsL[base + lr + 4][n0];
            }
#pragma unroll
            for (int i = 0; i < IBLK; i++)
#pragma unroll
                for (int j = 0; j < 4; j++) MMA_BF16(acc[i][j], aH[i], bL[j]);
#pragma unroll
            for (int i = 0; i < IBLK; i++)
#pragma unroll
                for (int j = 0; j < 4; j++) MMA_BF16(acc[i][j], aL[i], bH[j]);
#pragma unroll
            for (int i = 0; i < IBLK; i++)
#pragma unroll
                for (int j = 0; j < 4; j++) MMA_BF16(acc[i][j], aH[i], bH[j]);
        }
        __syncthreads();
        if (t + 1 < nt) { storeA(); storeB(); }
    }

    // epilogue; splitOut: also write ao_pack (AV only: z=(b,h), alpha=1)
    const int zb = z / HB, zh = z % HB;
#pragma unroll
    for (int i = 0; i < IBLK; i++) {
#pragma unroll
        for (int r2 = 0; r2 < 2; r2++) {
            int gm = rowBase + warpRow * (IBLK * 16) + i * 16 + lq + r2 * 8;
            if (gm >= M) continue;
            float* crow = Cb + (ll)gm * ldc;
#pragma unroll
            for (int j = 0; j < 4; j++) {
                int gn = colBase + warpCol * 32 + j * 8 + lr * 2;
                float v0 = alpha * acc[i][j][r2 * 2 + 0];
                float v1 = alpha * acc[i][j][r2 * 2 + 1];
                if (gn < N)     { if (accumulate) crow[gn] += v0;     else crow[gn] = v0; }
                if (gn + 1 < N) { if (accumulate) crow[gn + 1] += v1; else crow[gn + 1] = v1; }
                if (splitOut && gn + 1 < N) {
                    uint32_t h, l;
                    split_pack(v0, v1, h, l);
                    ll o = (ll)((zh * HD_ + gn) >> 1) * MT + zb * T_ + gm;
                    g_aopH[o] = h; g_aopL[o] = l;
                }
            }
        }
    }
}

static void gemm_old(const float* A, const float* Bm, float* C, int M, int N, int K,
                     int lda, int ldb, int ldc, int batch, int HB,
                     ll sAo, ll sAi, ll sBo, ll sBi, ll sCo, ll sCi,
                     float alpha, int accum, int transB, int gateMode, int splitOut) {
    int nx = (N + 127) / 128;
    ll blocks128 = (ll)nx * ((M + 127) / 128) * batch;
    if (blocks128 < 296 && (M % 64) == 0) {
        dim3 grid(nx, M / 64, batch);
        gemm_bf16x2_k<2><<<grid, 256>>>(A, Bm, C, M, N, K, lda, ldb, ldc,
                                        HB, sAo, sAi, sBo, sBi, sCo, sCi,
                                        alpha, accum, transB, gateMode, splitOut);
    } else {
        dim3 grid(nx, (M + 127) / 128, batch);
        gemm_bf16x2_k<4><<<grid, 256>>>(A, Bm, C, M, N, K, lda, ldb, ldc,
                                        HB, sAo, sAi, sBo, sBi, sCo, sCi,
                                        alpha, accum, transB, gateMode, splitOut);
    }
}

// ---------------------------------------------------------------------------
extern "C" void kernel_launch(void* const* d_in, const int* in_sizes, int n_in,
                              void* d_out, int out_size) {
    const int*   ids        = (const int*)  d_in[0];
    const float* embed      = (const float*)d_in[1];
    const float* wq         = (const float*)d_in[2];
    const float* wk         = (const float*)d_in[3];
    const float* wv         = (const float*)d_in[4];
    const float* wo         = (const float*)d_in[5];
    const float* w1         = (const float*)d_in[6];
    const float* w2         = (const float*)d_in[7];
    const float* w3         = (const float*)d_in[8];
    const float* norm1      = (const float*)d_in[9];
    const float* norm2      = (const float*)d_in[10];
    const float* final_norm = (const float*)d_in[11];
    const float* lm_head    = (const float*)d_in[12];
    const float* exit_w     = (const float*)d_in[13];
    const float* exit_b     = (const float*)d_in[14];
    const float* skip_w     = (const float*)d_in[15];
    const float* skip_b     = (const float*)d_in[16];
    float* out = (float*)d_out;

    cudaFuncSetAttribute(gemm_ws_k<2, 3>, cudaFuncAttributeMaxDynamicSharedMemorySize, SMEM_WS2);
    cudaFuncSetAttribute(gemm_ws_k<4, 4>, cudaFuncAttributeMaxDynamicSharedMemorySize, SMEM_WS4);

    float *px, *pqkv, *psc, *pf13, *phl;
    cudaGetSymbolAddress((void**)&px,   g_x);
    cudaGetSymbolAddress((void**)&pqkv, g_qkv);
    cudaGetSymbolAddress((void**)&psc,  g_sc);
    cudaGetSymbolAddress((void**)&pf13, g_f13);
    cudaGetSymbolAddress((void**)&phl,  g_hlast);
    float* pq = pqkv;
    float* pk = pqkv + (ll)BTD;
    float* pv = pqkv + 2ll * BTD;
    float* pao;
    cudaGetSymbolAddress((void**)&pao, g_ao);

    init_k<<<1, 32>>>();
    prepack_k<<<(int)((TOTPAIRS + 255) / 256), 256>>>(wq, wk, wv, wo, w1, w2, w3, lm_head);
    rope_tables_k<<<(T_ * (HD_ / 2)) / 256, 256>>>();
    embed_k<<<(B_ * T_ * D_) / 256, 256>>>(ids, embed);

    for (int li = 0; li < L_; li++) {
        // 1) skip decision (uses x BEFORE the block)
        compute_skip_k<<<1, 128>>>(px, skip_w + (ll)li * D_, skip_b + li, li);

        // 2) transformer block (gated by do_skip)
        rmsnorm_k<<<B_ * T_, 256>>>(px, norm1 + (ll)li * D_, nullptr, D_, D_, 1, 1, 1);
        // fused QKV from packed h (wSel 0, 3 batches)
        gemm_fast(0, 0, li, pqkv, MT, D_, D_, D_, D_, 3, 0, (ll)BTD, 0, 1);
        rope_k<<<(2 * B_ * T_ * D_ / 2) / 256, 256>>>(pq);
        // scores = (Q @ K^T) / sqrt(HD)  (legacy path)
        gemm_old(pq, pk, psc, T_, T_, HD_, D_, D_, T_, B_ * H_, H_,
                 (ll)T_ * D_, HD_, (ll)T_ * D_, HD_, (ll)H_ * T_ * T_, (ll)T_ * T_,
                 0.125f, 0, 1, 1, 0);
        softmax_k<<<B_ * H_ * T_, 256>>>();
        // o = att @ V  (legacy path, epilogue also writes ao_pack)
        gemm_old(psc, pv, pao, T_, HD_, T_, T_, D_, D_, B_ * H_, H_,
                 (ll)H_ * T_ * T_, (ll)T_ * T_, (ll)T_ * D_, HD_, (ll)T_ * D_, HD_,
                 1.f, 0, 0, 1, 1);
        // x += ao @ wo   (fast, A=ao_pack)
        gemm_fast(1, 1, li, px, MT, D_, D_, D_, D_, 1, 0, 0, 1, 1);
        // FFN
        rmsnorm_k<<<B_ * T_, 256>>>(px, norm2 + (ll)li * D_, nullptr, D_, D_, 1, 1, 1);
        gemm_fast(0, 2, li, pf13, MT, F_, D_, F_, F_, 2, 0, (ll)BTF, 0, 1);
        silu_pack_k<<<dim3(F_ / 64, MT / 64), 256>>>();
        gemm_fast(2, 3, li, px, MT, D_, F_, D_, D_, 1, 0, 0, 1, 1);

        // 3) exit logic
        rmsnorm_k<<<B_, 256>>>(px + (ll)(T_ - 1) * D_, final_norm, phl,
                               (ll)T_ * D_, D_, 1, 1, 0);
        logits_last_k<<<dim3(V_ / 256, B_), 256>>>(lm_head);
        exit_decide_k<<<1, 256>>>(px, exit_w + (ll)li * D_, exit_b + li, li);

        // 4) full logits only for newly-exited batches
        rmsnorm_k<<<B_ * T_, 256>>>(px, final_norm, nullptr, D_, D_, 2, T_, 1);
        gemm_fast(0, 4, li, out, T_, V_, D_, V_, V_, B_, T_, (ll)T_ * V_, 0, 2);
    }

    // final logits for batches that never exited
    finalize_k<<<1, 32>>>();
    rmsnorm_k<<<B_ * T_, 256>>>(px, final_norm, nullptr, D_, D_, 2, T_, 1);
    gemm_fast(0, 4, 0, out, T_, V_, D_, V_, V_, B_, T_, (ll)T_ * V_, 0, 2);

    if (out_size >= B_ * T_ * V_ + B_)
        write_exl_k<<<1, 32>>>(out + (ll)B_ * T_ * V_);
}

// round 10
// speedup vs baseline: 3.9940x; 1.0036x over previous
#include <cuda_runtime.h>
#include <cuda_bf16.h>
#include <math.h>
#include <stdint.h>

#define B_ 4
#define T_ 256
#define D_ 1024
#define H_ 16
#define HD_ 64
#define F_ 4096
#define L_ 6
#define V_ 32000

typedef long long ll;

#define BTD (B_*T_*D_)
#define BTF (B_*T_*F_)
#define MT  (B_*T_)          // 1024 total rows of activations

// pair counts for packed (bf16x2) tensors
#define WQPAIRS (L_*(D_/2)*D_)
#define W1PAIRS (L_*(D_/2)*F_)
#define W2PAIRS (L_*(F_/2)*D_)
#define LMPAIRS ((D_/2)*V_)
#define TOTPAIRS (4ll*WQPAIRS + 2ll*W1PAIRS + (ll)W2PAIRS + (ll)LMPAIRS)

#define HPN  ((D_/2)*MT)
#define F1PN ((F_/2)*MT)

// ---------------- scratch (static device memory, no allocs) ----------------
__device__ float g_x  [BTD];
__device__ float g_qkv[3*BTD];
__device__ float g_ao [BTD];
__device__ float g_sc [B_*H_*T_*T_];
__device__ float g_f13[2*BTF];
__device__ float g_hlast[B_*D_];
__device__ float g_ll[B_*V_];
__device__ float g_cos[T_*(HD_/2)];
__device__ float g_sin[T_*(HD_/2)];

// packed activations  [kp][MT]
__device__ uint32_t g_hpH [HPN],  g_hpL [HPN];
__device__ uint32_t g_aopH[HPN],  g_aopL[HPN];
__device__ uint32_t g_f1pH[F1PN], g_f1pL[F1PN];
// packed weights  [L*K/2][N]
__device__ uint32_t g_wqH[WQPAIRS], g_wqL[WQPAIRS];
__device__ uint32_t g_wkH[WQPAIRS], g_wkL[WQPAIRS];
__device__ uint32_t g_wvH[WQPAIRS], g_wvL[WQPAIRS];
__device__ uint32_t g_woH[WQPAIRS], g_woL[WQPAIRS];
__device__ uint32_t g_w1H[W1PAIRS], g_w1L[W1PAIRS];
__device__ uint32_t g_w3H[W1PAIRS], g_w3L[W1PAIRS];
__device__ uint32_t g_w2H[W2PAIRS], g_w2L[W2PAIRS];
__device__ uint32_t g_lmH[LMPAIRS], g_lmL[LMPAIRS];

// ---------------- control flags ----------------
__device__ int d_do_skip;
__device__ int d_exited[B_];
__device__ int d_newly[B_];
__device__ int d_exl[B_];

// ---------------------------------------------------------------------------
__device__ __forceinline__ void split_pack(float x0, float x1,
                                           uint32_t& hi, uint32_t& lo) {
    __nv_bfloat16 h0 = __float2bfloat16(x0);
    __nv_bfloat16 h1 = __float2bfloat16(x1);
    __nv_bfloat16 l0 = __float2bfloat16(x0 - __bfloat162float(h0));
    __nv_bfloat16 l1 = __float2bfloat16(x1 - __bfloat162float(h1));
    hi = ((uint32_t)__bfloat16_as_ushort(h1) << 16) | __bfloat16_as_ushort(h0);
    lo = ((uint32_t)__bfloat16_as_ushort(l1) << 16) | __bfloat16_as_ushort(l0);
}

__global__ void init_k() {
    int t = threadIdx.x;
    if (t < B_) { d_exited[t] = 0; d_newly[t] = 0; d_exl[t] = -1; }
    if (t == 0) d_do_skip = 0;
}

__global__ void finalize_k() {
    int t = threadIdx.x;
    if (t < B_) {
        int nv = d_exited[t] ? 0 : 1;
        d_newly[t] = nv;
        if (nv) d_exl[t] = L_ - 1;
    }
    if (t == 0) d_do_skip = 0;
}

__global__ void write_exl_k(float* out) {
    int t = threadIdx.x;
    if (t < B_) out[t] = (float)d_exl[t];
}

__global__ void rope_tables_k() {
    int idx = blockIdx.x * 256 + threadIdx.x;
    int t = idx >> 5;
    int i = idx & 31;
    float inv = expf(-logf(10000.f) * (2.f * (float)i) / (float)HD_);
    float f = (float)t * inv;
    g_cos[idx] = cosf(f);
    g_sin[idx] = sinf(f);
}

__global__ void embed_k(const int* __restrict__ ids, const float* __restrict__ emb) {
    ll idx = (ll)blockIdx.x * 256 + threadIdx.x;
    int tok = ids[idx >> 10];
    g_x[idx] = emb[(ll)tok * D_ + (idx & 1023)];
}

// ---- weight prepack: fp32 [K][N] -> hi/lo packed uint32 [K/2][N] ----------
__global__ void prepack_k(const float* __restrict__ wq, const float* __restrict__ wk,
                          const float* __restrict__ wv, const float* __restrict__ wo,
                          const float* __restrict__ w1, const float* __restrict__ w2,
                          const float* __restrict__ w3, const float* __restrict__ lm) {
    ll gid = (ll)blockIdx.x * 256 + threadIdx.x;
    if (gid >= TOTPAIRS) return;
    const float* src; uint32_t *dH, *dL; ll idx; int cols;
    ll c4 = 4ll * WQPAIRS;
    if (gid < (ll)WQPAIRS)        { src = wq; dH = g_wqH; dL = g_wqL; idx = gid; cols = D_; }
    else if (gid < 2ll*WQPAIRS)   { src = wk; dH = g_wkH; dL = g_wkL; idx = gid - WQPAIRS; cols = D_; }
    else if (gid < 3ll*WQPAIRS)   { src = wv; dH = g_wvH; dL = g_wvL; idx = gid - 2ll*WQPAIRS; cols = D_; }
    else if (gid < c4)            { src = wo; dH = g_woH; dL = g_woL; idx = gid - 3ll*WQPAIRS; cols = D_; }
    else if (gid < c4 + W1PAIRS)  { src = w1; dH = g_w1H; dL = g_w1L; idx = gid - c4; cols = F_; }
    else if (gid < c4 + 2ll*W1PAIRS) { src = w3; dH = g_w3H; dL = g_w3L; idx = gid - c4 - W1PAIRS; cols = F_; }
    else if (gid < c4 + 2ll*W1PAIRS + W2PAIRS)
                                  { src = w2; dH = g_w2H; dL = g_w2L; idx = gid - c4 - 2ll*W1PAIRS; cols = D_; }
    else                          { src = lm; dH = g_lmH; dL = g_lmL; idx = gid - c4 - 2ll*W1PAIRS - W2PAIRS; cols = V_; }
    ll kp = idx / cols;
    int col = (int)(idx - kp * cols);
    float a = src[(2*kp)     * (ll)cols + col];
    float b = src[(2*kp + 1) * (ll)cols + col];
    uint32_t h, l;
    split_pack(a, b, h, l);
    dH[idx] = h; dL[idx] = l;
}

// in-place RoPE on q and k together; layout (2B,T,H,HD)
__global__ void rope_k(float* __restrict__ q) {
    if (d_do_skip) return;
    int idx = blockIdx.x * 256 + threadIdx.x;
    int i = idx & 31;
    int t = (idx >> 9) & 255;
    ll base = (ll)(idx >> 5) * HD_ + i;
    float c = g_cos[t * 32 + i], s = g_sin[t * 32 + i];
    float x1 = q[base], x2 = q[base + 32];
    q[base]      = x1 * c - x2 * s;
    q[base + 32] = x1 * s + x2 * c;
}

// causal softmax over rows of scores (B,H,T,T)
__global__ void softmax_k() {
    if (d_do_skip) return;
    int r = blockIdx.x;
    int qrow = r & (T_ - 1);
    float* row = g_sc + (ll)r * T_;
    int tid = threadIdx.x;
    float v = (tid <= qrow) ? row[tid] : -3.4e38f;
    __shared__ float red[256];
    red[tid] = v; __syncthreads();
    for (int o = 128; o > 0; o >>= 1) { if (tid < o) red[tid] = fmaxf(red[tid], red[tid + o]); __syncthreads(); }
    float m = red[0]; __syncthreads();
    float e = (tid <= qrow) ? expf(v - m) : 0.f;
    red[tid] = e; __syncthreads();
    for (int o = 128; o > 0; o >>= 1) { if (tid < o) red[tid] += red[tid + o]; __syncthreads(); }
    row[tid] = e / red[0];
}

// silu(f1)*f3 -> packed f1 [F/2][MT] via smem transpose
__global__ void silu_pack_k() {
    if (d_do_skip) return;
    __shared__ float t1[64][65];
    __shared__ float t3[64][65];
    int f0 = blockIdx.x * 64;
    int m0 = blockIdx.y * 64;
    int tid = threadIdx.x;
#pragma unroll
    for (int it = 0; it < 16; it++) {
        int id = it * 256 + tid;
        int mm = id >> 6, ff = id & 63;
        t1[mm][ff] = g_f13[(ll)(m0 + mm) * F_ + f0 + ff];
        t3[mm][ff] = g_f13[(ll)(m0 + mm) * F_ + f0 + ff + (ll)BTF];
    }
    __syncthreads();
#pragma unroll
    for (int it = 0; it < 8; it++) {
        int id = it * 256 + tid;
        int fp = id >> 6, m = id & 63;
        float a0 = t1[m][2*fp],   b0 = t3[m][2*fp];
        float a1 = t1[m][2*fp+1], b1 = t3[m][2*fp+1];
        float v0 = (a0 / (1.f + expf(-a0))) * b0;
        float v1 = (a1 / (1.f + expf(-a1))) * b1;
        uint32_t h, l;
        split_pack(v0, v1, h, l);
        ll o = (ll)(f0/2 + fp) * MT + m0 + m;
        g_f1pH[o] = h; g_f1pL[o] = l;
    }
}

// rmsnorm: one block per row, D_=1024, 256 threads x float4
__global__ void rmsnorm_k(const float* __restrict__ in, const float* __restrict__ w,
                          float* outF, ll inStride, ll outStride,
                          int gateMode, int rowsPerBatch, int packOut) {
    if (gateMode == 1 && d_do_skip) return;
    int row = blockIdx.x;
    if (gateMode == 2 && !d_newly[row / rowsPerBatch]) return;
    const float* xr = in + (ll)row * inStride;
    int tid = threadIdx.x;
    float4 v = reinterpret_cast<const float4*>(xr)[tid];
    float s = v.x * v.x + v.y * v.y + v.z * v.z + v.w * v.w;
    __shared__ float red[256];
    red[tid] = s; __syncthreads();
    for (int o = 128; o > 0; o >>= 1) { if (tid < o) red[tid] += red[tid + o]; __syncthreads(); }
    float scale = rsqrtf(red[0] * (1.f / (float)D_) + 1e-6f);
    float4 wv = reinterpret_cast<const float4*>(w)[tid];
    float4 ov;
    ov.x = v.x * wv.x * scale; ov.y = v.y * wv.y * scale;
    ov.z = v.z * wv.z * scale; ov.w = v.w * wv.w * scale;
    if (outF) reinterpret_cast<float4*>(outF + (ll)row * outStride)[tid] = ov;
    if (packOut) {
        uint32_t h, l;
        split_pack(ov.x, ov.y, h, l);
        g_hpH[(ll)(2*tid)   * MT + row] = h; g_hpL[(ll)(2*tid)   * MT + row] = l;
        split_pack(ov.z, ov.w, h, l);
        g_hpH[(ll)(2*tid+1) * MT + row] = h; g_hpL[(ll)(2*tid+1) * MT + row] = l;
    }
}

// last-position logits
__global__ void logits_last_k(const float* __restrict__ lm_head) {
    if (d_do_skip) return;
    int b = blockIdx.y;
    int v = blockIdx.x * 256 + threadIdx.x;
    __shared__ float hs[D_];
    for (int i = threadIdx.x; i < D_; i += 256) hs[i] = g_hlast[b * D_ + i];
    __syncthreads();
    float acc = 0.f;
    const float* col = lm_head + v;
#pragma unroll 4
    for (int d = 0; d < D_; d++) acc = fmaf(hs[d], col[(ll)d * V_], acc);
    g_ll[(ll)b * V_ + v] = acc;
}

// warp-per-batch skip decision
__global__ void compute_skip_k(const float* __restrict__ x,
                               const float* __restrict__ sw,
                               const float* __restrict__ sb, int li) {
    int tid = threadIdx.x;
    int w = tid >> 5, l = tid & 31;
    __shared__ float sp[B_];
    if (w < B_) {
        const float* xr = x + ((ll)w * T_ + (T_ - 1)) * D_;
        float s = 0.f;
#pragma unroll 8
        for (int i = l; i < D_; i += 32) s += xr[i] * sw[i];
#pragma unroll
        for (int o = 16; o > 0; o >>= 1) s += __shfl_down_sync(0xffffffff, s, o);
        if (l == 0) sp[w] = 1.f / (1.f + expf(-(s + sb[0])));
    }
    __syncthreads();
    if (tid == 0) {
        float cnt = 0.f, s = 0.f;
        for (int b = 0; b < B_; b++) {
            float a = d_exited[b] ? 0.f : 1.f;
            cnt += a; s += sp[b] * a;
        }
        float mean = s / fmaxf(cnt, 1.f);
        d_do_skip = (li >= 1 && cnt > 0.f && mean < 0.1f) ? 1 : 0;
    }
}

// parallel exit decision: 4 batches x 64 threads
__global__ void exit_decide_k(const float* __restrict__ x,
                              const float* __restrict__ ew,
                              const float* __restrict__ eb, int li) {
    int tid = threadIdx.x;
    if (d_do_skip) { if (tid < B_) d_newly[tid] = 0; return; }
    __shared__ float red[256];
    __shared__ float mxs[B_], sums[B_], eps_[B_];
    int b = tid >> 6, l = tid & 63;
    const float* lr = g_ll + (ll)b * V_;
    float m = -3.4e38f;
    for (int i = l; i < V_; i += 64) m = fmaxf(m, lr[i]);
    red[tid] = m; __syncthreads();
    for (int o = 32; o > 0; o >>= 1) { if (l < o) red[tid] = fmaxf(red[tid], red[tid + o]); __syncthreads(); }
    if (l == 0) mxs[b] = red[tid];
    __syncthreads();
    float mx = mxs[b];
    float s = 0.f;
    for (int i = l; i < V_; i += 64) s += expf(lr[i] - mx);
    red[tid] = s; __syncthreads();
    for (int o = 32; o > 0; o >>= 1) { if (l < o) red[tid] += red[tid + o]; __syncthreads(); }
    if (l == 0) sums[b] = red[tid];
    __syncthreads();
    const float* xr = x + ((ll)b * T_ + (T_ - 1)) * D_;
    float e = 0.f;
    for (int i = l; i < D_; i += 64) e += xr[i] * ew[i];
    red[tid] = e; __syncthreads();
    for (int o = 32; o > 0; o >>= 1) { if (l < o) red[tid] += red[tid + o]; __syncthreads(); }
    if (l == 0) eps_[b] = 1.f / (1.f + expf(-(red[tid] + eb[0])));
    __syncthreads();
    if (tid < B_) {
        int bb = tid;
        float conf = 1.f / sums[bb];
        int should = (conf > 0.9f) || (eps_[bb] > 0.9f);
        int nw = (should && !d_exited[bb]) ? 1 : 0;
        d_newly[bb] = nw;
        if (nw) { d_exited[bb] = 1; d_exl[bb] = li; }
    }
}

#define MMA_BF16(acc, a, b)                                                   \
    asm volatile(                                                             \
        "mma.sync.aligned.m16n8k16.row.col.f32.bf16.bf16.f32 "                \
        "{%0,%1,%2,%3}, {%4,%5,%6,%7}, {%8,%9}, {%0,%1,%2,%3};"               \
        : "+f"(acc[0]), "+f"(acc[1]), "+f"(acc[2]), "+f"(acc[3])              \
        : "r"(a[0]), "r"(a[1]), "r"(a[2]), "r"(a[3]), "r"(b[0]), "r"(b[1]))

// =====================  fast cp.async GEMM on packed operands ==============
// A: packed [K/2][MT] hi/lo (aSel 0=h,1=ao,2=f1). B: packed weights (wSel).
// C fp32 [M][ldc]. BM = IBLK*32, BN=128, KT=32, STG-stage cp.async pipeline.
// IBLK=4: 1 CTA/SM. IBLK=2/1: 2 CTA/SM.
template <int IBLK, int STG>
__global__ __launch_bounds__(256, (IBLK == 4) ? 1 : 2) void gemm_ws_k(
    int aSel, int wSel, int li, float* __restrict__ C,
    int M, int N, int K, int ldbU, int ldc,
    int aColStride, ll sCo, int accumulate, int gateMode) {
    if (gateMode == 1 && d_do_skip) return;
    if (gateMode == 2 && !d_newly[blockIdx.z]) return;
    constexpr int BM = IBLK * 32;
    constexpr int SPA = BM + 8;
    constexpr int SPB = 136;
    constexpr int KP = 16;
    constexpr int AS = KP * SPA, BS = KP * SPB;
    constexpr int STAGE = 2 * AS + 2 * BS;
    constexpr int ACHROW = BM / 4;
    constexpr int ACH = KP * ACHROW;
    constexpr int BCH = KP * 32;
    constexpr int TCH = 2 * ACH + 2 * BCH;

    extern __shared__ uint32_t sm[];
    const int z = blockIdx.z;

    const uint32_t* aHp = (aSel == 0) ? g_hpH : ((aSel == 1) ? g_aopH : g_f1pH);
    const uint32_t* aLp = (aSel == 0) ? g_hpL : ((aSel == 1) ? g_aopL : g_f1pL);
    const uint32_t *bHp, *bLp;
    {
        ll off;
        switch (wSel) {
        case 0:
            off = (ll)li * (D_/2) * D_;
            bHp = ((z == 0) ? g_wqH : ((z == 1) ? g_wkH : g_wvH)) + off;
            bLp = ((z == 0) ? g_wqL : ((z == 1) ? g_wkL : g_wvL)) + off;
            break;
        case 1:
            off = (ll)li * (D_/2) * D_;
            bHp = g_woH + off; bLp = g_woL + off; break;
        case 2:
            off = (ll)li * (D_/2) * F_;
            bHp = ((z == 0) ? g_w1H : g_w3H) + off;
            bLp = ((z == 0) ? g_w1L : g_w3L) + off; break;
        case 3:
            off = (ll)li * (F_/2) * D_;
            bHp = g_w2H + off; bLp = g_w2L + off; break;
        default:
            bHp = g_lmH; bLp = g_lmL; break;
        }
    }
    const int aOff = z * aColStride;
    float* Cb = C + (ll)z * sCo;

    const int tid = threadIdx.x;
    const int lane = tid & 31;
    const int warp = tid >> 5;
    const int warpRow = warp >> 2;
    const int warpCol = warp & 3;
    const int rowBase = blockIdx.y * BM;
    const int colBase = blockIdx.x * 128;
    const int lq = lane >> 2;
    const int lr = lane & 3;

    auto loadTile = [&](int t, int s) {
        uint32_t* st = sm + s * STAGE;
        int kp0 = t * KP;
#pragma unroll
        for (int c = tid; c < TCH; c += 256) {
            uint32_t* dst; const uint32_t* src;
            if (c < 2 * ACH) {
                int cc = c; const uint32_t* g = aHp; uint32_t* ss = st;
                if (cc >= ACH) { cc -= ACH; g = aLp; ss = st + AS; }
                int row = cc / ACHROW, col = (cc % ACHROW) * 4;
                dst = ss + row * SPA + col;
                src = g + (ll)(kp0 + row) * MT + aOff + rowBase + col;
            } else {
                int cc = c - 2 * ACH; const uint32_t* g = bHp; uint32_t* ss = st + 2 * AS;
                if (cc >= BCH) { cc -= BCH; g = bLp; ss += BS; }
                int row = cc >> 5, col = (cc & 31) * 4;
                dst = ss + row * SPB + col;
                src = g + (ll)(kp0 + row) * ldbU + colBase + col;
            }
            uint32_t da = (uint32_t)__cvta_generic_to_shared(dst);
            asm volatile("cp.async.cg.shared.global [%0], [%1], 16;\n"
                         :: "r"(da), "l"(src));
        }
        asm volatile("cp.async.commit_group;\n");
    };

    float acc[IBLK][4][4];
#pragma unroll
    for (int i = 0; i < IBLK; i++)
#pragma unroll
        for (int j = 0; j < 4; j++)
#pragma unroll
            for (int r = 0; r < 4; r++) acc[i][j][r] = 0.f;

    const int nt = K / 32;
#pragma unroll
    for (int s = 0; s < STG - 1; s++) loadTile(s, s);

    for (int t = 0; t < nt; t++) {
        asm volatile("cp.async.wait_group %0;\n" :: "n"(STG - 2));
        __syncthreads();
        int tn = t + STG - 1;
        if (tn < nt) loadTile(tn, tn % STG);
        else asm volatile("cp.async.commit_group;\n");

        const uint32_t* AsH = sm + (t % STG) * STAGE;
        const uint32_t* AsL = AsH + AS;
        const uint32_t* BsH = AsH + 2 * AS;
        const uint32_t* BsL = BsH + BS;
#pragma unroll
        for (int st2 = 0; st2 < 2; st2++) {
            int base = st2 * 8;
            uint32_t aH[IBLK][4], aL[IBLK][4], bH[4][2], bL[4][2];
#pragma unroll
            for (int i = 0; i < IBLK; i++) {
                int m0 = warpRow * (IBLK * 16) + i * 16 + lq;
                aH[i][0] = AsH[(base + lr) * SPA + m0];
                aH[i][1] = AsH[(base + lr) * SPA + m0 + 8];
                aH[i][2] = AsH[(base + lr + 4) * SPA + m0];
                aH[i][3] = AsH[(base + lr + 4) * SPA + m0 + 8];
                aL[i][0] = AsL[(base + lr) * SPA + m0];
                aL[i][1] = AsL[(base + lr) * SPA + m0 + 8];
                aL[i][2] = AsL[(base + lr + 4) * SPA + m0];
                aL[i][3] = AsL[(base + lr + 4) * SPA + m0 + 8];
            }
#pragma unroll
            for (int j = 0; j < 4; j++) {
                int n0 = warpCol * 32 + j * 8 + lq;
                bH[j][0] = BsH[(base + lr) * SPB + n0];
                bH[j][1] = BsH[(base + lr + 4) * SPB + n0];
                bL[j][0] = BsL[(base + lr) * SPB + n0];
                bL[j][1] = BsL[(base + lr + 4) * SPB + n0];
            }
#pragma unroll
            for (int i = 0; i < IBLK; i++)
#pragma unroll
                for (int j = 0; j < 4; j++) MMA_BF16(acc[i][j], aH[i], bL[j]);
#pragma unroll
            for (int i = 0; i < IBLK; i++)
#pragma unroll
                for (int j = 0; j < 4; j++) MMA_BF16(acc[i][j], aL[i], bH[j]);
#pragma unroll
            for (int i = 0; i < IBLK; i++)
#pragma unroll
                for (int j = 0; j < 4; j++) MMA_BF16(acc[i][j], aH[i], bH[j]);
        }
    }

#pragma unroll
    for (int i = 0; i < IBLK; i++) {
#pragma unroll
        for (int r2 = 0; r2 < 2; r2++) {
            int gm = rowBase + warpRow * (IBLK * 16) + i * 16 + lq + r2 * 8;
            if (gm >= M) continue;
            float* crow = Cb + (ll)gm * ldc;
#pragma unroll
            for (int j = 0; j < 4; j++) {
                int gn = colBase + warpCol * 32 + j * 8 + lr * 2;
                float v0 = acc[i][j][r2 * 2 + 0];
                float v1 = acc[i][j][r2 * 2 + 1];
                if (gn < N)     { if (accumulate) crow[gn] += v0;     else crow[gn] = v0; }
                if (gn + 1 < N) { if (accumulate) crow[gn + 1] += v1; else crow[gn + 1] = v1; }
            }
        }
    }
}

// stage sizes (bytes): STAGE words = 2*16*(BM+8) + 2*16*136
#define SMEM_WS1 (4 * (2*16*(32+8)  + 2*16*136) * 4)   //  90,112
#define SMEM_WS2 (4 * (2*16*(64+8)  + 2*16*136) * 4)   // 106,496
#define SMEM_WS4 (4 * (2*16*(128+8) + 2*16*136) * 4)   // 139,264

static void gemm_fast(int aSel, int wSel, int li, float* C,
                      int M, int N, int K, int ldbU, int ldc,
                      int batch, int aColStride, ll sCo, int acc, int gate) {
    int nx = N / 128;
    int b128 = nx * (M / 128) * batch;
    if (b128 >= 296) {
        dim3 g(nx, M / 128, batch);
        gemm_ws_k<4, 4><<<g, 256, SMEM_WS4>>>(aSel, wSel, li, C, M, N, K, ldbU, ldc,
                                              aColStride, sCo, acc, gate);
    } else if (b128 * 2 >= 240) {
        dim3 g(nx, M / 64, batch);
        gemm_ws_k<2, 4><<<g, 256, SMEM_WS2>>>(aSel, wSel, li, C, M, N, K, ldbU, ldc,
                                              aColStride, sCo, acc, gate);
    } else {
        dim3 g(nx, M / 32, batch);
        gemm_ws_k<1, 4><<<g, 256, SMEM_WS1>>>(aSel, wSel, li, C, M, N, K, ldbU, ldc,
                                              aColStride, sCo, acc, gate);
    }
}

// ============= legacy register-staged GEMM (QK^T and AV paths) =============
#define KT 32

template <int IBLK>
__global__ __launch_bounds__(256, (IBLK == 2) ? 2 : 1) void gemm_bf16x2_k(
    const float* __restrict__ A, const float* __restrict__ Bm, float* __restrict__ C,
    int M, int N, int K, int lda, int ldb, int ldc,
    int HB, ll sAo, ll sAi, ll sBo, ll sBi, ll sCo, ll sCi,
    float alpha, int accumulate, int transB, int gateMode, int splitOut) {
    if (gateMode == 1 && d_do_skip) return;
    constexpr int BM = IBLK * 32;
    constexpr int SPA = BM + 8;
    constexpr int SPB = 136;

    int z = blockIdx.z;
    const float* Ab = A  + (ll)(z / HB) * sAo + (ll)(z % HB) * sAi;
    const float* Bb = Bm + (ll)(z / HB) * sBo + (ll)(z % HB) * sBi;
    float*       Cb = C  + (ll)(z / HB) * sCo + (ll)(z % HB) * sCi;

    __shared__ uint32_t AsH[KT/2][SPA], AsL[KT/2][SPA];
    __shared__ uint32_t BsH[KT/2][SPB], BsL[KT/2][SPB];

    const int tid = threadIdx.x;
    const int lane = tid & 31;
    const int warp = tid >> 5;
    const int warpRow = warp >> 2;
    const int warpCol = warp & 3;
    const int rowBase = blockIdx.y * BM;
    const int colBase = blockIdx.x * 128;

    float acc[IBLK][4][4];
#pragma unroll
    for (int i = 0; i < IBLK; i++)
#pragma unroll
        for (int j = 0; j < 4; j++)
#pragma unroll
            for (int r = 0; r < 4; r++) acc[i][j][r] = 0.f;

    const int lq = lane >> 2;
    const int lr = lane & 3;

    float4 ar[IBLK];
    float4 br[4];

    const int a_m   = (IBLK == 4) ? (tid >> 1) : (tid >> 2);
    const int a_kk0 = (IBLK == 4) ? ((tid & 1) * 8) : ((tid & 3) * 8);
    const int bn_kp = tid >> 5;
    const int bn_n4 = (tid & 31) * 4;
    const int bt_n  = tid >> 1;
    const int bt_kk0= (tid & 1) * 8;

    const int gmA = rowBase + a_m;
    const bool aOk = (gmA < M);
    const int gnBn = colBase + bn_n4;
    const int gnBt = colBase + bt_n;

    auto loadA = [&](int k0) {
        if (IBLK == 4) {
#pragma unroll
            for (int seg = 0; seg < 2; seg++) {
                int kk = a_kk0 + seg * 16;
                if (aOk) {
                    const float* p = Ab + (ll)gmA * lda + k0 + kk;
                    ar[seg * 2 + 0] = *reinterpret_cast<const float4*>(p);
                    ar[seg * 2 + 1] = *reinterpret_cast<const float4*>(p + 4);
                } else {
                    ar[seg * 2 + 0] = make_float4(0, 0, 0, 0);
                    ar[seg * 2 + 1] = make_float4(0, 0, 0, 0);
                }
            }
        } else {
            if (aOk) {
                const float* p = Ab + (ll)gmA * lda + k0 + a_kk0;
                ar[0] = *reinterpret_cast<const float4*>(p);
                ar[1] = *reinterpret_cast<const float4*>(p + 4);
            } else {
                ar[0] = make_float4(0, 0, 0, 0);
                ar[1] = make_float4(0, 0, 0, 0);
            }
        }
    };
    auto loadB = [&](int k0) {
        if (!transB) {
#pragma unroll
            for (int seg = 0; seg < 2; seg++) {
                int kpair = bn_kp + seg * 8;
                const float* p0 = Bb + (ll)(k0 + 2 * kpair) * ldb + gnBn;
                const float* p1 = p0 + ldb;
                if (gnBn + 3 < N) {
                    br[seg * 2 + 0] = *reinterpret_cast<const float4*>(p0);
                    br[seg * 2 + 1] = *reinterpret_cast<const float4*>(p1);
                } else {
                    float u[4], w[4];
#pragma unroll
                    for (int q = 0; q < 4; q++) {
                        u[q] = (gnBn + q < N) ? p0[q] : 0.f;
                        w[q] = (gnBn + q < N) ? p1[q] : 0.f;
                    }
                    br[seg * 2 + 0] = make_float4(u[0], u[1], u[2], u[3]);
                    br[seg * 2 + 1] = make_float4(w[0], w[1], w[2], w[3]);
                }
            }
        } else {
#pragma unroll
            for (int seg = 0; seg < 2; seg++) {
                int kk = bt_kk0 + seg * 16;
                if (gnBt < N) {
                    const float* p = Bb + (ll)gnBt * ldb + k0 + kk;
                    br[seg * 2 + 0] = *reinterpret_cast<const float4*>(p);
                    br[seg * 2 + 1] = *reinterpret_cast<const float4*>(p + 4);
                } else {
                    br[seg * 2 + 0] = make_float4(0, 0, 0, 0);
                    br[seg * 2 + 1] = make_float4(0, 0, 0, 0);
                }
            }
        }
    };
    auto storeA = [&]() {
        if (IBLK == 4) {
#pragma unroll
            for (int seg = 0; seg < 2; seg++) {
                int kp0 = (a_kk0 + seg * 16) >> 1;
                float4 v0 = ar[seg * 2 + 0], v1 = ar[seg * 2 + 1];
                uint32_t h, l;
                split_pack(v0.x, v0.y, h, l); AsH[kp0 + 0][a_m] = h; AsL[kp0 + 0][a_m] = l;
                split_pack(v0.z, v0.w, h, l); AsH[kp0 + 1][a_m] = h; AsL[kp0 + 1][a_m] = l;
                split_pack(v1.x, v1.y, h, l); AsH[kp0 + 2][a_m] = h; AsL[kp0 + 2][a_m] = l;
                split_pack(v1.z, v1.w, h, l); AsH[kp0 + 3][a_m] = h; AsL[kp0 + 3][a_m] = l;
            }
        } else {
            int kp0 = a_kk0 >> 1;
            float4 v0 = ar[0], v1 = ar[1];
            uint32_t h, l;
            split_pack(v0.x, v0.y, h, l); AsH[kp0 + 0][a_m] = h; AsL[kp0 + 0][a_m] = l;
            split_pack(v0.z, v0.w, h, l); AsH[kp0 + 1][a_m] = h; AsL[kp0 + 1][a_m] = l;
            split_pack(v1.x, v1.y, h, l); AsH[kp0 + 2][a_m] = h; AsL[kp0 + 2][a_m] = l;
            split_pack(v1.z, v1.w, h, l); AsH[kp0 + 3][a_m] = h; AsL[kp0 + 3][a_m] = l;
        }
    };
    auto storeB = [&]() {
        if (!transB) {
#pragma unroll
            for (int seg = 0; seg < 2; seg++) {
                int kpair = bn_kp + seg * 8;
                float4 u4 = br[seg * 2 + 0], w4 = br[seg * 2 + 1];
                float u[4] = {u4.x, u4.y, u4.z, u4.w};
                float w[4] = {w4.x, w4.y, w4.z, w4.w};
#pragma unroll
                for (int q = 0; q < 4; q++) {
                    uint32_t h, l;
                    split_pack(u[q], w[q], h, l);
                    BsH[kpair][bn_n4 + q] = h; BsL[kpair][bn_n4 + q] = l;
                }
            }
        } else {
#pragma unroll
            for (int seg = 0; seg < 2; seg++) {
                int kp0 = (bt_kk0 + seg * 16) >> 1;
                float4 v0 = br[seg * 2 + 0], v1 = br[seg * 2 + 1];
                uint32_t h, l;
                split_pack(v0.x, v0.y, h, l); BsH[kp0 + 0][bt_n] = h; BsL[kp0 + 0][bt_n] = l;
                split_pack(v0.z, v0.w, h, l); BsH[kp0 + 1][bt_n] = h; BsL[kp0 + 1][bt_n] = l;
                split_pack(v1.x, v1.y, h, l); BsH[kp0 + 2][bt_n] = h; BsL[kp0 + 2][bt_n] = l;
                split_pack(v1.z, v1.w, h, l); BsH[kp0 + 3][bt_n] = h; BsL[kp0 + 3][bt_n] = l;
            }
        }
    };

    const int nt = K / KT;
    loadA(0); loadB(0);
    storeA(); storeB();
    for (int t = 0; t < nt; t++) {
        __syncthreads();
        if (t + 1 < nt) { loadA((t + 1) * KT); loadB((t + 1) * KT); }
#pragma unroll
        for (int st = 0; st < 2; st++) {
            int base = st * 8;
            uint32_t aH[IBLK][4], aL[IBLK][4], bH[4][2], bL[4][2];
#pragma unroll
            for (int i = 0; i < IBLK; i++) {
                int m0 = warpRow * (IBLK * 16) + i * 16 + lq;
                aH[i][0] = AsH[base + lr][m0];     aH[i][1] = AsH[base + lr][m0 + 8];
                aH[i][2] = AsH[base + lr + 4][m0]; aH[i][3] = AsH[base + lr + 4][m0 + 8];
                aL[i][0] = AsL[base + lr][m0];     aL[i][1] = AsL[base + lr][m0 + 8];
                aL[i][2] = AsL[base + lr + 4][m0]; aL[i][3] = AsL[base + lr + 4][m0 + 8];
            }
#pragma unroll
            for (int j = 0; j < 4; j++) {
                int n0 = warpCol * 32 + j * 8 + lq;
                bH[j][0] = BsH[base + lr][n0]; bH[j][1] = BsH[base + lr + 4][n0];
                bL[j][0] = BsL[base + lr][n0]; bL[j][1] = BsL[base + lr + 4][n0];
            }
#pragma unroll
            for (int i = 0; i < IBLK; i++)
#pragma unroll
                for (int j = 0; j < 4; j++) MMA_BF16(acc[i][j], aH[i], bL[j]);
#pragma unroll
            for (int i = 0; i < IBLK; i++)
#pragma unroll
                for (int j = 0; j < 4; j++) MMA_BF16(acc[i][j], aL[i], bH[j]);
#pragma unroll
            for (int i = 0; i < IBLK; i++)
#pragma unroll
                for (int j = 0; j < 4; j++) MMA_BF16(acc[i][j], aH[i], bH[j]);
        }
        __syncthreads();
        if (t + 1 < nt) { storeA(); storeB(); }
    }

    // epilogue; splitOut: also write ao_pack (AV only: z=(b,h), alpha=1)
    const int zb = z / HB, zh = z % HB;
#pragma unroll
    for (int i = 0; i < IBLK; i++) {
#pragma unroll
        for (int r2 = 0; r2 < 2; r2++) {
            int gm = rowBase + warpRow * (IBLK * 16) + i * 16 + lq + r2 * 8;
            if (gm >= M) continue;
            float* crow = Cb + (ll)gm * ldc;
#pragma unroll
            for (int j = 0; j < 4; j++) {
                int gn = colBase + warpCol * 32 + j * 8 + lr * 2;
                float v0 = alpha * acc[i][j][r2 * 2 + 0];
                float v1 = alpha * acc[i][j][r2 * 2 + 1];
                if (gn < N)     { if (accumulate) crow[gn] += v0;     else crow[gn] = v0; }
                if (gn + 1 < N) { if (accumulate) crow[gn + 1] += v1; else crow[gn + 1] = v1; }
                if (splitOut && gn + 1 < N) {
                    uint32_t h, l;
                    split_pack(v0, v1, h, l);
                    ll o = (ll)((zh * HD_ + gn) >> 1) * MT + zb * T_ + gm;
                    g_aopH[o] = h; g_aopL[o] = l;
                }
            }
        }
    }
}

static void gemm_old(const float* A, const float* Bm, float* C, int M, int N, int K,
                     int lda, int ldb, int ldc, int batch, int HB,
                     ll sAo, ll sAi, ll sBo, ll sBi, ll sCo, ll sCi,
                     float alpha, int accum, int transB, int gateMode, int splitOut) {
    int nx = (N + 127) / 128;
    ll blocks128 = (ll)nx * ((M + 127) / 128) * batch;
    if (blocks128 < 296 && (M % 64) == 0) {
        dim3 grid(nx, M / 64, batch);
        gemm_bf16x2_k<2><<<grid, 256>>>(A, Bm, C, M, N, K, lda, ldb, ldc,
                                        HB, sAo, sAi, sBo, sBi, sCo, sCi,
                                        alpha, accum, transB, gateMode, splitOut);
    } else {
        dim3 grid(nx, (M + 127) / 128, batch);
        gemm_bf16x2_k<4><<<grid, 256>>>(A, Bm, C, M, N, K, lda, ldb, ldc,
                                        HB, sAo, sAi, sBo, sBi, sCo, sCi,
                                        alpha, accum, transB, gateMode, splitOut);
    }
}

// ---------------------------------------------------------------------------
extern "C" void kernel_launch(void* const* d_in, const int* in_sizes, int n_in,
                              void* d_out, int out_size) {
    const int*   ids        = (const int*)  d_in[0];
    const float* embed      = (const float*)d_in[1];
    const float* wq         = (const float*)d_in[2];
    const float* wk         = (const float*)d_in[3];
    const float* wv         = (const float*)d_in[4];
    const float* wo         = (const float*)d_in[5];
    const float* w1         = (const float*)d_in[6];
    const float* w2         = (const float*)d_in[7];
    const float* w3         = (const float*)d_in[8];
    const float* norm1      = (const float*)d_in[9];
    const float* norm2      = (const float*)d_in[10];
    const float* final_norm = (const float*)d_in[11];
    const float* lm_head    = (const float*)d_in[12];
    const float* exit_w     = (const float*)d_in[13];
    const float* exit_b     = (const float*)d_in[14];
    const float* skip_w     = (const float*)d_in[15];
    const float* skip_b     = (const float*)d_in[16];
    float* out = (float*)d_out;

    cudaFuncSetAttribute(gemm_ws_k<1, 4>, cudaFuncAttributeMaxDynamicSharedMemorySize, SMEM_WS1);
    cudaFuncSetAttribute(gemm_ws_k<2, 4>, cudaFuncAttributeMaxDynamicSharedMemorySize, SMEM_WS2);
    cudaFuncSetAttribute(gemm_ws_k<4, 4>, cudaFuncAttributeMaxDynamicSharedMemorySize, SMEM_WS4);

    float *px, *pqkv, *psc, *pf13, *phl;
    cudaGetSymbolAddress((void**)&px,   g_x);
    cudaGetSymbolAddress((void**)&pqkv, g_qkv);
    cudaGetSymbolAddress((void**)&psc,  g_sc);
    cudaGetSymbolAddress((void**)&pf13, g_f13);
    cudaGetSymbolAddress((void**)&phl,  g_hlast);
    float* pq = pqkv;
    float* pk = pqkv + (ll)BTD;
    float* pv = pqkv + 2ll * BTD;
    float* pao;
    cudaGetSymbolAddress((void**)&pao, g_ao);

    init_k<<<1, 32>>>();
    prepack_k<<<(int)((TOTPAIRS + 255) / 256), 256>>>(wq, wk, wv, wo, w1, w2, w3, lm_head);
    rope_tables_k<<<(T_ * (HD_ / 2)) / 256, 256>>>();
    embed_k<<<(B_ * T_ * D_) / 256, 256>>>(ids, embed);

    for (int li = 0; li < L_; li++) {
        // 1) skip decision (uses x BEFORE the block)
        compute_skip_k<<<1, 128>>>(px, skip_w + (ll)li * D_, skip_b + li, li);

        // 2) transformer block (gated by do_skip)
        rmsnorm_k<<<B_ * T_, 256>>>(px, norm1 + (ll)li * D_, nullptr, D_, D_, 1, 1, 1);
        gemm_fast(0, 0, li, pqkv, MT, D_, D_, D_, D_, 3, 0, (ll)BTD, 0, 1);
        rope_k<<<(2 * B_ * T_ * D_ / 2) / 256, 256>>>(pq);
        // scores = (Q @ K^T) / sqrt(HD)  (legacy path)
        gemm_old(pq, pk, psc, T_, T_, HD_, D_, D_, T_, B_ * H_, H_,
                 (ll)T_ * D_, HD_, (ll)T_ * D_, HD_, (ll)H_ * T_ * T_, (ll)T_ * T_,
                 0.125f, 0, 1, 1, 0);
        softmax_k<<<B_ * H_ * T_, 256>>>();
        // o = att @ V  (legacy path, epilogue also writes ao_pack)
        gemm_old(psc, pv, pao, T_, HD_, T_, T_, D_, D_, B_ * H_, H_,
                 (ll)H_ * T_ * T_, (ll)T_ * T_, (ll)T_ * D_, HD_, (ll)T_ * D_, HD_,
                 1.f, 0, 0, 1, 1);
        // x += ao @ wo   (fast, A=ao_pack, BM32 fill)
        gemm_fast(1, 1, li, px, MT, D_, D_, D_, D_, 1, 0, 0, 1, 1);
        // FFN
        rmsnorm_k<<<B_ * T_, 256>>>(px, norm2 + (ll)li * D_, nullptr, D_, D_, 1, 1, 1);
        gemm_fast(0, 2, li, pf13, MT, F_, D_, F_, F_, 2, 0, (ll)BTF, 0, 1);
        silu_pack_k<<<dim3(F_ / 64, MT / 64), 256>>>();
        gemm_fast(2, 3, li, px, MT, D_, F_, D_, D_, 1, 0, 0, 1, 1);

        // 3) exit logic
        rmsnorm_k<<<B_, 256>>>(px + (ll)(T_ - 1) * D_, final_norm, phl,
                               (ll)T_ * D_, D_, 1, 1, 0);
        logits_last_k<<<dim3(V_ / 256, B_), 256>>>(lm_head);
        exit_decide_k<<<1, 256>>>(px, exit_w + (ll)li * D_, exit_b + li, li);

        // 4) full logits only for newly-exited batches
        rmsnorm_k<<<B_ * T_, 256>>>(px, final_norm, nullptr, D_, D_, 2, T_, 1);
        gemm_fast(0, 4, li, out, T_, V_, D_, V_, V_, B_, T_, (ll)T_ * V_, 0, 2);
    }

    // final logits for batches that never exited
    finalize_k<<<1, 32>>>();
    rmsnorm_k<<<B_ * T_, 256>>>(px, final_norm, nullptr, D_, D_, 2, T_, 1);
    gemm_fast(0, 4, 0, out, T_, V_, D_, V_, V_, B_, T_, (ll)T_ * V_, 0, 2);

    if (out_size >= B_ * T_ * V_ + B_)
        write_exl_k<<<1, 32>>>(out + (ll)B_ * T_ * V_);
}

// round 12
// speedup vs baseline: 4.4860x; 1.1232x over previous
#include <cuda_runtime.h>
#include <cuda_bf16.h>
#include <math.h>
#include <stdint.h>

#define B_ 4
#define T_ 256
#define D_ 1024
#define H_ 16
#define HD_ 64
#define F_ 4096
#define L_ 6
#define V_ 32000

typedef long long ll;

#define BTD (B_*T_*D_)
#define BTF (B_*T_*F_)
#define MT  (B_*T_)

#define WQPAIRS (L_*(D_/2)*D_)
#define W1PAIRS (L_*(D_/2)*F_)
#define W2PAIRS (L_*(F_/2)*D_)
#define LMPAIRS ((D_/2)*V_)
#define TOTPAIRS (4ll*WQPAIRS + 2ll*W1PAIRS + (ll)W2PAIRS + (ll)LMPAIRS)

#define HPN  ((D_/2)*MT)
#define F1PN ((F_/2)*MT)

// ---------------- scratch (static device memory, no allocs) ----------------
__device__ float g_x  [BTD];
__device__ float g_qkv[3*BTD];
__device__ float g_ao [BTD];
__device__ float g_sc [B_*H_*T_*T_];
__device__ float g_f13[2*BTF];
__device__ float g_hlast[B_*D_];
__device__ float g_ll[B_*V_];
__device__ float g_cos[T_*(HD_/2)];
__device__ float g_sin[T_*(HD_/2)];

// packed activations  [kp][MT]
__device__ uint32_t g_hpH [HPN],  g_hpL [HPN];
__device__ uint32_t g_aopH[HPN],  g_aopL[HPN];
__device__ uint32_t g_f1pH[F1PN], g_f1pL[F1PN];
__device__ uint32_t g_exH [HPN],  g_exL [HPN];   // exit-snapshot of rmsnorm(x, final_norm)
// packed weights  [L*K/2][N]
__device__ uint32_t g_wqH[WQPAIRS], g_wqL[WQPAIRS];
__device__ uint32_t g_wkH[WQPAIRS], g_wkL[WQPAIRS];
__device__ uint32_t g_wvH[WQPAIRS], g_wvL[WQPAIRS];
__device__ uint32_t g_woH[WQPAIRS], g_woL[WQPAIRS];
__device__ uint32_t g_w1H[W1PAIRS], g_w1L[W1PAIRS];
__device__ uint32_t g_w3H[W1PAIRS], g_w3L[W1PAIRS];
__device__ uint32_t g_w2H[W2PAIRS], g_w2L[W2PAIRS];
__device__ uint32_t g_lmH[LMPAIRS], g_lmL[LMPAIRS];

// ---------------- control flags ----------------
__device__ int d_do_skip;
__device__ int d_exited[B_];
__device__ int d_newly[B_];
__device__ int d_exl[B_];

// ---------------------------------------------------------------------------
__device__ __forceinline__ void split_pack(float x0, float x1,
                                           uint32_t& hi, uint32_t& lo) {
    __nv_bfloat16 h0 = __float2bfloat16(x0);
    __nv_bfloat16 h1 = __float2bfloat16(x1);
    __nv_bfloat16 l0 = __float2bfloat16(x0 - __bfloat162float(h0));
    __nv_bfloat16 l1 = __float2bfloat16(x1 - __bfloat162float(h1));
    hi = ((uint32_t)__bfloat16_as_ushort(h1) << 16) | __bfloat16_as_ushort(h0);
    lo = ((uint32_t)__bfloat16_as_ushort(l1) << 16) | __bfloat16_as_ushort(l0);
}

__global__ void init_k() {
    int t = threadIdx.x;
    if (t < B_) { d_exited[t] = 0; d_newly[t] = 0; d_exl[t] = -1; }
    if (t == 0) d_do_skip = 0;
}

__global__ void finalize_k() {
    int t = threadIdx.x;
    if (t < B_) {
        int nv = d_exited[t] ? 0 : 1;
        d_newly[t] = nv;
        if (nv) d_exl[t] = L_ - 1;
    }
    if (t == 0) d_do_skip = 0;
}

__global__ void write_exl_k(float* out) {
    int t = threadIdx.x;
    if (t < B_) out[t] = (float)d_exl[t];
}

__global__ void rope_tables_k() {
    int idx = blockIdx.x * 256 + threadIdx.x;
    int t = idx >> 5;
    int i = idx & 31;
    float inv = expf(-logf(10000.f) * (2.f * (float)i) / (float)HD_);
    float f = (float)t * inv;
    g_cos[idx] = cosf(f);
    g_sin[idx] = sinf(f);
}

__global__ void embed_k(const int* __restrict__ ids, const float* __restrict__ emb) {
    ll idx = (ll)blockIdx.x * 256 + threadIdx.x;
    int tok = ids[idx >> 10];
    g_x[idx] = emb[(ll)tok * D_ + (idx & 1023)];
}

// ---- weight prepack ----
__global__ void prepack_k(const float* __restrict__ wq, const float* __restrict__ wk,
                          const float* __restrict__ wv, const float* __restrict__ wo,
                          const float* __restrict__ w1, const float* __restrict__ w2,
                          const float* __restrict__ w3, const float* __restrict__ lm) {
    ll gid = (ll)blockIdx.x * 256 + threadIdx.x;
    if (gid >= TOTPAIRS) return;
    const float* src; uint32_t *dH, *dL; ll idx; int cols;
    ll c4 = 4ll * WQPAIRS;
    if (gid < (ll)WQPAIRS)        { src = wq; dH = g_wqH; dL = g_wqL; idx = gid; cols = D_; }
    else if (gid < 2ll*WQPAIRS)   { src = wk; dH = g_wkH; dL = g_wkL; idx = gid - WQPAIRS; cols = D_; }
    else if (gid < 3ll*WQPAIRS)   { src = wv; dH = g_wvH; dL = g_wvL; idx = gid - 2ll*WQPAIRS; cols = D_; }
    else if (gid < c4)            { src = wo; dH = g_woH; dL = g_woL; idx = gid - 3ll*WQPAIRS; cols = D_; }
    else if (gid < c4 + W1PAIRS)  { src = w1; dH = g_w1H; dL = g_w1L; idx = gid - c4; cols = F_; }
    else if (gid < c4 + 2ll*W1PAIRS) { src = w3; dH = g_w3H; dL = g_w3L; idx = gid - c4 - W1PAIRS; cols = F_; }
    else if (gid < c4 + 2ll*W1PAIRS + W2PAIRS)
                                  { src = w2; dH = g_w2H; dL = g_w2L; idx = gid - c4 - 2ll*W1PAIRS; cols = D_; }
    else                          { src = lm; dH = g_lmH; dL = g_lmL; idx = gid - c4 - 2ll*W1PAIRS - W2PAIRS; cols = V_; }
    ll kp = idx / cols;
    int col = (int)(idx - kp * cols);
    float a = src[(2*kp)     * (ll)cols + col];
    float b = src[(2*kp + 1) * (ll)cols + col];
    uint32_t h, l;
    split_pack(a, b, h, l);
    dH[idx] = h; dL[idx] = l;
}

// in-place RoPE on q and k together; layout (2B,T,H,HD)
__global__ void rope_k(float* __restrict__ q) {
    if (d_do_skip) return;
    int idx = blockIdx.x * 256 + threadIdx.x;
    int i = idx & 31;
    int t = (idx >> 9) & 255;
    ll base = (ll)(idx >> 5) * HD_ + i;
    float c = g_cos[t * 32 + i], s = g_sin[t * 32 + i];
    float x1 = q[base], x2 = q[base + 32];
    q[base]      = x1 * c - x2 * s;
    q[base + 32] = x1 * s + x2 * c;
}

// causal softmax over rows of scores (B,H,T,T)
__global__ void softmax_k() {
    if (d_do_skip) return;
    int r = blockIdx.x;
    int qrow = r & (T_ - 1);
    float* row = g_sc + (ll)r * T_;
    int tid = threadIdx.x;
    float v = (tid <= qrow) ? row[tid] : -3.4e38f;
    __shared__ float red[256];
    red[tid] = v; __syncthreads();
    for (int o = 128; o > 0; o >>= 1) { if (tid < o) red[tid] = fmaxf(red[tid], red[tid + o]); __syncthreads(); }
    float m = red[0]; __syncthreads();
    float e = (tid <= qrow) ? expf(v - m) : 0.f;
    red[tid] = e; __syncthreads();
    for (int o = 128; o > 0; o >>= 1) { if (tid < o) red[tid] += red[tid + o]; __syncthreads(); }
    row[tid] = e / red[0];
}

// silu(f1)*f3 -> packed f1 [F/2][MT] via smem transpose
__global__ void silu_pack_k() {
    if (d_do_skip) return;
    __shared__ float t1[64][65];
    __shared__ float t3[64][65];
    int f0 = blockIdx.x * 64;
    int m0 = blockIdx.y * 64;
    int tid = threadIdx.x;
#pragma unroll
    for (int it = 0; it < 16; it++) {
        int id = it * 256 + tid;
        int mm = id >> 6, ff = id & 63;
        t1[mm][ff] = g_f13[(ll)(m0 + mm) * F_ + f0 + ff];
        t3[mm][ff] = g_f13[(ll)(m0 + mm) * F_ + f0 + ff + (ll)BTF];
    }
    __syncthreads();
#pragma unroll
    for (int it = 0; it < 8; it++) {
        int id = it * 256 + tid;
        int fp = id >> 6, m = id & 63;
        float a0 = t1[m][2*fp],   b0 = t3[m][2*fp];
        float a1 = t1[m][2*fp+1], b1 = t3[m][2*fp+1];
        float v0 = (a0 / (1.f + expf(-a0))) * b0;
        float v1 = (a1 / (1.f + expf(-a1))) * b1;
        uint32_t h, l;
        split_pack(v0, v1, h, l);
        ll o = (ll)(f0/2 + fp) * MT + m0 + m;
        g_f1pH[o] = h; g_f1pL[o] = l;
    }
}

// rmsnorm; packOut: 0 none, 1 -> g_hp, 3 -> g_ex
__global__ void rmsnorm_k(const float* __restrict__ in, const float* __restrict__ w,
                          float* outF, ll inStride, ll outStride,
                          int gateMode, int rowsPerBatch, int packOut) {
    if (gateMode == 1 && d_do_skip) return;
    int row = blockIdx.x;
    if (gateMode == 2 && !d_newly[row / rowsPerBatch]) return;
    const float* xr = in + (ll)row * inStride;
    int tid = threadIdx.x;
    float4 v = reinterpret_cast<const float4*>(xr)[tid];
    float s = v.x * v.x + v.y * v.y + v.z * v.z + v.w * v.w;
    __shared__ float red[256];
    red[tid] = s; __syncthreads();
    for (int o = 128; o > 0; o >>= 1) { if (tid < o) red[tid] += red[tid + o]; __syncthreads(); }
    float scale = rsqrtf(red[0] * (1.f / (float)D_) + 1e-6f);
    float4 wv = reinterpret_cast<const float4*>(w)[tid];
    float4 ov;
    ov.x = v.x * wv.x * scale; ov.y = v.y * wv.y * scale;
    ov.z = v.z * wv.z * scale; ov.w = v.w * wv.w * scale;
    if (outF) reinterpret_cast<float4*>(outF + (ll)row * outStride)[tid] = ov;
    if (packOut) {
        uint32_t* pH = (packOut == 1) ? g_hpH : g_exH;
        uint32_t* pL = (packOut == 1) ? g_hpL : g_exL;
        uint32_t h, l;
        split_pack(ov.x, ov.y, h, l);
        pH[(ll)(2*tid)   * MT + row] = h; pL[(ll)(2*tid)   * MT + row] = l;
        split_pack(ov.z, ov.w, h, l);
        pH[(ll)(2*tid+1) * MT + row] = h; pL[(ll)(2*tid+1) * MT + row] = l;
    }
}

// last-position logits for ALL batches in one pass over packed bf16-hi lm_head.
// Decision-only precision (feeds exit confidence; margin vs 0.9 is ~2000x).
__global__ void logits_last_pk() {
    if (d_do_skip) return;
    int v = blockIdx.x * 256 + threadIdx.x;
    __shared__ float hs[B_][D_];
    for (int i = threadIdx.x; i < B_ * D_; i += 256)
        hs[i >> 10][i & 1023] = g_hlast[i];
    __syncthreads();
    float acc0 = 0.f, acc1 = 0.f, acc2 = 0.f, acc3 = 0.f;
    const uint32_t* col = g_lmH + v;
#pragma unroll 4
    for (int kp = 0; kp < D_ / 2; kp++) {
        uint32_t hv = col[(ll)kp * V_];
        float e0 = __uint_as_float(hv << 16);
        float e1 = __uint_as_float(hv & 0xffff0000u);
        acc0 = fmaf(e0, hs[0][2*kp], fmaf(e1, hs[0][2*kp+1], acc0));
        acc1 = fmaf(e0, hs[1][2*kp], fmaf(e1, hs[1][2*kp+1], acc1));
        acc2 = fmaf(e0, hs[2][2*kp], fmaf(e1, hs[2][2*kp+1], acc2));
        acc3 = fmaf(e0, hs[3][2*kp], fmaf(e1, hs[3][2*kp+1], acc3));
    }
    g_ll[v] = acc0;
    g_ll[v + V_] = acc1;
    g_ll[v + 2*V_] = acc2;
    g_ll[v + 3*V_] = acc3;
}

// warp-per-batch skip decision
__global__ void compute_skip_k(const float* __restrict__ x,
                               const float* __restrict__ sw,
                               const float* __restrict__ sb, int li) {
    int tid = threadIdx.x;
    int w = tid >> 5, l = tid & 31;
    __shared__ float sp[B_];
    if (w < B_) {
        const float* xr = x + ((ll)w * T_ + (T_ - 1)) * D_;
        float s = 0.f;
#pragma unroll 8
        for (int i = l; i < D_; i += 32) s += xr[i] * sw[i];
#pragma unroll
        for (int o = 16; o > 0; o >>= 1) s += __shfl_down_sync(0xffffffff, s, o);
        if (l == 0) sp[w] = 1.f / (1.f + expf(-(s + sb[0])));
    }
    __syncthreads();
    if (tid == 0) {
        float cnt = 0.f, s = 0.f;
        for (int b = 0; b < B_; b++) {
            float a = d_exited[b] ? 0.f : 1.f;
            cnt += a; s += sp[b] * a;
        }
        float mean = s / fmaxf(cnt, 1.f);
        d_do_skip = (li >= 1 && cnt > 0.f && mean < 0.1f) ? 1 : 0;
    }
}

// parallel exit decision: 4 batches x 64 threads
__global__ void exit_decide_k(const float* __restrict__ x,
                              const float* __restrict__ ew,
                              const float* __restrict__ eb, int li) {
    int tid = threadIdx.x;
    if (d_do_skip) { if (tid < B_) d_newly[tid] = 0; return; }
    __shared__ float red[256];
    __shared__ float mxs[B_], sums[B_], eps_[B_];
    int b = tid >> 6, l = tid & 63;
    const float* lr = g_ll + (ll)b * V_;
    float m = -3.4e38f;
    for (int i = l; i < V_; i += 64) m = fmaxf(m, lr[i]);
    red[tid] = m; __syncthreads();
    for (int o = 32; o > 0; o >>= 1) { if (l < o) red[tid] = fmaxf(red[tid], red[tid + o]); __syncthreads(); }
    if (l == 0) mxs[b] = red[tid];
    __syncthreads();
    float mx = mxs[b];
    float s = 0.f;
    for (int i = l; i < V_; i += 64) s += expf(lr[i] - mx);
    red[tid] = s; __syncthreads();
    for (int o = 32; o > 0; o >>= 1) { if (l < o) red[tid] += red[tid + o]; __syncthreads(); }
    if (l == 0) sums[b] = red[tid];
    __syncthreads();
    const float* xr = x + ((ll)b * T_ + (T_ - 1)) * D_;
    float e = 0.f;
    for (int i = l; i < D_; i += 64) e += xr[i] * ew[i];
    red[tid] = e; __syncthreads();
    for (int o = 32; o > 0; o >>= 1) { if (l < o) red[tid] += red[tid + o]; __syncthreads(); }
    if (l == 0) eps_[b] = 1.f / (1.f + expf(-(red[tid] + eb[0])));
    __syncthreads();
    if (tid < B_) {
        int bb = tid;
        float conf = 1.f / sums[bb];
        int should = (conf > 0.9f) || (eps_[bb] > 0.9f);
        int nw = (should && !d_exited[bb]) ? 1 : 0;
        d_newly[bb] = nw;
        if (nw) { d_exited[bb] = 1; d_exl[bb] = li; }
    }
}

#define MMA_BF16(acc, a, b)                                                   \
    asm volatile(                                                             \
        "mma.sync.aligned.m16n8k16.row.col.f32.bf16.bf16.f32 "                \
        "{%0,%1,%2,%3}, {%4,%5,%6,%7}, {%8,%9}, {%0,%1,%2,%3};"               \
        : "+f"(acc[0]), "+f"(acc[1]), "+f"(acc[2]), "+f"(acc[3])              \
        : "r"(a[0]), "r"(a[1]), "r"(a[2]), "r"(a[3]), "r"(b[0]), "r"(b[1]))

// =====================  fast cp.async GEMM on packed operands ==============
// A: packed [K/2][MT] hi/lo (aSel 0=h,1=ao,2=f1,3=ex). B: packed weights (wSel).
// accumulate: 0 store, 1 +=, 2 atomicAdd (split-K).
// splitK>1: blockIdx.z indexes the K chunk (batch must be 1).
template <int IBLK, int STG>
__global__ __launch_bounds__(256, (IBLK == 4) ? 1 : 2) void gemm_ws_k(
    int aSel, int wSel, int li, float* __restrict__ C,
    int M, int N, int K, int ldbU, int ldc,
    int aColStride, ll sCo, int accumulate, int gateMode, int splitK) {
    if (gateMode == 1 && d_do_skip) return;
    if (gateMode == 2 && !d_newly[blockIdx.z]) return;
    constexpr int BM = IBLK * 32;
    constexpr int SPA = BM + 8;
    constexpr int SPB = 136;
    constexpr int KP = 16;
    constexpr int AS = KP * SPA, BS = KP * SPB;
    constexpr int STAGE = 2 * AS + 2 * BS;
    constexpr int ACHROW = BM / 4;
    constexpr int ACH = KP * ACHROW;
    constexpr int BCH = KP * 32;
    constexpr int TCH = 2 * ACH + 2 * BCH;

    extern __shared__ uint32_t sm[];
    const int z = blockIdx.z;

    const uint32_t* aHp = (aSel == 0) ? g_hpH : ((aSel == 1) ? g_aopH :
                          ((aSel == 2) ? g_f1pH : g_exH));
    const uint32_t* aLp = (aSel == 0) ? g_hpL : ((aSel == 1) ? g_aopL :
                          ((aSel == 2) ? g_f1pL : g_exL));
    const uint32_t *bHp, *bLp;
    {
        ll off;
        switch (wSel) {
        case 0:
            off = (ll)li * (D_/2) * D_;
            bHp = ((z == 0) ? g_wqH : ((z == 1) ? g_wkH : g_wvH)) + off;
            bLp = ((z == 0) ? g_wqL : ((z == 1) ? g_wkL : g_wvL)) + off;
            break;
        case 1:
            off = (ll)li * (D_/2) * D_;
            bHp = g_woH + off; bLp = g_woL + off; break;
        case 2:
            off = (ll)li * (D_/2) * F_;
            bHp = ((z == 0) ? g_w1H : g_w3H) + off;
            bLp = ((z == 0) ? g_w1L : g_w3L) + off; break;
        case 3:
            off = (ll)li * (F_/2) * D_;
            bHp = g_w2H + off; bLp = g_w2L + off; break;
        default:
            bHp = g_lmH; bLp = g_lmL; break;
        }
    }
    const int Ksub = K / splitK;
    const int kpBase = (splitK > 1) ? z * (Ksub / 2) : 0;
    const int aOff = (splitK > 1) ? 0 : z * aColStride;
    float* Cb = (splitK > 1) ? C : (C + (ll)z * sCo);

    const int tid = threadIdx.x;
    const int lane = tid & 31;
    const int warp = tid >> 5;
    const int warpRow = warp >> 2;
    const int warpCol = warp & 3;
    const int rowBase = blockIdx.y * BM;
    const int colBase = blockIdx.x * 128;
    const int lq = lane >> 2;
    const int lr = lane & 3;

    auto loadTile = [&](int t, int s) {
        uint32_t* st = sm + s * STAGE;
        int kp0 = kpBase + t * KP;
#pragma unroll
        for (int c = tid; c < TCH; c += 256) {
            uint32_t* dst; const uint32_t* src;
            if (c < 2 * ACH) {
                int cc = c; const uint32_t* g = aHp; uint32_t* ss = st;
                if (cc >= ACH) { cc -= ACH; g = aLp; ss = st + AS; }
                int row = cc / ACHROW, col = (cc % ACHROW) * 4;
                dst = ss + row * SPA + col;
                src = g + (ll)(kp0 + row) * MT + aOff + rowBase + col;
            } else {
                int cc = c - 2 * ACH; const uint32_t* g = bHp; uint32_t* ss = st + 2 * AS;
                if (cc >= BCH) { cc -= BCH; g = bLp; ss += BS; }
                int row = cc >> 5, col = (cc & 31) * 4;
                dst = ss + row * SPB + col;
                src = g + (ll)(kp0 + row) * ldbU + colBase + col;
            }
            uint32_t da = (uint32_t)__cvta_generic_to_shared(dst);
            asm volatile("cp.async.cg.shared.global [%0], [%1], 16;\n"
                         :: "r"(da), "l"(src));
        }
        asm volatile("cp.async.commit_group;\n");
    };

    float acc[IBLK][4][4];
#pragma unroll
    for (int i = 0; i < IBLK; i++)
#pragma unroll
        for (int j = 0; j < 4; j++)
#pragma unroll
            for (int r = 0; r < 4; r++) acc[i][j][r] = 0.f;

    const int nt = Ksub / 32;
#pragma unroll
    for (int s = 0; s < STG - 1; s++) loadTile(s, s);

    for (int t = 0; t < nt; t++) {
        asm volatile("cp.async.wait_group %0;\n" :: "n"(STG - 2));
        __syncthreads();
        int tn = t + STG - 1;
        if (tn < nt) loadTile(tn, tn % STG);
        else asm volatile("cp.async.commit_group;\n");

        const uint32_t* AsH = sm + (t % STG) * STAGE;
        const uint32_t* AsL = AsH + AS;
        const uint32_t* BsH = AsH + 2 * AS;
        const uint32_t* BsL = BsH + BS;
#pragma unroll
        for (int st2 = 0; st2 < 2; st2++) {
            int base = st2 * 8;
            uint32_t aH[IBLK][4], aL[IBLK][4], bH[4][2], bL[4][2];
#pragma unroll
            for (int i = 0; i < IBLK; i++) {
                int m0 = warpRow * (IBLK * 16) + i * 16 + lq;
                aH[i][0] = AsH[(base + lr) * SPA + m0];
                aH[i][1] = AsH[(base + lr) * SPA + m0 + 8];
                aH[i][2] = AsH[(base + lr + 4) * SPA + m0];
                aH[i][3] = AsH[(base + lr + 4) * SPA + m0 + 8];
                aL[i][0] = AsL[(base + lr) * SPA + m0];
                aL[i][1] = AsL[(base + lr) * SPA + m0 + 8];
                aL[i][2] = AsL[(base + lr + 4) * SPA + m0];
                aL[i][3] = AsL[(base + lr + 4) * SPA + m0 + 8];
            }
#pragma unroll
            for (int j = 0; j < 4; j++) {
                int n0 = warpCol * 32 + j * 8 + lq;
                bH[j][0] = BsH[(base + lr) * SPB + n0];
                bH[j][1] = BsH[(base + lr + 4) * SPB + n0];
                bL[j][0] = BsL[(base + lr) * SPB + n0];
                bL[j][1] = BsL[(base + lr + 4) * SPB + n0];
            }
#pragma unroll
            for (int i = 0; i < IBLK; i++)
#pragma unroll
                for (int j = 0; j < 4; j++) MMA_BF16(acc[i][j], aH[i], bL[j]);
#pragma unroll
            for (int i = 0; i < IBLK; i++)
#pragma unroll
                for (int j = 0; j < 4; j++) MMA_BF16(acc[i][j], aL[i], bH[j]);
#pragma unroll
            for (int i = 0; i < IBLK; i++)
#pragma unroll
                for (int j = 0; j < 4; j++) MMA_BF16(acc[i][j], aH[i], bH[j]);
        }
    }

#pragma unroll
    for (int i = 0; i < IBLK; i++) {
#pragma unroll
        for (int r2 = 0; r2 < 2; r2++) {
            int gm = rowBase + warpRow * (IBLK * 16) + i * 16 + lq + r2 * 8;
            if (gm >= M) continue;
            float* crow = Cb + (ll)gm * ldc;
#pragma unroll
            for (int j = 0; j < 4; j++) {
                int gn = colBase + warpCol * 32 + j * 8 + lr * 2;
                float v0 = acc[i][j][r2 * 2 + 0];
                float v1 = acc[i][j][r2 * 2 + 1];
                if (gn < N) {
                    if (accumulate == 2)      atomicAdd(crow + gn, v0);
                    else if (accumulate == 1) crow[gn] += v0;
                    else                      crow[gn] = v0;
                }
                if (gn + 1 < N) {
                    if (accumulate == 2)      atomicAdd(crow + gn + 1, v1);
                    else if (accumulate == 1) crow[gn + 1] += v1;
                    else                      crow[gn + 1] = v1;
                }
            }
        }
    }
}

#define SMEM_WS1 (4 * (2*16*(32+8)  + 2*16*136) * 4)
#define SMEM_WS2 (4 * (2*16*(64+8)  + 2*16*136) * 4)
#define SMEM_WS4 (4 * (2*16*(128+8) + 2*16*136) * 4)

static void gemm_fast(int aSel, int wSel, int li, float* C,
                      int M, int N, int K, int ldbU, int ldc,
                      int batch, int aColStride, ll sCo, int acc, int gate) {
    int nx = N / 128;
    int b128 = nx * (M / 128) * batch;
    if (b128 >= 296) {
        dim3 g(nx, M / 128, batch);
        gemm_ws_k<4, 4><<<g, 256, SMEM_WS4>>>(aSel, wSel, li, C, M, N, K, ldbU, ldc,
                                              aColStride, sCo, acc, gate, 1);
    } else {
        dim3 g(nx, M / 64, batch);
        gemm_ws_k<2, 4><<<g, 256, SMEM_WS2>>>(aSel, wSel, li, C, M, N, K, ldbU, ldc,
                                              aColStride, sCo, acc, gate, 1);
    }
}

// split-K accumulate variant (wo / w2): BM64, splitK chunks atomicAdd into C
static void gemm_fast_sk(int aSel, int wSel, int li, float* C,
                         int M, int N, int K, int ldbU, int ldc,
                         int splitK, int gate) {
    dim3 g(N / 128, M / 64, splitK);
    gemm_ws_k<2, 4><<<g, 256, SMEM_WS2>>>(aSel, wSel, li, C, M, N, K, ldbU, ldc,
                                          0, 0, 2, gate, splitK);
}

// ============= legacy register-staged GEMM (QK^T and AV paths) =============
#define KT 32

template <int IBLK>
__global__ __launch_bounds__(256, (IBLK == 2) ? 2 : 1) void gemm_bf16x2_k(
    const float* __restrict__ A, const float* __restrict__ Bm, float* __restrict__ C,
    int M, int N, int K, int lda, int ldb, int ldc,
    int HB, ll sAo, ll sAi, ll sBo, ll sBi, ll sCo, ll sCi,
    float alpha, int accumulate, int transB, int gateMode, int splitOut) {
    if (gateMode == 1 && d_do_skip) return;
    constexpr int BM = IBLK * 32;
    constexpr int SPA = BM + 8;
    constexpr int SPB = 136;

    int z = blockIdx.z;
    const float* Ab = A  + (ll)(z / HB) * sAo + (ll)(z % HB) * sAi;
    const float* Bb = Bm + (ll)(z / HB) * sBo + (ll)(z % HB) * sBi;
    float*       Cb = C  + (ll)(z / HB) * sCo + (ll)(z % HB) * sCi;

    __shared__ uint32_t AsH[KT/2][SPA], AsL[KT/2][SPA];
    __shared__ uint32_t BsH[KT/2][SPB], BsL[KT/2][SPB];

    const int tid = threadIdx.x;
    const int lane = tid & 31;
    const int warp = tid >> 5;
    const int warpRow = warp >> 2;
    const int warpCol = warp & 3;
    const int rowBase = blockIdx.y * BM;
    const int colBase = blockIdx.x * 128;

    float acc[IBLK][4][4];
#pragma unroll
    for (int i = 0; i < IBLK; i++)
#pragma unroll
        for (int j = 0; j < 4; j++)
#pragma unroll
            for (int r = 0; r < 4; r++) acc[i][j][r] = 0.f;

    const int lq = lane >> 2;
    const int lr = lane & 3;

    float4 ar[IBLK];
    float4 br[4];

    const int a_m   = (IBLK == 4) ? (tid >> 1) : (tid >> 2);
    const int a_kk0 = (IBLK == 4) ? ((tid & 1) * 8) : ((tid & 3) * 8);
    const int bn_kp = tid >> 5;
    const int bn_n4 = (tid & 31) * 4;
    const int bt_n  = tid >> 1;
    const int bt_kk0= (tid & 1) * 8;

    const int gmA = rowBase + a_m;
    const bool aOk = (gmA < M);
    const int gnBn = colBase + bn_n4;
    const int gnBt = colBase + bt_n;

    auto loadA = [&](int k0) {
        if (IBLK == 4) {
#pragma unroll
            for (int seg = 0; seg < 2; seg++) {
                int kk = a_kk0 + seg * 16;
                if (aOk) {
                    const float* p = Ab + (ll)gmA * lda + k0 + kk;
                    ar[seg * 2 + 0] = *reinterpret_cast<const float4*>(p);
                    ar[seg * 2 + 1] = *reinterpret_cast<const float4*>(p + 4);
                } else {
                    ar[seg * 2 + 0] = make_float4(0, 0, 0, 0);
                    ar[seg * 2 + 1] = make_float4(0, 0, 0, 0);
                }
            }
        } else {
            if (aOk) {
                const float* p = Ab + (ll)gmA * lda + k0 + a_kk0;
                ar[0] = *reinterpret_cast<const float4*>(p);
                ar[1] = *reinterpret_cast<const float4*>(p + 4);
            } else {
                ar[0] = make_float4(0, 0, 0, 0);
                ar[1] = make_float4(0, 0, 0, 0);
            }
        }
    };
    auto loadB = [&](int k0) {
        if (!transB) {
#pragma unroll
            for (int seg = 0; seg < 2; seg++) {
                int kpair = bn_kp + seg * 8;
                const float* p0 = Bb + (ll)(k0 + 2 * kpair) * ldb + gnBn;
                const float* p1 = p0 + ldb;
                if (gnBn + 3 < N) {
                    br[seg * 2 + 0] = *reinterpret_cast<const float4*>(p0);
                    br[seg * 2 + 1] = *reinterpret_cast<const float4*>(p1);
                } else {
                    float u[4], w[4];
#pragma unroll
                    for (int q = 0; q < 4; q++) {
                        u[q] = (gnBn + q < N) ? p0[q] : 0.f;
                        w[q] = (gnBn + q < N) ? p1[q] : 0.f;
                    }
                    br[seg * 2 + 0] = make_float4(u[0], u[1], u[2], u[3]);
                    br[seg * 2 + 1] = make_float4(w[0], w[1], w[2], w[3]);
                }
            }
        } else {
#pragma unroll
            for (int seg = 0; seg < 2; seg++) {
                int kk = bt_kk0 + seg * 16;
                if (gnBt < N) {
                    const float* p = Bb + (ll)gnBt * ldb + k0 + kk;
                    br[seg * 2 + 0] = *reinterpret_cast<const float4*>(p);
                    br[seg * 2 + 1] = *reinterpret_cast<const float4*>(p + 4);
                } else {
                    br[seg * 2 + 0] = make_float4(0, 0, 0, 0);
                    br[seg * 2 + 1] = make_float4(0, 0, 0, 0);
                }
            }
        }
    };
    auto storeA = [&]() {
        if (IBLK == 4) {
#pragma unroll
            for (int seg = 0; seg < 2; seg++) {
                int kp0 = (a_kk0 + seg * 16) >> 1;
                float4 v0 = ar[seg * 2 + 0], v1 = ar[seg * 2 + 1];
                uint32_t h, l;
                split_pack(v0.x, v0.y, h, l); AsH[kp0 + 0][a_m] = h; AsL[kp0 + 0][a_m] = l;
                split_pack(v0.z, v0.w, h, l); AsH[kp0 + 1][a_m] = h; AsL[kp0 + 1][a_m] = l;
                split_pack(v1.x, v1.y, h, l); AsH[kp0 + 2][a_m] = h; AsL[kp0 + 2][a_m] = l;
                split_pack(v1.z, v1.w, h, l); AsH[kp0 + 3][a_m] = h; AsL[kp0 + 3][a_m] = l;
            }
        } else {
            int kp0 = a_kk0 >> 1;
            float4 v0 = ar[0], v1 = ar[1];
            uint32_t h, l;
            split_pack(v0.x, v0.y, h, l); AsH[kp0 + 0][a_m] = h; AsL[kp0 + 0][a_m] = l;
            split_pack(v0.z, v0.w, h, l); AsH[kp0 + 1][a_m] = h; AsL[kp0 + 1][a_m] = l;
            split_pack(v1.x, v1.y, h, l); AsH[kp0 + 2][a_m] = h; AsL[kp0 + 2][a_m] = l;
            split_pack(v1.z, v1.w, h, l); AsH[kp0 + 3][a_m] = h; AsL[kp0 + 3][a_m] = l;
        }
    };
    auto storeB = [&]() {
        if (!transB) {
#pragma unroll
            for (int seg = 0; seg < 2; seg++) {
                int kpair = bn_kp + seg * 8;
                float4 u4 = br[seg * 2 + 0], w4 = br[seg * 2 + 1];
                float u[4] = {u4.x, u4.y, u4.z, u4.w};
                float w[4] = {w4.x, w4.y, w4.z, w4.w};
#pragma unroll
                for (int q = 0; q < 4; q++) {
                    uint32_t h, l;
                    split_pack(u[q], w[q], h, l);
                    BsH[kpair][bn_n4 + q] = h; BsL[kpair][bn_n4 + q] = l;
                }
            }
        } else {
#pragma unroll
            for (int seg = 0; seg < 2; seg++) {
                int kp0 = (bt_kk0 + seg * 16) >> 1;
                float4 v0 = br[seg * 2 + 0], v1 = br[seg * 2 + 1];
                uint32_t h, l;
                split_pack(v0.x, v0.y, h, l); BsH[kp0 + 0][bt_n] = h; BsL[kp0 + 0][bt_n] = l;
                split_pack(v0.z, v0.w, h, l); BsH[kp0 + 1][bt_n] = h; BsL[kp0 + 1][bt_n] = l;
                split_pack(v1.x, v1.y, h, l); BsH[kp0 + 2][bt_n] = h; BsL[kp0 + 2][bt_n] = l;
                split_pack(v1.z, v1.w, h, l); BsH[kp0 + 3][bt_n] = h; BsL[kp0 + 3][bt_n] = l;
            }
        }
    };

    const int nt = K / KT;
    loadA(0); loadB(0);
    storeA(); storeB();
    for (int t = 0; t < nt; t++) {
        __syncthreads();
        if (t + 1 < nt) { loadA((t + 1) * KT); loadB((t + 1) * KT); }
#pragma unroll
        for (int st = 0; st < 2; st++) {
            int base = st * 8;
            uint32_t aH[IBLK][4], aL[IBLK][4], bH[4][2], bL[4][2];
#pragma unroll
            for (int i = 0; i < IBLK; i++) {
                int m0 = warpRow * (IBLK * 16) + i * 16 + lq;
                aH[i][0] = AsH[base + lr][m0];     aH[i][1] = AsH[base + lr][m0 + 8];
                aH[i][2] = AsH[base + lr + 4][m0]; aH[i][3] = AsH[base + lr + 4][m0 + 8];
                aL[i][0] = AsL[base + lr][m0];     aL[i][1] = AsL[base + lr][m0 + 8];
                aL[i][2] = AsL[base + lr + 4][m0]; aL[i][3] = AsL[base + lr + 4][m0 + 8];
            }
#pragma unroll
            for (int j = 0; j < 4; j++) {
                int n0 = warpCol * 32 + j * 8 + lq;
                bH[j][0] = BsH[base + lr][n0]; bH[j][1] = BsH[base + lr + 4][n0];
                bL[j][0] = BsL[base + lr][n0]; bL[j][1] = BsL[base + lr + 4][n0];
            }
#pragma unroll
            for (int i = 0; i < IBLK; i++)
#pragma unroll
                for (int j = 0; j < 4; j++) MMA_BF16(acc[i][j], aH[i], bL[j]);
#pragma unroll
            for (int i = 0; i < IBLK; i++)
#pragma unroll
                for (int j = 0; j < 4; j++) MMA_BF16(acc[i][j], aL[i], bH[j]);
#pragma unroll
            for (int i = 0; i < IBLK; i++)
#pragma unroll
                for (int j = 0; j < 4; j++) MMA_BF16(acc[i][j], aH[i], bH[j]);
        }
        __syncthreads();
        if (t + 1 < nt) { storeA(); storeB(); }
    }

    const int zb = z / HB, zh = z % HB;
#pragma unroll
    for (int i = 0; i < IBLK; i++) {
#pragma unroll
        for (int r2 = 0; r2 < 2; r2++) {
            int gm = rowBase + warpRow * (IBLK * 16) + i * 16 + lq + r2 * 8;
            if (gm >= M) continue;
            float* crow = Cb + (ll)gm * ldc;
#pragma unroll
            for (int j = 0; j < 4; j++) {
                int gn = colBase + warpCol * 32 + j * 8 + lr * 2;
                float v0 = alpha * acc[i][j][r2 * 2 + 0];
                float v1 = alpha * acc[i][j][r2 * 2 + 1];
                if (gn < N)     { if (accumulate) crow[gn] += v0;     else crow[gn] = v0; }
                if (gn + 1 < N) { if (accumulate) crow[gn + 1] += v1; else crow[gn + 1] = v1; }
                if (splitOut && gn + 1 < N) {
                    uint32_t h, l;
                    split_pack(v0, v1, h, l);
                    ll o = (ll)((zh * HD_ + gn) >> 1) * MT + zb * T_ + gm;
                    g_aopH[o] = h; g_aopL[o] = l;
                }
            }
        }
    }
}

static void gemm_old(const float* A, const float* Bm, float* C, int M, int N, int K,
                     int lda, int ldb, int ldc, int batch, int HB,
                     ll sAo, ll sAi, ll sBo, ll sBi, ll sCo, ll sCi,
                     float alpha, int accum, int transB, int gateMode, int splitOut) {
    int nx = (N + 127) / 128;
    ll blocks128 = (ll)nx * ((M + 127) / 128) * batch;
    if (blocks128 < 296 && (M % 64) == 0) {
        dim3 grid(nx, M / 64, batch);
        gemm_bf16x2_k<2><<<grid, 256>>>(A, Bm, C, M, N, K, lda, ldb, ldc,
                                        HB, sAo, sAi, sBo, sBi, sCo, sCi,
                                        alpha, accum, transB, gateMode, splitOut);
    } else {
        dim3 grid(nx, (M + 127) / 128, batch);
        gemm_bf16x2_k<4><<<grid, 256>>>(A, Bm, C, M, N, K, lda, ldb, ldc,
                                        HB, sAo, sAi, sBo, sBi, sCo, sCi,
                                        alpha, accum, transB, gateMode, splitOut);
    }
}

// ---------------------------------------------------------------------------
extern "C" void kernel_launch(void* const* d_in, const int* in_sizes, int n_in,
                              void* d_out, int out_size) {
    const int*   ids        = (const int*)  d_in[0];
    const float* embed      = (const float*)d_in[1];
    const float* wq         = (const float*)d_in[2];
    const float* wk         = (const float*)d_in[3];
    const float* wv         = (const float*)d_in[4];
    const float* wo         = (const float*)d_in[5];
    const float* w1         = (const float*)d_in[6];
    const float* w2         = (const float*)d_in[7];
    const float* w3         = (const float*)d_in[8];
    const float* norm1      = (const float*)d_in[9];
    const float* norm2      = (const float*)d_in[10];
    const float* final_norm = (const float*)d_in[11];
    const float* lm_head    = (const float*)d_in[12];
    const float* exit_w     = (const float*)d_in[13];
    const float* exit_b     = (const float*)d_in[14];
    const float* skip_w     = (const float*)d_in[15];
    const float* skip_b     = (const float*)d_in[16];
    float* out = (float*)d_out;

    cudaFuncSetAttribute(gemm_ws_k<2, 4>, cudaFuncAttributeMaxDynamicSharedMemorySize, SMEM_WS2);
    cudaFuncSetAttribute(gemm_ws_k<4, 4>, cudaFuncAttributeMaxDynamicSharedMemorySize, SMEM_WS4);

    float *px, *pqkv, *psc, *pf13, *phl;
    cudaGetSymbolAddress((void**)&px,   g_x);
    cudaGetSymbolAddress((void**)&pqkv, g_qkv);
    cudaGetSymbolAddress((void**)&psc,  g_sc);
    cudaGetSymbolAddress((void**)&pf13, g_f13);
    cudaGetSymbolAddress((void**)&phl,  g_hlast);
    float* pq = pqkv;
    float* pk = pqkv + (ll)BTD;
    float* pv = pqkv + 2ll * BTD;
    float* pao;
    cudaGetSymbolAddress((void**)&pao, g_ao);

    init_k<<<1, 32>>>();
    prepack_k<<<(int)((TOTPAIRS + 255) / 256), 256>>>(wq, wk, wv, wo, w1, w2, w3, lm_head);
    rope_tables_k<<<(T_ * (HD_ / 2)) / 256, 256>>>();
    embed_k<<<(B_ * T_ * D_) / 256, 256>>>(ids, embed);

    for (int li = 0; li < L_; li++) {
        // 1) skip decision (uses x BEFORE the block)
        compute_skip_k<<<1, 128>>>(px, skip_w + (ll)li * D_, skip_b + li, li);

        // 2) transformer block (gated by do_skip)
        rmsnorm_k<<<B_ * T_, 256>>>(px, norm1 + (ll)li * D_, nullptr, D_, D_, 1, 1, 1);
        gemm_fast(0, 0, li, pqkv, MT, D_, D_, D_, D_, 3, 0, (ll)BTD, 0, 1);
        rope_k<<<(2 * B_ * T_ * D_ / 2) / 256, 256>>>(pq);
        gemm_old(pq, pk, psc, T_, T_, HD_, D_, D_, T_, B_ * H_, H_,
                 (ll)T_ * D_, HD_, (ll)T_ * D_, HD_, (ll)H_ * T_ * T_, (ll)T_ * T_,
                 0.125f, 0, 1, 1, 0);
        softmax_k<<<B_ * H_ * T_, 256>>>();
        gemm_old(psc, pv, pao, T_, HD_, T_, T_, D_, D_, B_ * H_, H_,
                 (ll)H_ * T_ * T_, (ll)T_ * T_, (ll)T_ * D_, HD_, (ll)T_ * D_, HD_,
                 1.f, 0, 0, 1, 1);
        // x += ao @ wo  (split-K=2, atomicAdd, full wave)
        gemm_fast_sk(1, 1, li, px, MT, D_, D_, D_, D_, 2, 1);
        // FFN
        rmsnorm_k<<<B_ * T_, 256>>>(px, norm2 + (ll)li * D_, nullptr, D_, D_, 1, 1, 1);
        gemm_fast(0, 2, li, pf13, MT, F_, D_, F_, F_, 2, 0, (ll)BTF, 0, 1);
        silu_pack_k<<<dim3(F_ / 64, MT / 64), 256>>>();
        // x += f1 @ w2  (split-K=2, atomicAdd, full wave)
        gemm_fast_sk(2, 3, li, px, MT, D_, F_, D_, D_, 2, 1);

        // 3) exit logic (packed bf16-hi lm_head, all batches in one pass)
        rmsnorm_k<<<B_, 256>>>(px + (ll)(T_ - 1) * D_, final_norm, phl,
                               (ll)T_ * D_, D_, 1, 1, 0);
        logits_last_pk<<<V_ / 256, 256>>>();
        exit_decide_k<<<1, 256>>>(px, exit_w + (ll)li * D_, exit_b + li, li);

        // 4) snapshot rmsnorm(x, final_norm) for newly-exited batches -> g_ex
        rmsnorm_k<<<B_ * T_, 256>>>(px, final_norm, nullptr, D_, D_, 2, T_, 3);
    }

    // final: snapshot for never-exited, then ONE logits GEMM for all batches
    finalize_k<<<1, 32>>>();
    rmsnorm_k<<<B_ * T_, 256>>>(px, final_norm, nullptr, D_, D_, 2, T_, 3);
    gemm_fast(3, 4, 0, out, T_, V_, D_, V_, V_, B_, T_, (ll)T_ * V_, 0, 0);

    if (out_size >= B_ * T_ * V_ + B_)
        write_exl_k<<<1, 32>>>(out + (ll)B_ * T_ * V_);
}

// round 13
// speedup vs baseline: 5.0770x; 1.1317x over previous
#include <cuda_runtime.h>
#include <cuda_bf16.h>
#include <math.h>
#include <stdint.h>

#define B_ 4
#define T_ 256
#define D_ 1024
#define H_ 16
#define HD_ 64
#define F_ 4096
#define L_ 6
#define V_ 32000
#define NPB (V_/256)          // logits partial blocks = 125

typedef long long ll;

#define BTD (B_*T_*D_)
#define BTF (B_*T_*F_)
#define MT  (B_*T_)

#define WQPAIRS (L_*(D_/2)*D_)
#define W1PAIRS (L_*(D_/2)*F_)
#define W2PAIRS (L_*(F_/2)*D_)
#define LMPAIRS ((D_/2)*V_)
#define TOTPAIRS (4ll*WQPAIRS + 2ll*W1PAIRS + (ll)W2PAIRS + (ll)LMPAIRS)

#define HPN  ((D_/2)*MT)
#define F1PN ((F_/2)*MT)

// ---------------- scratch (static device memory, no allocs) ----------------
__device__ float g_x  [BTD];
__device__ float g_qkv[3*BTD];
__device__ float g_f13[2*BTF];
__device__ float g_hlast[B_*D_];
__device__ float g_cos[T_*(HD_/2)];
__device__ float g_sin[T_*(HD_/2)];
__device__ float g_pM[NPB*B_];
__device__ float g_pS[NPB*B_];

// packed activations  [kp][MT]
__device__ uint32_t g_hpH [HPN],  g_hpL [HPN];
__device__ uint32_t g_aopH[HPN],  g_aopL[HPN];
__device__ uint32_t g_f1pH[F1PN], g_f1pL[F1PN];
__device__ uint32_t g_exH [HPN],  g_exL [HPN];
// packed weights  [L*K/2][N]
__device__ uint32_t g_wqH[WQPAIRS], g_wqL[WQPAIRS];
__device__ uint32_t g_wkH[WQPAIRS], g_wkL[WQPAIRS];
__device__ uint32_t g_wvH[WQPAIRS], g_wvL[WQPAIRS];
__device__ uint32_t g_woH[WQPAIRS], g_woL[WQPAIRS];
__device__ uint32_t g_w1H[W1PAIRS], g_w1L[W1PAIRS];
__device__ uint32_t g_w3H[W1PAIRS], g_w3L[W1PAIRS];
__device__ uint32_t g_w2H[W2PAIRS], g_w2L[W2PAIRS];
__device__ uint32_t g_lmH[LMPAIRS], g_lmL[LMPAIRS];

// ---------------- control flags ----------------
__device__ int d_do_skip;
__device__ int d_exited[B_];
__device__ int d_newly[B_];
__device__ int d_exl[B_];

// ---------------------------------------------------------------------------
__device__ __forceinline__ void split_pack(float x0, float x1,
                                           uint32_t& hi, uint32_t& lo) {
    __nv_bfloat16 h0 = __float2bfloat16(x0);
    __nv_bfloat16 h1 = __float2bfloat16(x1);
    __nv_bfloat16 l0 = __float2bfloat16(x0 - __bfloat162float(h0));
    __nv_bfloat16 l1 = __float2bfloat16(x1 - __bfloat162float(h1));
    hi = ((uint32_t)__bfloat16_as_ushort(h1) << 16) | __bfloat16_as_ushort(h0);
    lo = ((uint32_t)__bfloat16_as_ushort(l1) << 16) | __bfloat16_as_ushort(l0);
}

__global__ void init_k() {
    int t = threadIdx.x;
    if (t < B_) { d_exited[t] = 0; d_newly[t] = 0; d_exl[t] = -1; }
    if (t == 0) d_do_skip = 0;
}

__global__ void finalize_k() {
    int t = threadIdx.x;
    if (t < B_) {
        int nv = d_exited[t] ? 0 : 1;
        d_newly[t] = nv;
        if (nv) d_exl[t] = L_ - 1;
    }
    if (t == 0) d_do_skip = 0;
}

__global__ void write_exl_k(float* out) {
    int t = threadIdx.x;
    if (t < B_) out[t] = (float)d_exl[t];
}

__global__ void rope_tables_k() {
    int idx = blockIdx.x * 256 + threadIdx.x;
    int t = idx >> 5;
    int i = idx & 31;
    float inv = expf(-logf(10000.f) * (2.f * (float)i) / (float)HD_);
    float f = (float)t * inv;
    g_cos[idx] = cosf(f);
    g_sin[idx] = sinf(f);
}

__global__ void embed_k(const int* __restrict__ ids, const float* __restrict__ emb) {
    ll idx = (ll)blockIdx.x * 256 + threadIdx.x;
    int tok = ids[idx >> 10];
    g_x[idx] = emb[(ll)tok * D_ + (idx & 1023)];
}

// ---- weight prepack ----
__global__ void prepack_k(const float* __restrict__ wq, const float* __restrict__ wk,
                          const float* __restrict__ wv, const float* __restrict__ wo,
                          const float* __restrict__ w1, const float* __restrict__ w2,
                          const float* __restrict__ w3, const float* __restrict__ lm) {
    ll gid = (ll)blockIdx.x * 256 + threadIdx.x;
    if (gid >= TOTPAIRS) return;
    const float* src; uint32_t *dH, *dL; ll idx; int cols;
    ll c4 = 4ll * WQPAIRS;
    if (gid < (ll)WQPAIRS)        { src = wq; dH = g_wqH; dL = g_wqL; idx = gid; cols = D_; }
    else if (gid < 2ll*WQPAIRS)   { src = wk; dH = g_wkH; dL = g_wkL; idx = gid - WQPAIRS; cols = D_; }
    else if (gid < 3ll*WQPAIRS)   { src = wv; dH = g_wvH; dL = g_wvL; idx = gid - 2ll*WQPAIRS; cols = D_; }
    else if (gid < c4)            { src = wo; dH = g_woH; dL = g_woL; idx = gid - 3ll*WQPAIRS; cols = D_; }
    else if (gid < c4 + W1PAIRS)  { src = w1; dH = g_w1H; dL = g_w1L; idx = gid - c4; cols = F_; }
    else if (gid < c4 + 2ll*W1PAIRS) { src = w3; dH = g_w3H; dL = g_w3L; idx = gid - c4 - W1PAIRS; cols = F_; }
    else if (gid < c4 + 2ll*W1PAIRS + W2PAIRS)
                                  { src = w2; dH = g_w2H; dL = g_w2L; idx = gid - c4 - 2ll*W1PAIRS; cols = D_; }
    else                          { src = lm; dH = g_lmH; dL = g_lmL; idx = gid - c4 - 2ll*W1PAIRS - W2PAIRS; cols = V_; }
    ll kp = idx / cols;
    int col = (int)(idx - kp * cols);
    float a = src[(2*kp)     * (ll)cols + col];
    float b = src[(2*kp + 1) * (ll)cols + col];
    uint32_t h, l;
    split_pack(a, b, h, l);
    dH[idx] = h; dL[idx] = l;
}

// in-place RoPE on q and k together; layout (2B,T,H,HD)
__global__ void rope_k(float* __restrict__ q) {
    if (d_do_skip) return;
    int idx = blockIdx.x * 256 + threadIdx.x;
    int i = idx & 31;
    int t = (idx >> 9) & 255;
    ll base = (ll)(idx >> 5) * HD_ + i;
    float c = g_cos[t * 32 + i], s = g_sin[t * 32 + i];
    float x1 = q[base], x2 = q[base + 32];
    q[base]      = x1 * c - x2 * s;
    q[base + 32] = x1 * s + x2 * c;
}

// silu(f1)*f3 -> packed f1 [F/2][MT] via smem transpose
__global__ void silu_pack_k() {
    if (d_do_skip) return;
    __shared__ float t1[64][65];
    __shared__ float t3[64][65];
    int f0 = blockIdx.x * 64;
    int m0 = blockIdx.y * 64;
    int tid = threadIdx.x;
#pragma unroll
    for (int it = 0; it < 16; it++) {
        int id = it * 256 + tid;
        int mm = id >> 6, ff = id & 63;
        t1[mm][ff] = g_f13[(ll)(m0 + mm) * F_ + f0 + ff];
        t3[mm][ff] = g_f13[(ll)(m0 + mm) * F_ + f0 + ff + (ll)BTF];
    }
    __syncthreads();
#pragma unroll
    for (int it = 0; it < 8; it++) {
        int id = it * 256 + tid;
        int fp = id >> 6, m = id & 63;
        float a0 = t1[m][2*fp],   b0 = t3[m][2*fp];
        float a1 = t1[m][2*fp+1], b1 = t3[m][2*fp+1];
        float v0 = (a0 / (1.f + expf(-a0))) * b0;
        float v1 = (a1 / (1.f + expf(-a1))) * b1;
        uint32_t h, l;
        split_pack(v0, v1, h, l);
        ll o = (ll)(f0/2 + fp) * MT + m0 + m;
        g_f1pH[o] = h; g_f1pL[o] = l;
    }
}

// rmsnorm; packOut: 0 none, 1 -> g_hp, 3 -> g_ex
__global__ void rmsnorm_k(const float* __restrict__ in, const float* __restrict__ w,
                          float* outF, ll inStride, ll outStride,
                          int gateMode, int rowsPerBatch, int packOut) {
    if (gateMode == 1 && d_do_skip) return;
    int row = blockIdx.x;
    if (gateMode == 2 && !d_newly[row / rowsPerBatch]) return;
    const float* xr = in + (ll)row * inStride;
    int tid = threadIdx.x;
    float4 v = reinterpret_cast<const float4*>(xr)[tid];
    float s = v.x * v.x + v.y * v.y + v.z * v.z + v.w * v.w;
    __shared__ float red[256];
    red[tid] = s; __syncthreads();
    for (int o = 128; o > 0; o >>= 1) { if (tid < o) red[tid] += red[tid + o]; __syncthreads(); }
    float scale = rsqrtf(red[0] * (1.f / (float)D_) + 1e-6f);
    float4 wv = reinterpret_cast<const float4*>(w)[tid];
    float4 ov;
    ov.x = v.x * wv.x * scale; ov.y = v.y * wv.y * scale;
    ov.z = v.z * wv.z * scale; ov.w = v.w * wv.w * scale;
    if (outF) reinterpret_cast<float4*>(outF + (ll)row * outStride)[tid] = ov;
    if (packOut) {
        uint32_t* pH = (packOut == 1) ? g_hpH : g_exH;
        uint32_t* pL = (packOut == 1) ? g_hpL : g_exL;
        uint32_t h, l;
        split_pack(ov.x, ov.y, h, l);
        pH[(ll)(2*tid)   * MT + row] = h; pL[(ll)(2*tid)   * MT + row] = l;
        split_pack(ov.z, ov.w, h, l);
        pH[(ll)(2*tid+1) * MT + row] = h; pL[(ll)(2*tid+1) * MT + row] = l;
    }
}

#define MMA_BF16(acc, a, b)                                                   \
    asm volatile(                                                             \
        "mma.sync.aligned.m16n8k16.row.col.f32.bf16.bf16.f32 "                \
        "{%0,%1,%2,%3}, {%4,%5,%6,%7}, {%8,%9}, {%0,%1,%2,%3};"               \
        : "+f"(acc[0]), "+f"(acc[1]), "+f"(acc[2]), "+f"(acc[3])              \
        : "r"(a[0]), "r"(a[1]), "r"(a[2]), "r"(a[3]), "r"(b[0]), "r"(b[1]))

// ==================== fused flash attention ================================
// grid (2, B*H); block 256 = 8 warps x 16 q-rows. K/V tiles of 64 keys.
// Same bf16 hi/lo 3-product emulation for QK^T and PV as the GEMMs.
// Epilogue writes ao_pack [dp][MT] directly.
#define FLASH_SMEM ((2*32*136 + 4*32*72)*4)

__global__ __launch_bounds__(256, 1) void flash_k() {
    if (d_do_skip) return;
    extern __shared__ uint32_t fsm[];
    uint32_t* Qh = fsm;                 // [32 dp][136]
    uint32_t* Ql = Qh + 32*136;
    uint32_t* Kh = Ql + 32*136;         // [32 dp][72]
    uint32_t* Kl = Kh + 32*72;
    uint32_t* Vh = Kl + 32*72;          // [32 keypair][72]
    uint32_t* Vl = Vh + 32*72;

    const int qt = blockIdx.x;
    const int bh = blockIdx.y;
    const int b  = bh >> 4, h = bh & 15;
    const int tid = threadIdx.x;
    const int lane = tid & 31, warp = tid >> 5;
    const int lq = lane >> 2, lr = lane & 3;

    const float* qg = g_qkv;
    const float* kg = g_qkv + (ll)BTD;
    const float* vg = g_qkv + 2ll*BTD;

    // ---- load Q tile 128x64 -> packed [dp][row] ----
    {
        int row = tid >> 1;
        int dh = (tid & 1) * 32;
        const float* p = qg + ((ll)(b*T_ + qt*128 + row))*D_ + h*HD_ + dh;
#pragma unroll
        for (int q4 = 0; q4 < 8; q4++) {
            float4 v4 = *reinterpret_cast<const float4*>(p + q4*4);
            uint32_t hh, lo;
            split_pack(v4.x, v4.y, hh, lo);
            Qh[(dh/2 + 2*q4    )*136 + row] = hh; Ql[(dh/2 + 2*q4    )*136 + row] = lo;
            split_pack(v4.z, v4.w, hh, lo);
            Qh[(dh/2 + 2*q4 + 1)*136 + row] = hh; Ql[(dh/2 + 2*q4 + 1)*136 + row] = lo;
        }
    }

    float m0r = -1e30f, m1r = -1e30f, l0r = 0.f, l1r = 0.f;
    float O[8][4];
#pragma unroll
    for (int j = 0; j < 8; j++)
#pragma unroll
        for (int r = 0; r < 4; r++) O[j][r] = 0.f;

    const int qr0 = qt*128 + warp*16 + lq;
    const int qr1 = qr0 + 8;
    const int ktmax = (qt*128 + 127) >> 6;

    for (int kt = 0; kt <= ktmax; kt++) {
        // ---- load K tile: packed along d, [dp][key] ----
        {
            int key = tid >> 2;
            int ds = (tid & 3) * 16;
            const float* p = kg + ((ll)(b*T_ + kt*64 + key))*D_ + h*HD_ + ds;
#pragma unroll
            for (int q4 = 0; q4 < 4; q4++) {
                float4 v4 = *reinterpret_cast<const float4*>(p + q4*4);
                uint32_t hh, lo;
                split_pack(v4.x, v4.y, hh, lo);
                Kh[(ds/2 + 2*q4    )*72 + key] = hh; Kl[(ds/2 + 2*q4    )*72 + key] = lo;
                split_pack(v4.z, v4.w, hh, lo);
                Kh[(ds/2 + 2*q4 + 1)*72 + key] = hh; Kl[(ds/2 + 2*q4 + 1)*72 + key] = lo;
            }
        }
        // ---- load V tile: packed along key, [keypair][d] ----
        {
            int d4 = (tid & 15) * 4;
            int kpb = (tid >> 4) * 2;
#pragma unroll
            for (int kk = 0; kk < 2; kk++) {
                int kp = kpb + kk;
                const float* p0 = vg + ((ll)(b*T_ + kt*64 + 2*kp))*D_ + h*HD_ + d4;
                float4 a4 = *reinterpret_cast<const float4*>(p0);
                float4 b4 = *reinterpret_cast<const float4*>(p0 + D_);
                uint32_t hh, lo;
                split_pack(a4.x, b4.x, hh, lo); Vh[kp*72 + d4+0] = hh; Vl[kp*72 + d4+0] = lo;
                split_pack(a4.y, b4.y, hh, lo); Vh[kp*72 + d4+1] = hh; Vl[kp*72 + d4+1] = lo;
                split_pack(a4.z, b4.z, hh, lo); Vh[kp*72 + d4+2] = hh; Vl[kp*72 + d4+2] = lo;
                split_pack(a4.w, b4.w, hh, lo); Vh[kp*72 + d4+3] = hh; Vl[kp*72 + d4+3] = lo;
            }
        }
        __syncthreads();

        // ---- S = Q K^T  (m16 x n64 per warp) ----
        float sa[8][4];
#pragma unroll
        for (int j = 0; j < 8; j++)
#pragma unroll
            for (int r = 0; r < 4; r++) sa[j][r] = 0.f;
        const int m0 = warp*16 + lq;
#pragma unroll
        for (int s = 0; s < 4; s++) {
            uint32_t aH[4], aL[4];
            aH[0] = Qh[(8*s + lr    )*136 + m0]; aH[1] = Qh[(8*s + lr    )*136 + m0 + 8];
            aH[2] = Qh[(8*s + lr + 4)*136 + m0]; aH[3] = Qh[(8*s + lr + 4)*136 + m0 + 8];
            aL[0] = Ql[(8*s + lr    )*136 + m0]; aL[1] = Ql[(8*s + lr    )*136 + m0 + 8];
            aL[2] = Ql[(8*s + lr + 4)*136 + m0]; aL[3] = Ql[(8*s + lr + 4)*136 + m0 + 8];
#pragma unroll
            for (int j = 0; j < 8; j++) {
                int n0 = 8*j + lq;
                uint32_t bH[2], bL[2];
                bH[0] = Kh[(8*s + lr    )*72 + n0]; bH[1] = Kh[(8*s + lr + 4)*72 + n0];
                bL[0] = Kl[(8*s + lr    )*72 + n0]; bL[1] = Kl[(8*s + lr + 4)*72 + n0];
                MMA_BF16(sa[j], aH, bL);
                MMA_BF16(sa[j], aL, bH);
                MMA_BF16(sa[j], aH, bH);
            }
        }

        // ---- scale + causal mask + online softmax ----
        float mx0 = -1e30f, mx1 = -1e30f;
#pragma unroll
        for (int j = 0; j < 8; j++) {
            int kc0 = kt*64 + 8*j + 2*lr;
            int kc1 = kc0 + 1;
            sa[j][0] = (kc0 <= qr0) ? sa[j][0]*0.125f : -1e30f;
            sa[j][1] = (kc1 <= qr0) ? sa[j][1]*0.125f : -1e30f;
            sa[j][2] = (kc0 <= qr1) ? sa[j][2]*0.125f : -1e30f;
            sa[j][3] = (kc1 <= qr1) ? sa[j][3]*0.125f : -1e30f;
            mx0 = fmaxf(mx0, fmaxf(sa[j][0], sa[j][1]));
            mx1 = fmaxf(mx1, fmaxf(sa[j][2], sa[j][3]));
        }
        mx0 = fmaxf(mx0, __shfl_xor_sync(0xffffffff, mx0, 1));
        mx0 = fmaxf(mx0, __shfl_xor_sync(0xffffffff, mx0, 2));
        mx1 = fmaxf(mx1, __shfl_xor_sync(0xffffffff, mx1, 1));
        mx1 = fmaxf(mx1, __shfl_xor_sync(0xffffffff, mx1, 2));
        float mn0 = fmaxf(m0r, mx0), mn1 = fmaxf(m1r, mx1);
        float c0 = __expf(m0r - mn0), c1 = __expf(m1r - mn1);
        float s0 = 0.f, s1 = 0.f;
#pragma unroll
        for (int j = 0; j < 8; j++) {
            sa[j][0] = __expf(sa[j][0] - mn0);
            sa[j][1] = __expf(sa[j][1] - mn0);
            sa[j][2] = __expf(sa[j][2] - mn1);
            sa[j][3] = __expf(sa[j][3] - mn1);
            s0 += sa[j][0] + sa[j][1];
            s1 += sa[j][2] + sa[j][3];
        }
        s0 += __shfl_xor_sync(0xffffffff, s0, 1);
        s0 += __shfl_xor_sync(0xffffffff, s0, 2);
        s1 += __shfl_xor_sync(0xffffffff, s1, 1);
        s1 += __shfl_xor_sync(0xffffffff, s1, 2);
        l0r = l0r * c0 + s0;
        l1r = l1r * c1 + s1;
        m0r = mn0; m1r = mn1;
#pragma unroll
        for (int j = 0; j < 8; j++) {
            O[j][0] *= c0; O[j][1] *= c0;
            O[j][2] *= c1; O[j][3] *= c1;
        }

        // ---- O += P V ----
#pragma unroll
        for (int s = 0; s < 4; s++) {
            uint32_t pH[4], pL[4];
            split_pack(sa[2*s][0],   sa[2*s][1],   pH[0], pL[0]);
            split_pack(sa[2*s][2],   sa[2*s][3],   pH[1], pL[1]);
            split_pack(sa[2*s+1][0], sa[2*s+1][1], pH[2], pL[2]);
            split_pack(sa[2*s+1][2], sa[2*s+1][3], pH[3], pL[3]);
#pragma unroll
            for (int j = 0; j < 8; j++) {
                int n0 = 8*j + lq;
                uint32_t bH[2], bL[2];
                bH[0] = Vh[(8*s + lr    )*72 + n0]; bH[1] = Vh[(8*s + lr + 4)*72 + n0];
                bL[0] = Vl[(8*s + lr    )*72 + n0]; bL[1] = Vl[(8*s + lr + 4)*72 + n0];
                MMA_BF16(O[j], pH, bL);
                MMA_BF16(O[j], pL, bH);
                MMA_BF16(O[j], pH, bH);
            }
        }
        __syncthreads();
    }

    // ---- epilogue: normalize and write ao_pack ----
    float i0 = 1.f / l0r, i1 = 1.f / l1r;
#pragma unroll
    for (int j = 0; j < 8; j++) {
        uint32_t hh, lo;
        ll o = (ll)(h*32 + 4*j + lr) * MT + b*T_ + qr0;
        split_pack(O[j][0]*i0, O[j][1]*i0, hh, lo);
        g_aopH[o] = hh; g_aopL[o] = lo;
        split_pack(O[j][2]*i1, O[j][3]*i1, hh, lo);
        g_aopH[o + 8] = hh; g_aopL[o + 8] = lo;
    }
}

// ==================== fused exit-logits partials ===========================
// per-block (max, sumexp) partials over 256 vocab entries x 4 batches.
__global__ void logits_exit_k() {
    if (d_do_skip) return;
    int tid = threadIdx.x;
    __shared__ float hs[B_][D_];
    for (int i = tid; i < B_ * D_; i += 256)
        hs[i >> 10][i & 1023] = g_hlast[i];
    __syncthreads();
    int v = blockIdx.x * 256 + tid;
    float a[B_] = {0.f, 0.f, 0.f, 0.f};
    const uint32_t* col = g_lmH + v;
#pragma unroll 4
    for (int kp = 0; kp < D_ / 2; kp++) {
        uint32_t hv = col[(ll)kp * V_];
        float e0 = __uint_as_float(hv << 16);
        float e1 = __uint_as_float(hv & 0xffff0000u);
        a[0] = fmaf(e0, hs[0][2*kp], fmaf(e1, hs[0][2*kp+1], a[0]));
        a[1] = fmaf(e0, hs[1][2*kp], fmaf(e1, hs[1][2*kp+1], a[1]));
        a[2] = fmaf(e0, hs[2][2*kp], fmaf(e1, hs[2][2*kp+1], a[2]));
        a[3] = fmaf(e0, hs[3][2*kp], fmaf(e1, hs[3][2*kp+1], a[3]));
    }
    __shared__ float wred[8];
    __shared__ float bm;
    int lane = tid & 31, warp = tid >> 5;
    for (int b = 0; b < B_; b++) {
        float m = a[b];
#pragma unroll
        for (int o = 16; o > 0; o >>= 1) m = fmaxf(m, __shfl_xor_sync(0xffffffff, m, o));
        if (lane == 0) wred[warp] = m;
        __syncthreads();
        if (tid == 0) {
            float mm = wred[0];
            for (int i = 1; i < 8; i++) mm = fmaxf(mm, wred[i]);
            bm = mm;
        }
        __syncthreads();
        float e = __expf(a[b] - bm);
#pragma unroll
        for (int o = 16; o > 0; o >>= 1) e += __shfl_xor_sync(0xffffffff, e, o);
        __syncthreads();
        if (lane == 0) wred[warp] = e;
        __syncthreads();
        if (tid == 0) {
            float ss = 0.f;
            for (int i = 0; i < 8; i++) ss += wred[i];
            g_pM[blockIdx.x * B_ + b] = bm;
            g_pS[blockIdx.x * B_ + b] = ss;
        }
        __syncthreads();
    }
}

// ==================== fused exit decision + next-layer skip ================
__global__ void exit_skip_k(const float* __restrict__ x,
                            const float* __restrict__ ew, const float* __restrict__ eb,
                            const float* __restrict__ swn, const float* __restrict__ sbn,
                            int li, int haveNext) {
    int tid = threadIdx.x;
    int warp = tid >> 5, lane = tid & 31;
    __shared__ float conf[B_], eps[B_], sp[B_];
    const int doskip = d_do_skip;

    if (!doskip) {
        if (warp < B_) {
            // combine logits partials for batch = warp
            float m = -1e30f;
            for (int i = lane; i < NPB; i += 32) m = fmaxf(m, g_pM[i * B_ + warp]);
#pragma unroll
            for (int o = 16; o > 0; o >>= 1) m = fmaxf(m, __shfl_xor_sync(0xffffffff, m, o));
            float s = 0.f;
            for (int i = lane; i < NPB; i += 32)
                s += g_pS[i * B_ + warp] * __expf(g_pM[i * B_ + warp] - m);
#pragma unroll
            for (int o = 16; o > 0; o >>= 1) s += __shfl_xor_sync(0xffffffff, s, o);
            if (lane == 0) conf[warp] = 1.f / s;
        } else {
            int b = warp - B_;
            const float* xr = x + ((ll)b * T_ + (T_ - 1)) * D_;
            float e = 0.f;
#pragma unroll 8
            for (int i = lane; i < D_; i += 32) e += xr[i] * ew[i];
#pragma unroll
            for (int o = 16; o > 0; o >>= 1) e += __shfl_xor_sync(0xffffffff, e, o);
            if (lane == 0) eps[b] = 1.f / (1.f + expf(-(e + eb[0])));
        }
    }
    __syncthreads();
    if (tid < B_) {
        int nw = 0;
        if (!doskip) {
            int should = (conf[tid] > 0.9f) || (eps[tid] > 0.9f);
            nw = (should && !d_exited[tid]) ? 1 : 0;
        }
        d_newly[tid] = nw;
        if (nw) { d_exited[tid] = 1; d_exl[tid] = li; }
    }
    __syncthreads();
    // next-layer skip decision (uses UPDATED exited state, same x)
    if (haveNext) {
        if (warp < B_) {
            const float* xr = x + ((ll)warp * T_ + (T_ - 1)) * D_;
            float s = 0.f;
#pragma unroll 8
            for (int i = lane; i < D_; i += 32) s += xr[i] * swn[i];
#pragma unroll
            for (int o = 16; o > 0; o >>= 1) s += __shfl_xor_sync(0xffffffff, s, o);
            if (lane == 0) sp[warp] = 1.f / (1.f + expf(-(s + sbn[0])));
        }
        __syncthreads();
        if (tid == 0) {
            float cnt = 0.f, s = 0.f;
            for (int b = 0; b < B_; b++) {
                float a = d_exited[b] ? 0.f : 1.f;
                cnt += a; s += sp[b] * a;
            }
            float mean = s / fmaxf(cnt, 1.f);
            d_do_skip = (cnt > 0.f && mean < 0.1f) ? 1 : 0;   // li+1 >= 1 always
        }
    } else if (tid == 0) {
        d_do_skip = 0;
    }
}

// =====================  fast cp.async GEMM on packed operands ==============
template <int IBLK, int STG>
__global__ __launch_bounds__(256, (IBLK == 4) ? 1 : 2) void gemm_ws_k(
    int aSel, int wSel, int li, float* __restrict__ C,
    int M, int N, int K, int ldbU, int ldc,
    int aColStride, ll sCo, int accumulate, int gateMode, int splitK) {
    if (gateMode == 1 && d_do_skip) return;
    if (gateMode == 2 && !d_newly[blockIdx.z]) return;
    constexpr int BM = IBLK * 32;
    constexpr int SPA = BM + 8;
    constexpr int SPB = 136;
    constexpr int KP = 16;
    constexpr int AS = KP * SPA, BS = KP * SPB;
    constexpr int STAGE = 2 * AS + 2 * BS;
    constexpr int ACHROW = BM / 4;
    constexpr int ACH = KP * ACHROW;
    constexpr int BCH = KP * 32;
    constexpr int TCH = 2 * ACH + 2 * BCH;

    extern __shared__ uint32_t sm[];
    const int z = blockIdx.z;

    const uint32_t* aHp = (aSel == 0) ? g_hpH : ((aSel == 1) ? g_aopH :
                          ((aSel == 2) ? g_f1pH : g_exH));
    const uint32_t* aLp = (aSel == 0) ? g_hpL : ((aSel == 1) ? g_aopL :
                          ((aSel == 2) ? g_f1pL : g_exL));
    const uint32_t *bHp, *bLp;
    {
        ll off;
        switch (wSel) {
        case 0:
            off = (ll)li * (D_/2) * D_;
            bHp = ((z == 0) ? g_wqH : ((z == 1) ? g_wkH : g_wvH)) + off;
            bLp = ((z == 0) ? g_wqL : ((z == 1) ? g_wkL : g_wvL)) + off;
            break;
        case 1:
            off = (ll)li * (D_/2) * D_;
            bHp = g_woH + off; bLp = g_woL + off; break;
        case 2:
            off = (ll)li * (D_/2) * F_;
            bHp = ((z == 0) ? g_w1H : g_w3H) + off;
            bLp = ((z == 0) ? g_w1L : g_w3L) + off; break;
        case 3:
            off = (ll)li * (F_/2) * D_;
            bHp = g_w2H + off; bLp = g_w2L + off; break;
        default:
            bHp = g_lmH; bLp = g_lmL; break;
        }
    }
    const int Ksub = K / splitK;
    const int kpBase = (splitK > 1) ? z * (Ksub / 2) : 0;
    const int aOff = (splitK > 1) ? 0 : z * aColStride;
    float* Cb = (splitK > 1) ? C : (C + (ll)z * sCo);

    const int tid = threadIdx.x;
    const int lane = tid & 31;
    const int warp = tid >> 5;
    const int warpRow = warp >> 2;
    const int warpCol = warp & 3;
    const int rowBase = blockIdx.y * BM;
    const int colBase = blockIdx.x * 128;
    const int lq = lane >> 2;
    const int lr = lane & 3;

    auto loadTile = [&](int t, int s) {
        uint32_t* st = sm + s * STAGE;
        int kp0 = kpBase + t * KP;
#pragma unroll
        for (int c = tid; c < TCH; c += 256) {
            uint32_t* dst; const uint32_t* src;
            if (c < 2 * ACH) {
                int cc = c; const uint32_t* g = aHp; uint32_t* ss = st;
                if (cc >= ACH) { cc -= ACH; g = aLp; ss = st + AS; }
                int row = cc / ACHROW, col = (cc % ACHROW) * 4;
                dst = ss + row * SPA + col;
                src = g + (ll)(kp0 + row) * MT + aOff + rowBase + col;
            } else {
                int cc = c - 2 * ACH; const uint32_t* g = bHp; uint32_t* ss = st + 2 * AS;
                if (cc >= BCH) { cc -= BCH; g = bLp; ss += BS; }
                int row = cc >> 5, col = (cc & 31) * 4;
                dst = ss + row * SPB + col;
                src = g + (ll)(kp0 + row) * ldbU + colBase + col;
            }
            uint32_t da = (uint32_t)__cvta_generic_to_shared(dst);
            asm volatile("cp.async.cg.shared.global [%0], [%1], 16;\n"
                         :: "r"(da), "l"(src));
        }
        asm volatile("cp.async.commit_group;\n");
    };

    float acc[IBLK][4][4];
#pragma unroll
    for (int i = 0; i < IBLK; i++)
#pragma unroll
        for (int j = 0; j < 4; j++)
#pragma unroll
            for (int r = 0; r < 4; r++) acc[i][j][r] = 0.f;

    const int nt = Ksub / 32;
#pragma unroll
    for (int s = 0; s < STG - 1; s++) loadTile(s, s);

    for (int t = 0; t < nt; t++) {
        asm volatile("cp.async.wait_group %0;\n" :: "n"(STG - 2));
        __syncthreads();
        int tn = t + STG - 1;
        if (tn < nt) loadTile(tn, tn % STG);
        else asm volatile("cp.async.commit_group;\n");

        const uint32_t* AsH = sm + (t % STG) * STAGE;
        const uint32_t* AsL = AsH + AS;
        const uint32_t* BsH = AsH + 2 * AS;
        const uint32_t* BsL = BsH + BS;
#pragma unroll
        for (int st2 = 0; st2 < 2; st2++) {
            int base = st2 * 8;
            uint32_t aH[IBLK][4], aL[IBLK][4], bH[4][2], bL[4][2];
#pragma unroll
            for (int i = 0; i < IBLK; i++) {
                int m0 = warpRow * (IBLK * 16) + i * 16 + lq;
                aH[i][0] = AsH[(base + lr) * SPA + m0];
                aH[i][1] = AsH[(base + lr) * SPA + m0 + 8];
                aH[i][2] = AsH[(base + lr + 4) * SPA + m0];
                aH[i][3] = AsH[(base + lr + 4) * SPA + m0 + 8];
                aL[i][0] = AsL[(base + lr) * SPA + m0];
                aL[i][1] = AsL[(base + lr) * SPA + m0 + 8];
                aL[i][2] = AsL[(base + lr + 4) * SPA + m0];
                aL[i][3] = AsL[(base + lr + 4) * SPA + m0 + 8];
            }
#pragma unroll
            for (int j = 0; j < 4; j++) {
                int n0 = warpCol * 32 + j * 8 + lq;
                bH[j][0] = BsH[(base + lr) * SPB + n0];
                bH[j][1] = BsH[(base + lr + 4) * SPB + n0];
                bL[j][0] = BsL[(base + lr) * SPB + n0];
                bL[j][1] = BsL[(base + lr + 4) * SPB + n0];
            }
#pragma unroll
            for (int i = 0; i < IBLK; i++)
#pragma unroll
                for (int j = 0; j < 4; j++) MMA_BF16(acc[i][j], aH[i], bL[j]);
#pragma unroll
            for (int i = 0; i < IBLK; i++)
#pragma unroll
                for (int j = 0; j < 4; j++) MMA_BF16(acc[i][j], aL[i], bH[j]);
#pragma unroll
            for (int i = 0; i < IBLK; i++)
#pragma unroll
                for (int j = 0; j < 4; j++) MMA_BF16(acc[i][j], aH[i], bH[j]);
        }
    }

#pragma unroll
    for (int i = 0; i < IBLK; i++) {
#pragma unroll
        for (int r2 = 0; r2 < 2; r2++) {
            int gm = rowBase + warpRow * (IBLK * 16) + i * 16 + lq + r2 * 8;
            if (gm >= M) continue;
            float* crow = Cb + (ll)gm * ldc;
#pragma unroll
            for (int j = 0; j < 4; j++) {
                int gn = colBase + warpCol * 32 + j * 8 + lr * 2;
                float v0 = acc[i][j][r2 * 2 + 0];
                float v1 = acc[i][j][r2 * 2 + 1];
                if (gn < N) {
                    if (accumulate == 2)      atomicAdd(crow + gn, v0);
                    else if (accumulate == 1) crow[gn] += v0;
                    else                      crow[gn] = v0;
                }
                if (gn + 1 < N) {
                    if (accumulate == 2)      atomicAdd(crow + gn + 1, v1);
                    else if (accumulate == 1) crow[gn + 1] += v1;
                    else                      crow[gn + 1] = v1;
                }
            }
        }
    }
}

#define SMEM_WS2 (4 * (2*16*(64+8)  + 2*16*136) * 4)
#define SMEM_WS4 (4 * (2*16*(128+8) + 2*16*136) * 4)

static void gemm_fast(int aSel, int wSel, int li, float* C,
                      int M, int N, int K, int ldbU, int ldc,
                      int batch, int aColStride, ll sCo, int acc, int gate) {
    int nx = N / 128;
    int b128 = nx * (M / 128) * batch;
    if (b128 >= 296) {
        dim3 g(nx, M / 128, batch);
        gemm_ws_k<4, 4><<<g, 256, SMEM_WS4>>>(aSel, wSel, li, C, M, N, K, ldbU, ldc,
                                              aColStride, sCo, acc, gate, 1);
    } else {
        dim3 g(nx, M / 64, batch);
        gemm_ws_k<2, 4><<<g, 256, SMEM_WS2>>>(aSel, wSel, li, C, M, N, K, ldbU, ldc,
                                              aColStride, sCo, acc, gate, 1);
    }
}

static void gemm_fast_sk(int aSel, int wSel, int li, float* C,
                         int M, int N, int K, int ldbU, int ldc,
                         int splitK, int gate) {
    dim3 g(N / 128, M / 64, splitK);
    gemm_ws_k<2, 4><<<g, 256, SMEM_WS2>>>(aSel, wSel, li, C, M, N, K, ldbU, ldc,
                                          0, 0, 2, gate, splitK);
}

// ---------------------------------------------------------------------------
extern "C" void kernel_launch(void* const* d_in, const int* in_sizes, int n_in,
                              void* d_out, int out_size) {
    const int*   ids        = (const int*)  d_in[0];
    const float* embed      = (const float*)d_in[1];
    const float* wq         = (const float*)d_in[2];
    const float* wk         = (const float*)d_in[3];
    const float* wv         = (const float*)d_in[4];
    const float* wo         = (const float*)d_in[5];
    const float* w1         = (const float*)d_in[6];
    const float* w2         = (const float*)d_in[7];
    const float* w3         = (const float*)d_in[8];
    const float* norm1      = (const float*)d_in[9];
    const float* norm2      = (const float*)d_in[10];
    const float* final_norm = (const float*)d_in[11];
    const float* lm_head    = (const float*)d_in[12];
    const float* exit_w     = (const float*)d_in[13];
    const float* exit_b     = (const float*)d_in[14];
    const float* skip_w     = (const float*)d_in[15];
    const float* skip_b     = (const float*)d_in[16];
    float* out = (float*)d_out;

    cudaFuncSetAttribute(gemm_ws_k<2, 4>, cudaFuncAttributeMaxDynamicSharedMemorySize, SMEM_WS2);
    cudaFuncSetAttribute(gemm_ws_k<4, 4>, cudaFuncAttributeMaxDynamicSharedMemorySize, SMEM_WS4);
    cudaFuncSetAttribute(flash_k, cudaFuncAttributeMaxDynamicSharedMemorySize, FLASH_SMEM);

    float *px, *pqkv, *pf13, *phl;
    cudaGetSymbolAddress((void**)&px,   g_x);
    cudaGetSymbolAddress((void**)&pqkv, g_qkv);
    cudaGetSymbolAddress((void**)&pf13, g_f13);
    cudaGetSymbolAddress((void**)&phl,  g_hlast);
    float* pq = pqkv;

    init_k<<<1, 32>>>();
    prepack_k<<<(int)((TOTPAIRS + 255) / 256), 256>>>(wq, wk, wv, wo, w1, w2, w3, lm_head);
    rope_tables_k<<<(T_ * (HD_ / 2)) / 256, 256>>>();
    embed_k<<<(B_ * T_ * D_) / 256, 256>>>(ids, embed);

    for (int li = 0; li < L_; li++) {
        // transformer block (gated by do_skip, set by previous layer's exit_skip_k)
        rmsnorm_k<<<B_ * T_, 256>>>(px, norm1 + (ll)li * D_, nullptr, D_, D_, 1, 1, 1);
        gemm_fast(0, 0, li, pqkv, MT, D_, D_, D_, D_, 3, 0, (ll)BTD, 0, 1);
        rope_k<<<(2 * B_ * T_ * D_ / 2) / 256, 256>>>(pq);
        flash_k<<<dim3(2, B_ * H_), 256, FLASH_SMEM>>>();
        gemm_fast_sk(1, 1, li, px, MT, D_, D_, D_, D_, 2, 1);
        rmsnorm_k<<<B_ * T_, 256>>>(px, norm2 + (ll)li * D_, nullptr, D_, D_, 1, 1, 1);
        gemm_fast(0, 2, li, pf13, MT, F_, D_, F_, F_, 2, 0, (ll)BTF, 0, 1);
        silu_pack_k<<<dim3(F_ / 64, MT / 64), 256>>>();
        gemm_fast_sk(2, 3, li, px, MT, D_, F_, D_, D_, 2, 1);

        // exit logic + next-layer skip (fused)
        rmsnorm_k<<<B_, 256>>>(px + (ll)(T_ - 1) * D_, final_norm, phl,
                               (ll)T_ * D_, D_, 1, 1, 0);
        logits_exit_k<<<NPB, 256>>>();
        int nli = (li + 1 < L_) ? (li + 1) : (L_ - 1);
        exit_skip_k<<<1, 256>>>(px, exit_w + (ll)li * D_, exit_b + li,
                                skip_w + (ll)nli * D_, skip_b + nli,
                                li, li + 1 < L_ ? 1 : 0);

        // snapshot rmsnorm(x, final_norm) for newly-exited batches -> g_ex
        rmsnorm_k<<<B_ * T_, 256>>>(px, final_norm, nullptr, D_, D_, 2, T_, 3);
    }

    // final: snapshot for never-exited, then ONE logits GEMM for all batches
    finalize_k<<<1, 32>>>();
    rmsnorm_k<<<B_ * T_, 256>>>(px, final_norm, nullptr, D_, D_, 2, T_, 3);
    gemm_fast(3, 4, 0, out, T_, V_, D_, V_, V_, B_, T_, (ll)T_ * V_, 0, 0);

    if (out_size >= B_ * T_ * V_ + B_)
        write_exl_k<<<1, 32>>>(out + (ll)B_ * T_ * V_);
}